// round 1
// baseline (speedup 1.0000x reference)
#include <cuda_runtime.h>

#define NN 100000
#define NE 1600000

// scratch (static device globals: allocation-free)
__device__ float g_Xs[NN * 64];
__device__ float g_Xr[NN * 64];
__device__ float g_agg[NN * 64];

__device__ __forceinline__ void red_add_v4(float* addr, float a, float b, float c, float d) {
    asm volatile("red.global.add.v4.f32 [%0], {%1, %2, %3, %4};"
                 :: "l"(addr), "f"(a), "f"(b), "f"(c), "f"(d) : "memory");
}

// 64xK tile GEMM: C[64][64] = A[64][K] @ W[K][64].
// 256 threads, thread (q = tid>>3, cg = tid&7) owns rows {2q,2q+1}, cols [8cg,8cg+8).
// A row-major stride AS (scalar broadcast loads), W row-major stride 64 (float4 loads).
template<int K, int AS>
__device__ __forceinline__ void gemm_tile(const float* __restrict__ As,
                                          const float* __restrict__ Ws,
                                          int q, int cg,
                                          float* __restrict__ acc0,
                                          float* __restrict__ acc1) {
#pragma unroll
    for (int j = 0; j < 8; j++) { acc0[j] = 0.f; acc1[j] = 0.f; }
    const float* a0p = As + (2 * q) * AS;
    const float* a1p = As + (2 * q + 1) * AS;
    const float* wp  = Ws + 8 * cg;
#pragma unroll 4
    for (int k = 0; k < K; k++) {
        float a0 = a0p[k];
        float a1 = a1p[k];
        float4 b0 = *(const float4*)(wp + k * 64);
        float4 b1 = *(const float4*)(wp + k * 64 + 4);
        acc0[0] = fmaf(a0, b0.x, acc0[0]); acc1[0] = fmaf(a1, b0.x, acc1[0]);
        acc0[1] = fmaf(a0, b0.y, acc0[1]); acc1[1] = fmaf(a1, b0.y, acc1[1]);
        acc0[2] = fmaf(a0, b0.z, acc0[2]); acc1[2] = fmaf(a1, b0.z, acc1[2]);
        acc0[3] = fmaf(a0, b0.w, acc0[3]); acc1[3] = fmaf(a1, b0.w, acc1[3]);
        acc0[4] = fmaf(a0, b1.x, acc0[4]); acc1[4] = fmaf(a1, b1.x, acc1[4]);
        acc0[5] = fmaf(a0, b1.y, acc0[5]); acc1[5] = fmaf(a1, b1.y, acc1[5]);
        acc0[6] = fmaf(a0, b1.z, acc0[6]); acc1[6] = fmaf(a1, b1.z, acc1[6]);
        acc0[7] = fmaf(a0, b1.w, acc0[7]); acc1[7] = fmaf(a1, b1.w, acc1[7]);
    }
}

// ---------------------------------------------------------------------------
__global__ void zero_agg_kernel() {
    int idx = blockIdx.x * blockDim.x + threadIdx.x;
    float4* p = (float4*)g_agg;
    const int n4 = NN * 64 / 4;
    for (int i = idx; i < n4; i += gridDim.x * blockDim.x)
        p[i] = make_float4(0.f, 0.f, 0.f, 0.f);
}

// ---------------------------------------------------------------------------
// Xs = x @ We1[64:128], Xr = x @ We1[128:192] + be1
__global__ __launch_bounds__(256, 2)
void precompute_kernel(const float* __restrict__ x,
                       const float* __restrict__ We1,
                       const float* __restrict__ be1) {
    extern __shared__ float sm[];
    float* Wls = sm;            // 4096
    float* Wlr = sm + 4096;     // 4096
    float* b1  = sm + 8192;     // 64
    float* As  = sm + 8256;     // 64*65
    int tid = threadIdx.x;
    for (int i = tid; i < 4096; i += 256) {
        int k = i >> 6, j = i & 63;
        Wls[i] = We1[(64 + k) * 64 + j];
        Wlr[i] = We1[(128 + k) * 64 + j];
    }
    if (tid < 64) b1[tid] = be1[tid];
    __syncthreads();
    int q = tid >> 3, cg = tid & 7;
    const int NT = (NN + 63) / 64;
    for (int tile = blockIdx.x; tile < NT; tile += gridDim.x) {
        int base = tile * 64;
        for (int i = tid; i < 4096; i += 256) {
            int r = i >> 6, c = i & 63;
            int n = base + r;
            As[r * 65 + c] = (n < NN) ? x[n * 64 + c] : 0.f;
        }
        __syncthreads();
        float s0[8], s1[8], r0[8], r1[8];
        gemm_tile<64, 65>(As, Wls, q, cg, s0, s1);
        gemm_tile<64, 65>(As, Wlr, q, cg, r0, r1);
        int n0 = base + 2 * q;
        if (n0 < NN) {
            *(float4*)&g_Xs[n0 * 64 + 8 * cg]     = make_float4(s0[0], s0[1], s0[2], s0[3]);
            *(float4*)&g_Xs[n0 * 64 + 8 * cg + 4] = make_float4(s0[4], s0[5], s0[6], s0[7]);
            *(float4*)&g_Xr[n0 * 64 + 8 * cg] = make_float4(r0[0] + b1[8*cg+0], r0[1] + b1[8*cg+1],
                                                            r0[2] + b1[8*cg+2], r0[3] + b1[8*cg+3]);
            *(float4*)&g_Xr[n0 * 64 + 8 * cg + 4] = make_float4(r0[4] + b1[8*cg+4], r0[5] + b1[8*cg+5],
                                                                r0[6] + b1[8*cg+6], r0[7] + b1[8*cg+7]);
        }
        int n1 = n0 + 1;
        if (n1 < NN) {
            *(float4*)&g_Xs[n1 * 64 + 8 * cg]     = make_float4(s1[0], s1[1], s1[2], s1[3]);
            *(float4*)&g_Xs[n1 * 64 + 8 * cg + 4] = make_float4(s1[4], s1[5], s1[6], s1[7]);
            *(float4*)&g_Xr[n1 * 64 + 8 * cg] = make_float4(r1[0] + b1[8*cg+0], r1[1] + b1[8*cg+1],
                                                            r1[2] + b1[8*cg+2], r1[3] + b1[8*cg+3]);
            *(float4*)&g_Xr[n1 * 64 + 8 * cg + 4] = make_float4(r1[4] + b1[8*cg+4], r1[5] + b1[8*cg+5],
                                                                r1[6] + b1[8*cg+6], r1[7] + b1[8*cg+7]);
        }
        __syncthreads();
    }
}

// ---------------------------------------------------------------------------
// Per-edge 3-layer MLP + atomic aggregation into g_agg[receiver].
__global__ __launch_bounds__(256, 2)
void edge_kernel(const float* __restrict__ e,
                 const int* __restrict__ senders,
                 const int* __restrict__ receivers,
                 const float* __restrict__ We1,
                 const float* __restrict__ We2, const float* __restrict__ be2,
                 const float* __restrict__ We3, const float* __restrict__ be3) {
    extern __shared__ float sm[];
    float* W1 = sm;                 // 4096 (We1 rows 0..63)
    float* W2 = sm + 4096;          // 4096
    float* W3 = sm + 8192;          // 4096
    float* b2 = sm + 12288;         // 64
    float* b3 = sm + 12352;         // 64
    float* As = sm + 12416;         // 64*65
    float* Bx = sm + 16576;         // 64*65
    int*   rv = (int*)(sm + 20736); // 64
    int tid = threadIdx.x;
    for (int i = tid; i < 4096; i += 256) {
        W1[i] = We1[i];
        W2[i] = We2[i];
        W3[i] = We3[i];
    }
    if (tid < 64) { b2[tid] = be2[tid]; b3[tid] = be3[tid]; }
    __syncthreads();
    int q = tid >> 3, cg = tid & 7;
    const int NT = NE / 64;
    float acc0[8], acc1[8];
    for (int tile = blockIdx.x; tile < NT; tile += gridDim.x) {
        int base = tile * 64;
        // load tile: e rows + per-row bias gather Bx = Xs[s] + Xr[r] + recv ids
        if (tid < 64) rv[tid] = receivers[base + tid];
        for (int i = tid; i < 1024; i += 256) {
            int r = i >> 4, c4 = i & 15;
            float4 v = *(const float4*)&e[(base + r) * 64 + c4 * 4];
            float* d = &As[r * 65 + c4 * 4];
            d[0] = v.x; d[1] = v.y; d[2] = v.z; d[3] = v.w;
        }
        for (int i = tid; i < 4096; i += 256) {
            int r = i >> 6, c = i & 63;
            int s = senders[base + r];
            int t = receivers[base + r];
            Bx[r * 65 + c] = g_Xs[s * 64 + c] + g_Xr[t * 64 + c];
        }
        __syncthreads();
        // layer 1: relu(e@W1 + Bx)
        gemm_tile<64, 65>(As, W1, q, cg, acc0, acc1);
        __syncthreads();
#pragma unroll
        for (int j = 0; j < 8; j++) {
            As[(2*q)   * 65 + 8*cg + j] = fmaxf(acc0[j] + Bx[(2*q)   * 65 + 8*cg + j], 0.f);
            As[(2*q+1) * 65 + 8*cg + j] = fmaxf(acc1[j] + Bx[(2*q+1) * 65 + 8*cg + j], 0.f);
        }
        __syncthreads();
        // layer 2: relu(h@W2 + b2)
        gemm_tile<64, 65>(As, W2, q, cg, acc0, acc1);
        __syncthreads();
#pragma unroll
        for (int j = 0; j < 8; j++) {
            As[(2*q)   * 65 + 8*cg + j] = fmaxf(acc0[j] + b2[8*cg + j], 0.f);
            As[(2*q+1) * 65 + 8*cg + j] = fmaxf(acc1[j] + b2[8*cg + j], 0.f);
        }
        __syncthreads();
        // layer 3: h@W3 + b3 -> atomic segment-sum
        gemm_tile<64, 65>(As, W3, q, cg, acc0, acc1);
        __syncthreads();
        {
            float* p0 = &g_agg[rv[2*q]     * 64 + 8 * cg];
            float* p1 = &g_agg[rv[2*q + 1] * 64 + 8 * cg];
            red_add_v4(p0,     acc0[0] + b3[8*cg+0], acc0[1] + b3[8*cg+1],
                               acc0[2] + b3[8*cg+2], acc0[3] + b3[8*cg+3]);
            red_add_v4(p0 + 4, acc0[4] + b3[8*cg+4], acc0[5] + b3[8*cg+5],
                               acc0[6] + b3[8*cg+6], acc0[7] + b3[8*cg+7]);
            red_add_v4(p1,     acc1[0] + b3[8*cg+0], acc1[1] + b3[8*cg+1],
                               acc1[2] + b3[8*cg+2], acc1[3] + b3[8*cg+3]);
            red_add_v4(p1 + 4, acc1[4] + b3[8*cg+4], acc1[5] + b3[8*cg+5],
                               acc1[6] + b3[8*cg+6], acc1[7] + b3[8*cg+7]);
        }
        __syncthreads();
    }
}

// ---------------------------------------------------------------------------
// Node MLP: relu/relu/linear over concat(x, agg) [K=128 first layer]
__global__ __launch_bounds__(256, 2)
void node_kernel(const float* __restrict__ x,
                 const float* __restrict__ Wn1, const float* __restrict__ bn1,
                 const float* __restrict__ Wn2, const float* __restrict__ bn2,
                 const float* __restrict__ Wn3, const float* __restrict__ bn3,
                 float* __restrict__ out) {
    extern __shared__ float sm[];
    float* W1 = sm;             // 8192 (128x64)
    float* W2 = sm + 8192;      // 4096
    float* W3 = sm + 12288;     // 4096
    float* b1 = sm + 16384;     // 64
    float* b2 = sm + 16448;     // 64
    float* b3 = sm + 16512;     // 64
    float* As = sm + 16576;     // 64*130
    int tid = threadIdx.x;
    for (int i = tid; i < 8192; i += 256) W1[i] = Wn1[i];
    for (int i = tid; i < 4096; i += 256) { W2[i] = Wn2[i]; W3[i] = Wn3[i]; }
    if (tid < 64) { b1[tid] = bn1[tid]; b2[tid] = bn2[tid]; b3[tid] = bn3[tid]; }
    __syncthreads();
    int q = tid >> 3, cg = tid & 7;
    const int NT = (NN + 63) / 64;
    float acc0[8], acc1[8];
    for (int tile = blockIdx.x; tile < NT; tile += gridDim.x) {
        int base = tile * 64;
        for (int i = tid; i < 4096; i += 256) {
            int r = i >> 6, c = i & 63;
            int n = base + r;
            float vx = 0.f, va = 0.f;
            if (n < NN) { vx = x[n * 64 + c]; va = g_agg[n * 64 + c]; }
            As[r * 130 + c]      = vx;
            As[r * 130 + 64 + c] = va;
        }
        __syncthreads();
        // layer 1 (K=128)
        gemm_tile<128, 130>(As, W1, q, cg, acc0, acc1);
        __syncthreads();
#pragma unroll
        for (int j = 0; j < 8; j++) {
            As[(2*q)   * 130 + 8*cg + j] = fmaxf(acc0[j] + b1[8*cg + j], 0.f);
            As[(2*q+1) * 130 + 8*cg + j] = fmaxf(acc1[j] + b1[8*cg + j], 0.f);
        }
        __syncthreads();
        // layer 2
        gemm_tile<64, 130>(As, W2, q, cg, acc0, acc1);
        __syncthreads();
#pragma unroll
        for (int j = 0; j < 8; j++) {
            As[(2*q)   * 130 + 8*cg + j] = fmaxf(acc0[j] + b2[8*cg + j], 0.f);
            As[(2*q+1) * 130 + 8*cg + j] = fmaxf(acc1[j] + b2[8*cg + j], 0.f);
        }
        __syncthreads();
        // layer 3 -> out
        gemm_tile<64, 130>(As, W3, q, cg, acc0, acc1);
        __syncthreads();
        {
            int n0 = base + 2 * q;
            if (n0 < NN) {
                *(float4*)&out[n0 * 64 + 8*cg]     = make_float4(acc0[0] + b3[8*cg+0], acc0[1] + b3[8*cg+1],
                                                                 acc0[2] + b3[8*cg+2], acc0[3] + b3[8*cg+3]);
                *(float4*)&out[n0 * 64 + 8*cg + 4] = make_float4(acc0[4] + b3[8*cg+4], acc0[5] + b3[8*cg+5],
                                                                 acc0[6] + b3[8*cg+6], acc0[7] + b3[8*cg+7]);
            }
            int n1 = n0 + 1;
            if (n1 < NN) {
                *(float4*)&out[n1 * 64 + 8*cg]     = make_float4(acc1[0] + b3[8*cg+0], acc1[1] + b3[8*cg+1],
                                                                 acc1[2] + b3[8*cg+2], acc1[3] + b3[8*cg+3]);
                *(float4*)&out[n1 * 64 + 8*cg + 4] = make_float4(acc1[4] + b3[8*cg+4], acc1[5] + b3[8*cg+5],
                                                                 acc1[6] + b3[8*cg+6], acc1[7] + b3[8*cg+7]);
            }
        }
    }
}

// ---------------------------------------------------------------------------
extern "C" void kernel_launch(void* const* d_in, const int* in_sizes, int n_in,
                              void* d_out, int out_size) {
    const float* x         = (const float*)d_in[0];
    const float* e         = (const float*)d_in[1];
    const int*   senders   = (const int*)d_in[2];
    const int*   receivers = (const int*)d_in[3];
    const float* We1 = (const float*)d_in[4];
    const float* be1 = (const float*)d_in[5];
    const float* We2 = (const float*)d_in[6];
    const float* be2 = (const float*)d_in[7];
    const float* We3 = (const float*)d_in[8];
    const float* be3 = (const float*)d_in[9];
    const float* Wn1 = (const float*)d_in[10];
    const float* bn1 = (const float*)d_in[11];
    const float* Wn2 = (const float*)d_in[12];
    const float* bn2 = (const float*)d_in[13];
    const float* Wn3 = (const float*)d_in[14];
    const float* bn3 = (const float*)d_in[15];
    float* out = (float*)d_out;

    const int PRE_SMEM  = 12416 * 4;  // 49664 B
    const int EDGE_SMEM = 20864 * 4;  // 83456 B
    const int NODE_SMEM = 24896 * 4;  // 99584 B
    cudaFuncSetAttribute(precompute_kernel, cudaFuncAttributeMaxDynamicSharedMemorySize, PRE_SMEM);
    cudaFuncSetAttribute(edge_kernel,       cudaFuncAttributeMaxDynamicSharedMemorySize, EDGE_SMEM);
    cudaFuncSetAttribute(node_kernel,       cudaFuncAttributeMaxDynamicSharedMemorySize, NODE_SMEM);

    const int GRID = 304;  // 152 SMs x 2 resident blocks
    zero_agg_kernel<<<GRID, 256>>>();
    precompute_kernel<<<GRID, 256, PRE_SMEM>>>(x, We1, be1);
    edge_kernel<<<GRID, 256, EDGE_SMEM>>>(e, senders, receivers, We1, We2, be2, We3, be3);
    node_kernel<<<GRID, 256, NODE_SMEM>>>(x, Wn1, bn1, Wn2, bn2, Wn3, bn3, out);
}

// round 2
// speedup vs baseline: 2.0285x; 2.0285x over previous
#include <cuda_runtime.h>

#define NN 100000
#define NE 1600000

// scratch (static device globals: allocation-free)
__device__ float g_Xs[NN * 64];
__device__ float g_Xr[NN * 64];
__device__ float g_agg[NN * 64];

using u64 = unsigned long long;

__device__ __forceinline__ u64 pk2(float lo, float hi) {
    u64 r; asm("mov.b64 %0, {%1, %2};" : "=l"(r) : "f"(lo), "f"(hi)); return r;
}
__device__ __forceinline__ void fma2(u64& d, u64 a, u64 b) {
    asm("fma.rn.f32x2 %0, %1, %2, %0;" : "+l"(d) : "l"(a), "l"(b));
}
__device__ __forceinline__ float2 upk(u64 v) {
    float2 f; asm("mov.b64 {%0, %1}, %2;" : "=f"(f.x), "=f"(f.y) : "l"(v)); return f;
}
__device__ __forceinline__ void red_add_v4(float* addr, float a, float b, float c, float d) {
    asm volatile("red.global.add.v4.f32 [%0], {%1, %2, %3, %4};"
                 :: "l"(addr), "f"(a), "f"(b), "f"(c), "f"(d) : "memory");
}

// ---------------------------------------------------------------------------
// C(128x64) = A(128xK) @ W(Kx64). 256 threads.
// thread: tr = tid>>3 (0..31) -> rows 4tr..4tr+3 ; tc = tid&7 -> cols 8tc..8tc+7
// A in smem: float4 granules, row stride SGR granules, granule g stored at (g ^ (tr&7))
//   -> conflict-free LDS.128 (4 distinct rows per warp land on distinct bank groups)
// W in smem: row k = 16 granules, granule g stored at slot ((g&1)<<3)|(g>>1)
//   -> both per-k LDS.128 (slots tc and 8+tc) cover a full 128B line, conflict-free.
// Accumulators are f32x2 pairs: acc[rr][0..3] = col pairs (0,1)(2,3)(4,5)(6,7) of the 8.
template<int K, int SGR>
__device__ __forceinline__ void gemm_core(const float4* __restrict__ As4,
                                          const ulonglong2* __restrict__ Wv,
                                          int tr, int tc, u64 acc[4][4]) {
#pragma unroll
    for (int r = 0; r < 4; r++)
#pragma unroll
        for (int j = 0; j < 4; j++) acc[r][j] = 0ull;
    const int sw = tr & 7;
    const int r0 = tr * 4;
#pragma unroll 4
    for (int kg = 0; kg < K / 4; kg++) {
        float4 av[4];
#pragma unroll
        for (int rr = 0; rr < 4; rr++) av[rr] = As4[(r0 + rr) * SGR + (kg ^ sw)];
#pragma unroll
        for (int j = 0; j < 4; j++) {
            const int k = kg * 4 + j;
            ulonglong2 wa = Wv[k * 16 + tc];
            ulonglong2 wb = Wv[k * 16 + 8 + tc];
#pragma unroll
            for (int rr = 0; rr < 4; rr++) {
                float a = (j == 0) ? av[rr].x : (j == 1) ? av[rr].y : (j == 2) ? av[rr].z : av[rr].w;
                u64 aa = pk2(a, a);
                fma2(acc[rr][0], aa, wa.x);
                fma2(acc[rr][1], aa, wa.y);
                fma2(acc[rr][2], aa, wb.x);
                fma2(acc[rr][3], aa, wb.y);
            }
        }
    }
}

// load a [K x 64] row-major weight into smem with the slot remap
__device__ __forceinline__ void load_w(float* dst, const float* __restrict__ src,
                                       int nelem, int tid) {
    for (int i = tid; i < nelem; i += 256) {
        int k = i >> 6, g = (i >> 2) & 15, w = i & 3;
        dst[k * 64 + ((((g & 1) << 3) | (g >> 1)) << 2) + w] = src[i];
    }
}

// ---------------------------------------------------------------------------
__global__ void zero_agg_kernel() {
    int idx = blockIdx.x * blockDim.x + threadIdx.x;
    float4* p = (float4*)g_agg;
    const int n4 = NN * 64 / 4;
    for (int i = idx; i < n4; i += gridDim.x * blockDim.x)
        p[i] = make_float4(0.f, 0.f, 0.f, 0.f);
}

// ---------------------------------------------------------------------------
// Xs = x @ We1[64:128], Xr = x @ We1[128:192] + be1   (tiles of 128 nodes)
__global__ __launch_bounds__(256)
void precompute_kernel(const float* __restrict__ x,
                       const float* __restrict__ We1,
                       const float* __restrict__ be1) {
    extern __shared__ float sm[];
    float* Ws = sm;             // 4096
    float* Wr = sm + 4096;      // 4096
    float* b1 = sm + 8192;      // 64
    float* As = sm + 8256;      // 8192
    const int tid = threadIdx.x;
    load_w(Ws, We1 + 64 * 64, 4096, tid);
    load_w(Wr, We1 + 128 * 64, 4096, tid);
    if (tid < 64) b1[tid] = be1[tid];
    __syncthreads();
    const int tr = tid >> 3, tc = tid & 7, sw = tr & 7, r0 = tr * 4;
    float4* As4 = (float4*)As;
    const ulonglong2* Wsv = (const ulonglong2*)Ws;
    const ulonglong2* Wrv = (const ulonglong2*)Wr;
    const float4* x4 = (const float4*)x;
    float4* Xs4 = (float4*)g_Xs;
    float4* Xr4 = (float4*)g_Xr;
    const int NT = (NN + 127) / 128;
    u64 acc[4][4];
    float4 bb0 = *(float4*)&b1[8 * tc];
    float4 bb1 = *(float4*)&b1[8 * tc + 4];
    for (int tile = blockIdx.x; tile < NT; tile += gridDim.x) {
        const int base = tile * 128;
        for (int i = tid; i < 2048; i += 256) {
            int r = i >> 4, g = i & 15;
            int n = base + r;
            As4[r * 16 + (g ^ ((r >> 2) & 7))] =
                (n < NN) ? x4[n * 16 + g] : make_float4(0.f, 0.f, 0.f, 0.f);
        }
        __syncthreads();
        gemm_core<64, 16>(As4, Wsv, tr, tc, acc);
#pragma unroll
        for (int rr = 0; rr < 4; rr++) {
            int n = base + r0 + rr;
            if (n < NN) {
                float2 p0 = upk(acc[rr][0]), p1 = upk(acc[rr][1]),
                       p2 = upk(acc[rr][2]), p3 = upk(acc[rr][3]);
                Xs4[n * 16 + 2 * tc]     = make_float4(p0.x, p0.y, p1.x, p1.y);
                Xs4[n * 16 + 2 * tc + 1] = make_float4(p2.x, p2.y, p3.x, p3.y);
            }
        }
        gemm_core<64, 16>(As4, Wrv, tr, tc, acc);
#pragma unroll
        for (int rr = 0; rr < 4; rr++) {
            int n = base + r0 + rr;
            if (n < NN) {
                float2 p0 = upk(acc[rr][0]), p1 = upk(acc[rr][1]),
                       p2 = upk(acc[rr][2]), p3 = upk(acc[rr][3]);
                Xr4[n * 16 + 2 * tc]     = make_float4(p0.x + bb0.x, p0.y + bb0.y, p1.x + bb0.z, p1.y + bb0.w);
                Xr4[n * 16 + 2 * tc + 1] = make_float4(p2.x + bb1.x, p2.y + bb1.y, p3.x + bb1.z, p3.y + bb1.w);
            }
        }
        __syncthreads();
    }
}

// ---------------------------------------------------------------------------
// Per-edge 3-layer MLP + atomic segment-sum into g_agg[receiver]. Tiles of 128 edges.
__global__ __launch_bounds__(256)
void edge_kernel(const float* __restrict__ e,
                 const int* __restrict__ senders,
                 const int* __restrict__ receivers,
                 const float* __restrict__ We1,
                 const float* __restrict__ We2, const float* __restrict__ be2,
                 const float* __restrict__ We3, const float* __restrict__ be3) {
    extern __shared__ float sm[];
    float* W1 = sm;                  // 4096
    float* W2 = sm + 4096;           // 4096
    float* W3 = sm + 8192;           // 4096
    float* b2 = sm + 12288;          // 64
    float* b3 = sm + 12352;          // 64
    int*   rv = (int*)(sm + 12416);  // 128
    float* As = sm + 12544;          // 8192
    float* Bx = sm + 20736;          // 8192
    const int tid = threadIdx.x;
    load_w(W1, We1, 4096, tid);
    load_w(W2, We2, 4096, tid);
    load_w(W3, We3, 4096, tid);
    if (tid < 64) { b2[tid] = be2[tid]; b3[tid] = be3[tid]; }
    __syncthreads();
    const int tr = tid >> 3, tc = tid & 7, sw = tr & 7, r0 = tr * 4;
    float4* As4 = (float4*)As;
    float4* Bx4 = (float4*)Bx;
    const ulonglong2* W1v = (const ulonglong2*)W1;
    const ulonglong2* W2v = (const ulonglong2*)W2;
    const ulonglong2* W3v = (const ulonglong2*)W3;
    const float4* e4  = (const float4*)e;
    const float4* Xs4 = (const float4*)g_Xs;
    const float4* Xr4 = (const float4*)g_Xr;
    const int NT = NE / 128;
    u64 acc[4][4];
    float4 bb0 = *(float4*)&b2[8 * tc];
    float4 bb1 = *(float4*)&b2[8 * tc + 4];
    float4 cc0 = *(float4*)&b3[8 * tc];
    float4 cc1 = *(float4*)&b3[8 * tc + 4];
    for (int tile = blockIdx.x; tile < NT; tile += gridDim.x) {
        const int base = tile * 128;
        if (tid < 128) rv[tid] = receivers[base + tid];
        for (int i = tid; i < 2048; i += 256) {
            int r = i >> 4, g = i & 15;
            As4[r * 16 + (g ^ ((r >> 2) & 7))] = e4[(base + r) * 16 + g];
        }
        for (int i = tid; i < 2048; i += 256) {
            int r = i >> 4, g = i & 15;
            int s = senders[base + r], t = receivers[base + r];
            float4 a = Xs4[s * 16 + g], b = Xr4[t * 16 + g];
            Bx4[r * 16 + (g ^ ((r >> 2) & 7))] =
                make_float4(a.x + b.x, a.y + b.y, a.z + b.z, a.w + b.w);
        }
        __syncthreads();
        // layer 1: relu(e@W1 + Xs[s] + Xr[t] + be1)
        gemm_core<64, 16>(As4, W1v, tr, tc, acc);
        __syncthreads();
#pragma unroll
        for (int rr = 0; rr < 4; rr++) {
            int r = r0 + rr;
            float4 x0 = Bx4[r * 16 + ((2 * tc) ^ sw)];
            float4 x1 = Bx4[r * 16 + ((2 * tc + 1) ^ sw)];
            float2 p0 = upk(acc[rr][0]), p1 = upk(acc[rr][1]),
                   p2 = upk(acc[rr][2]), p3 = upk(acc[rr][3]);
            As4[r * 16 + ((2 * tc) ^ sw)] =
                make_float4(fmaxf(p0.x + x0.x, 0.f), fmaxf(p0.y + x0.y, 0.f),
                            fmaxf(p1.x + x0.z, 0.f), fmaxf(p1.y + x0.w, 0.f));
            As4[r * 16 + ((2 * tc + 1) ^ sw)] =
                make_float4(fmaxf(p2.x + x1.x, 0.f), fmaxf(p2.y + x1.y, 0.f),
                            fmaxf(p3.x + x1.z, 0.f), fmaxf(p3.y + x1.w, 0.f));
        }
        __syncthreads();
        // layer 2
        gemm_core<64, 16>(As4, W2v, tr, tc, acc);
        __syncthreads();
#pragma unroll
        for (int rr = 0; rr < 4; rr++) {
            int r = r0 + rr;
            float2 p0 = upk(acc[rr][0]), p1 = upk(acc[rr][1]),
                   p2 = upk(acc[rr][2]), p3 = upk(acc[rr][3]);
            As4[r * 16 + ((2 * tc) ^ sw)] =
                make_float4(fmaxf(p0.x + bb0.x, 0.f), fmaxf(p0.y + bb0.y, 0.f),
                            fmaxf(p1.x + bb0.z, 0.f), fmaxf(p1.y + bb0.w, 0.f));
            As4[r * 16 + ((2 * tc + 1) ^ sw)] =
                make_float4(fmaxf(p2.x + bb1.x, 0.f), fmaxf(p2.y + bb1.y, 0.f),
                            fmaxf(p3.x + bb1.z, 0.f), fmaxf(p3.y + bb1.w, 0.f));
        }
        __syncthreads();
        // layer 3 -> atomic segment-sum
        gemm_core<64, 16>(As4, W3v, tr, tc, acc);
#pragma unroll
        for (int rr = 0; rr < 4; rr++) {
            float2 p0 = upk(acc[rr][0]), p1 = upk(acc[rr][1]),
                   p2 = upk(acc[rr][2]), p3 = upk(acc[rr][3]);
            float* p = &g_agg[rv[r0 + rr] * 64 + 8 * tc];
            red_add_v4(p,     p0.x + cc0.x, p0.y + cc0.y, p1.x + cc0.z, p1.y + cc0.w);
            red_add_v4(p + 4, p2.x + cc1.x, p2.y + cc1.y, p3.x + cc1.z, p3.y + cc1.w);
        }
        __syncthreads();
    }
}

// ---------------------------------------------------------------------------
// Node MLP over concat(x, agg): K=128 first layer, tiles of 128 nodes.
__global__ __launch_bounds__(256)
void node_kernel(const float* __restrict__ x,
                 const float* __restrict__ Wn1, const float* __restrict__ bn1,
                 const float* __restrict__ Wn2, const float* __restrict__ bn2,
                 const float* __restrict__ Wn3, const float* __restrict__ bn3,
                 float* __restrict__ out) {
    extern __shared__ float sm[];
    float* W1 = sm;              // 8192 (128x64)
    float* W2 = sm + 8192;       // 4096
    float* W3 = sm + 12288;      // 4096
    float* b1 = sm + 16384;      // 64
    float* b2 = sm + 16448;      // 64
    float* b3 = sm + 16512;      // 64
    float* As = sm + 16576;      // 128 x 128 = 16384
    const int tid = threadIdx.x;
    load_w(W1, Wn1, 8192, tid);
    load_w(W2, Wn2, 4096, tid);
    load_w(W3, Wn3, 4096, tid);
    if (tid < 64) { b1[tid] = bn1[tid]; b2[tid] = bn2[tid]; b3[tid] = bn3[tid]; }
    __syncthreads();
    const int tr = tid >> 3, tc = tid & 7, sw = tr & 7, r0 = tr * 4;
    float4* As4 = (float4*)As;
    const ulonglong2* W1v = (const ulonglong2*)W1;
    const ulonglong2* W2v = (const ulonglong2*)W2;
    const ulonglong2* W3v = (const ulonglong2*)W3;
    const float4* x4 = (const float4*)x;
    const float4* Ag4 = (const float4*)g_agg;
    const int NT = (NN + 127) / 128;
    u64 acc[4][4];
    float4 a0 = *(float4*)&b1[8 * tc], a1 = *(float4*)&b1[8 * tc + 4];
    float4 bb0 = *(float4*)&b2[8 * tc], bb1 = *(float4*)&b2[8 * tc + 4];
    float4 cc0 = *(float4*)&b3[8 * tc], cc1 = *(float4*)&b3[8 * tc + 4];
    for (int tile = blockIdx.x; tile < NT; tile += gridDim.x) {
        const int base = tile * 128;
        for (int i = tid; i < 2048; i += 256) {
            int r = i >> 4, g = i & 15;
            int n = base + r;
            int s = (r >> 2) & 7;
            float4 vx = make_float4(0.f, 0.f, 0.f, 0.f), va = vx;
            if (n < NN) { vx = x4[n * 16 + g]; va = Ag4[n * 16 + g]; }
            As4[r * 32 + (g ^ s)]        = vx;
            As4[r * 32 + 16 + (g ^ s)]   = va;
        }
        __syncthreads();
        // layer 1 (K=128)
        gemm_core<128, 32>(As4, W1v, tr, tc, acc);
        __syncthreads();
#pragma unroll
        for (int rr = 0; rr < 4; rr++) {
            int r = r0 + rr;
            float2 p0 = upk(acc[rr][0]), p1 = upk(acc[rr][1]),
                   p2 = upk(acc[rr][2]), p3 = upk(acc[rr][3]);
            As4[r * 32 + ((2 * tc) ^ sw)] =
                make_float4(fmaxf(p0.x + a0.x, 0.f), fmaxf(p0.y + a0.y, 0.f),
                            fmaxf(p1.x + a0.z, 0.f), fmaxf(p1.y + a0.w, 0.f));
            As4[r * 32 + ((2 * tc + 1) ^ sw)] =
                make_float4(fmaxf(p2.x + a1.x, 0.f), fmaxf(p2.y + a1.y, 0.f),
                            fmaxf(p3.x + a1.z, 0.f), fmaxf(p3.y + a1.w, 0.f));
        }
        __syncthreads();
        // layer 2
        gemm_core<64, 32>(As4, W2v, tr, tc, acc);
        __syncthreads();
#pragma unroll
        for (int rr = 0; rr < 4; rr++) {
            int r = r0 + rr;
            float2 p0 = upk(acc[rr][0]), p1 = upk(acc[rr][1]),
                   p2 = upk(acc[rr][2]), p3 = upk(acc[rr][3]);
            As4[r * 32 + ((2 * tc) ^ sw)] =
                make_float4(fmaxf(p0.x + bb0.x, 0.f), fmaxf(p0.y + bb0.y, 0.f),
                            fmaxf(p1.x + bb0.z, 0.f), fmaxf(p1.y + bb0.w, 0.f));
            As4[r * 32 + ((2 * tc + 1) ^ sw)] =
                make_float4(fmaxf(p2.x + bb1.x, 0.f), fmaxf(p2.y + bb1.y, 0.f),
                            fmaxf(p3.x + bb1.z, 0.f), fmaxf(p3.y + bb1.w, 0.f));
        }
        __syncthreads();
        // layer 3 -> out
        gemm_core<64, 32>(As4, W3v, tr, tc, acc);
#pragma unroll
        for (int rr = 0; rr < 4; rr++) {
            int n = base + r0 + rr;
            if (n < NN) {
                float2 p0 = upk(acc[rr][0]), p1 = upk(acc[rr][1]),
                       p2 = upk(acc[rr][2]), p3 = upk(acc[rr][3]);
                *(float4*)&out[n * 64 + 8 * tc] =
                    make_float4(p0.x + cc0.x, p0.y + cc0.y, p1.x + cc0.z, p1.y + cc0.w);
                *(float4*)&out[n * 64 + 8 * tc + 4] =
                    make_float4(p2.x + cc1.x, p2.y + cc1.y, p3.x + cc1.z, p3.y + cc1.w);
            }
        }
        __syncthreads();
    }
}

// ---------------------------------------------------------------------------
extern "C" void kernel_launch(void* const* d_in, const int* in_sizes, int n_in,
                              void* d_out, int out_size) {
    const float* x         = (const float*)d_in[0];
    const float* e         = (const float*)d_in[1];
    const int*   senders   = (const int*)d_in[2];
    const int*   receivers = (const int*)d_in[3];
    const float* We1 = (const float*)d_in[4];
    const float* be1 = (const float*)d_in[5];
    const float* We2 = (const float*)d_in[6];
    const float* be2 = (const float*)d_in[7];
    const float* We3 = (const float*)d_in[8];
    const float* be3 = (const float*)d_in[9];
    const float* Wn1 = (const float*)d_in[10];
    const float* bn1 = (const float*)d_in[11];
    const float* Wn2 = (const float*)d_in[12];
    const float* bn2 = (const float*)d_in[13];
    const float* Wn3 = (const float*)d_in[14];
    const float* bn3 = (const float*)d_in[15];
    float* out = (float*)d_out;

    const int PRE_SMEM  = 16448 * 4;   // 65792 B
    const int EDGE_SMEM = 28928 * 4;   // 115712 B
    const int NODE_SMEM = 32960 * 4;   // 131840 B
    cudaFuncSetAttribute(precompute_kernel, cudaFuncAttributeMaxDynamicSharedMemorySize, PRE_SMEM);
    cudaFuncSetAttribute(edge_kernel,       cudaFuncAttributeMaxDynamicSharedMemorySize, EDGE_SMEM);
    cudaFuncSetAttribute(node_kernel,       cudaFuncAttributeMaxDynamicSharedMemorySize, NODE_SMEM);

    zero_agg_kernel<<<304, 256>>>();
    precompute_kernel<<<304, 256, PRE_SMEM>>>(x, We1, be1);
    edge_kernel<<<152, 256, EDGE_SMEM>>>(e, senders, receivers, We1, We2, be2, We3, be3);
    node_kernel<<<152, 256, NODE_SMEM>>>(x, Wn1, bn1, Wn2, bn2, Wn3, bn3, out);
}

// round 3
// speedup vs baseline: 2.0328x; 1.0021x over previous
#include <cuda_runtime.h>

#define NN 100000
#define NE 1600000

// scratch (static device globals: allocation-free)
__device__ float g_Xs[NN * 64];
__device__ float g_Xr[NN * 64];
__device__ float g_agg[NN * 64];

using u64 = unsigned long long;

__device__ __forceinline__ u64 pk2(float lo, float hi) {
    u64 r; asm("mov.b64 %0, {%1, %2};" : "=l"(r) : "f"(lo), "f"(hi)); return r;
}
__device__ __forceinline__ void fma2(u64& d, u64 a, u64 b) {
    asm("fma.rn.f32x2 %0, %1, %2, %0;" : "+l"(d) : "l"(a), "l"(b));
}
__device__ __forceinline__ float2 upk(u64 v) {
    float2 f; asm("mov.b64 {%0, %1}, %2;" : "=f"(f.x), "=f"(f.y) : "l"(v)); return f;
}
__device__ __forceinline__ void red_add_v4(float* addr, float a, float b, float c, float d) {
    asm volatile("red.global.add.v4.f32 [%0], {%1, %2, %3, %4};"
                 :: "l"(addr), "f"(a), "f"(b), "f"(c), "f"(d) : "memory");
}

// ---------------------------------------------------------------------------
// C(128x64) = A(128xK) @ W(Kx64). 256 threads.
// thread: tr = tid>>3 (0..31) -> rows 4tr..4tr+3 ; tc = tid&7 -> cols 8tc..8tc+7
// A in smem: float4 granules, row stride SGR granules, granule g stored at (g ^ (tr&7))
//   -> conflict-free LDS.128 (4 distinct rows per warp land on distinct bank groups)
// W in smem: row k = 16 granules, granule g stored at slot ((g&1)<<3)|(g>>1)
//   -> both per-k LDS.128 (slots tc and 8+tc) cover a full 128B line, conflict-free.
// Accumulators are f32x2 pairs: acc[rr][0..3] = col pairs (0,1)(2,3)(4,5)(6,7) of the 8.
template<int K, int SGR>
__device__ __forceinline__ void gemm_core(const float4* __restrict__ As4,
                                          const ulonglong2* __restrict__ Wv,
                                          int tr, int tc, u64 acc[4][4]) {
#pragma unroll
    for (int r = 0; r < 4; r++)
#pragma unroll
        for (int j = 0; j < 4; j++) acc[r][j] = 0ull;
    const int sw = tr & 7;
    const int r0 = tr * 4;
#pragma unroll 4
    for (int kg = 0; kg < K / 4; kg++) {
        float4 av[4];
#pragma unroll
        for (int rr = 0; rr < 4; rr++) av[rr] = As4[(r0 + rr) * SGR + (kg ^ sw)];
#pragma unroll
        for (int j = 0; j < 4; j++) {
            const int k = kg * 4 + j;
            ulonglong2 wa = Wv[k * 16 + tc];
            ulonglong2 wb = Wv[k * 16 + 8 + tc];
#pragma unroll
            for (int rr = 0; rr < 4; rr++) {
                float a = (j == 0) ? av[rr].x : (j == 1) ? av[rr].y : (j == 2) ? av[rr].z : av[rr].w;
                u64 aa = pk2(a, a);
                fma2(acc[rr][0], aa, wa.x);
                fma2(acc[rr][1], aa, wa.y);
                fma2(acc[rr][2], aa, wb.x);
                fma2(acc[rr][3], aa, wb.y);
            }
        }
    }
}

// load a [K x 64] row-major weight into smem with the slot remap
__device__ __forceinline__ void load_w(float* dst, const float* __restrict__ src,
                                       int nelem, int tid) {
    for (int i = tid; i < nelem; i += 256) {
        int k = i >> 6, g = (i >> 2) & 15, w = i & 3;
        dst[k * 64 + ((((g & 1) << 3) | (g >> 1)) << 2) + w] = src[i];
    }
}

// ---------------------------------------------------------------------------
__global__ void zero_agg_kernel() {
    int idx = blockIdx.x * blockDim.x + threadIdx.x;
    float4* p = (float4*)g_agg;
    const int n4 = NN * 64 / 4;
    for (int i = idx; i < n4; i += gridDim.x * blockDim.x)
        p[i] = make_float4(0.f, 0.f, 0.f, 0.f);
}

// ---------------------------------------------------------------------------
// Xs = x @ We1[64:128], Xr = x @ We1[128:192] + be1   (tiles of 128 nodes)
__global__ __launch_bounds__(256)
void precompute_kernel(const float* __restrict__ x,
                       const float* __restrict__ We1,
                       const float* __restrict__ be1) {
    extern __shared__ float sm[];
    float* Ws = sm;             // 4096
    float* Wr = sm + 4096;      // 4096
    float* b1 = sm + 8192;      // 64
    float* As = sm + 8256;      // 8192
    const int tid = threadIdx.x;
    load_w(Ws, We1 + 64 * 64, 4096, tid);
    load_w(Wr, We1 + 128 * 64, 4096, tid);
    if (tid < 64) b1[tid] = be1[tid];
    __syncthreads();
    const int tr = tid >> 3, tc = tid & 7, sw = tr & 7, r0 = tr * 4;
    float4* As4 = (float4*)As;
    const ulonglong2* Wsv = (const ulonglong2*)Ws;
    const ulonglong2* Wrv = (const ulonglong2*)Wr;
    const float4* x4 = (const float4*)x;
    float4* Xs4 = (float4*)g_Xs;
    float4* Xr4 = (float4*)g_Xr;
    const int NT = (NN + 127) / 128;
    u64 acc[4][4];
    float4 bb0 = *(float4*)&b1[8 * tc];
    float4 bb1 = *(float4*)&b1[8 * tc + 4];
    for (int tile = blockIdx.x; tile < NT; tile += gridDim.x) {
        const int base = tile * 128;
        for (int i = tid; i < 2048; i += 256) {
            int r = i >> 4, g = i & 15;
            int n = base + r;
            As4[r * 16 + (g ^ ((r >> 2) & 7))] =
                (n < NN) ? x4[n * 16 + g] : make_float4(0.f, 0.f, 0.f, 0.f);
        }
        __syncthreads();
        gemm_core<64, 16>(As4, Wsv, tr, tc, acc);
#pragma unroll
        for (int rr = 0; rr < 4; rr++) {
            int n = base + r0 + rr;
            if (n < NN) {
                float2 p0 = upk(acc[rr][0]), p1 = upk(acc[rr][1]),
                       p2 = upk(acc[rr][2]), p3 = upk(acc[rr][3]);
                Xs4[n * 16 + 2 * tc]     = make_float4(p0.x, p0.y, p1.x, p1.y);
                Xs4[n * 16 + 2 * tc + 1] = make_float4(p2.x, p2.y, p3.x, p3.y);
            }
        }
        gemm_core<64, 16>(As4, Wrv, tr, tc, acc);
#pragma unroll
        for (int rr = 0; rr < 4; rr++) {
            int n = base + r0 + rr;
            if (n < NN) {
                float2 p0 = upk(acc[rr][0]), p1 = upk(acc[rr][1]),
                       p2 = upk(acc[rr][2]), p3 = upk(acc[rr][3]);
                Xr4[n * 16 + 2 * tc]     = make_float4(p0.x + bb0.x, p0.y + bb0.y, p1.x + bb0.z, p1.y + bb0.w);
                Xr4[n * 16 + 2 * tc + 1] = make_float4(p2.x + bb1.x, p2.y + bb1.y, p3.x + bb1.z, p3.y + bb1.w);
            }
        }
        __syncthreads();
    }
}

// ---------------------------------------------------------------------------
// Per-edge 3-layer MLP + atomic segment-sum into g_agg[receiver]. Tiles of 128 edges.
__global__ __launch_bounds__(256)
void edge_kernel(const float* __restrict__ e,
                 const int* __restrict__ senders,
                 const int* __restrict__ receivers,
                 const float* __restrict__ We1,
                 const float* __restrict__ We2, const float* __restrict__ be2,
                 const float* __restrict__ We3, const float* __restrict__ be3) {
    extern __shared__ float sm[];
    float* W1 = sm;                  // 4096
    float* W2 = sm + 4096;           // 4096
    float* W3 = sm + 8192;           // 4096
    float* b2 = sm + 12288;          // 64
    float* b3 = sm + 12352;          // 64
    int*   rv = (int*)(sm + 12416);  // 128
    float* As = sm + 12544;          // 8192
    float* Bx = sm + 20736;          // 8192
    const int tid = threadIdx.x;
    load_w(W1, We1, 4096, tid);
    load_w(W2, We2, 4096, tid);
    load_w(W3, We3, 4096, tid);
    if (tid < 64) { b2[tid] = be2[tid]; b3[tid] = be3[tid]; }
    __syncthreads();
    const int tr = tid >> 3, tc = tid & 7, sw = tr & 7, r0 = tr * 4;
    float4* As4 = (float4*)As;
    float4* Bx4 = (float4*)Bx;
    const ulonglong2* W1v = (const ulonglong2*)W1;
    const ulonglong2* W2v = (const ulonglong2*)W2;
    const ulonglong2* W3v = (const ulonglong2*)W3;
    const float4* e4  = (const float4*)e;
    const float4* Xs4 = (const float4*)g_Xs;
    const float4* Xr4 = (const float4*)g_Xr;
    const int NT = NE / 128;
    u64 acc[4][4];
    float4 bb0 = *(float4*)&b2[8 * tc];
    float4 bb1 = *(float4*)&b2[8 * tc + 4];
    float4 cc0 = *(float4*)&b3[8 * tc];
    float4 cc1 = *(float4*)&b3[8 * tc + 4];
    for (int tile = blockIdx.x; tile < NT; tile += gridDim.x) {
        const int base = tile * 128;
        if (tid < 128) rv[tid] = receivers[base + tid];
        for (int i = tid; i < 2048; i += 256) {
            int r = i >> 4, g = i & 15;
            As4[r * 16 + (g ^ ((r >> 2) & 7))] = e4[(base + r) * 16 + g];
        }
        for (int i = tid; i < 2048; i += 256) {
            int r = i >> 4, g = i & 15;
            int s = senders[base + r], t = receivers[base + r];
            float4 a = Xs4[s * 16 + g], b = Xr4[t * 16 + g];
            Bx4[r * 16 + (g ^ ((r >> 2) & 7))] =
                make_float4(a.x + b.x, a.y + b.y, a.z + b.z, a.w + b.w);
        }
        __syncthreads();
        // layer 1: relu(e@W1 + Xs[s] + Xr[t] + be1)
        gemm_core<64, 16>(As4, W1v, tr, tc, acc);
        __syncthreads();
#pragma unroll
        for (int rr = 0; rr < 4; rr++) {
            int r = r0 + rr;
            float4 x0 = Bx4[r * 16 + ((2 * tc) ^ sw)];
            float4 x1 = Bx4[r * 16 + ((2 * tc + 1) ^ sw)];
            float2 p0 = upk(acc[rr][0]), p1 = upk(acc[rr][1]),
                   p2 = upk(acc[rr][2]), p3 = upk(acc[rr][3]);
            As4[r * 16 + ((2 * tc) ^ sw)] =
                make_float4(fmaxf(p0.x + x0.x, 0.f), fmaxf(p0.y + x0.y, 0.f),
                            fmaxf(p1.x + x0.z, 0.f), fmaxf(p1.y + x0.w, 0.f));
            As4[r * 16 + ((2 * tc + 1) ^ sw)] =
                make_float4(fmaxf(p2.x + x1.x, 0.f), fmaxf(p2.y + x1.y, 0.f),
                            fmaxf(p3.x + x1.z, 0.f), fmaxf(p3.y + x1.w, 0.f));
        }
        __syncthreads();
        // layer 2
        gemm_core<64, 16>(As4, W2v, tr, tc, acc);
        __syncthreads();
#pragma unroll
        for (int rr = 0; rr < 4; rr++) {
            int r = r0 + rr;
            float2 p0 = upk(acc[rr][0]), p1 = upk(acc[rr][1]),
                   p2 = upk(acc[rr][2]), p3 = upk(acc[rr][3]);
            As4[r * 16 + ((2 * tc) ^ sw)] =
                make_float4(fmaxf(p0.x + bb0.x, 0.f), fmaxf(p0.y + bb0.y, 0.f),
                            fmaxf(p1.x + bb0.z, 0.f), fmaxf(p1.y + bb0.w, 0.f));
            As4[r * 16 + ((2 * tc + 1) ^ sw)] =
                make_float4(fmaxf(p2.x + bb1.x, 0.f), fmaxf(p2.y + bb1.y, 0.f),
                            fmaxf(p3.x + bb1.z, 0.f), fmaxf(p3.y + bb1.w, 0.f));
        }
        __syncthreads();
        // layer 3 -> atomic segment-sum
        gemm_core<64, 16>(As4, W3v, tr, tc, acc);
#pragma unroll
        for (int rr = 0; rr < 4; rr++) {
            float2 p0 = upk(acc[rr][0]), p1 = upk(acc[rr][1]),
                   p2 = upk(acc[rr][2]), p3 = upk(acc[rr][3]);
            float* p = &g_agg[rv[r0 + rr] * 64 + 8 * tc];
            red_add_v4(p,     p0.x + cc0.x, p0.y + cc0.y, p1.x + cc0.z, p1.y + cc0.w);
            red_add_v4(p + 4, p2.x + cc1.x, p2.y + cc1.y, p3.x + cc1.z, p3.y + cc1.w);
        }
        __syncthreads();
    }
}

// ---------------------------------------------------------------------------
// Node MLP over concat(x, agg): K=128 first layer, tiles of 128 nodes.
__global__ __launch_bounds__(256)
void node_kernel(const float* __restrict__ x,
                 const float* __restrict__ Wn1, const float* __restrict__ bn1,
                 const float* __restrict__ Wn2, const float* __restrict__ bn2,
                 const float* __restrict__ Wn3, const float* __restrict__ bn3,
                 float* __restrict__ out) {
    extern __shared__ float sm[];
    float* W1 = sm;              // 8192 (128x64)
    float* W2 = sm + 8192;       // 4096
    float* W3 = sm + 12288;      // 4096
    float* b1 = sm + 16384;      // 64
    float* b2 = sm + 16448;      // 64
    float* b3 = sm + 16512;      // 64
    float* As = sm + 16576;      // 128 x 128 = 16384
    const int tid = threadIdx.x;
    load_w(W1, Wn1, 8192, tid);
    load_w(W2, Wn2, 4096, tid);
    load_w(W3, Wn3, 4096, tid);
    if (tid < 64) { b1[tid] = bn1[tid]; b2[tid] = bn2[tid]; b3[tid] = bn3[tid]; }
    __syncthreads();
    const int tr = tid >> 3, tc = tid & 7, sw = tr & 7, r0 = tr * 4;
    float4* As4 = (float4*)As;
    const ulonglong2* W1v = (const ulonglong2*)W1;
    const ulonglong2* W2v = (const ulonglong2*)W2;
    const ulonglong2* W3v = (const ulonglong2*)W3;
    const float4* x4 = (const float4*)x;
    const float4* Ag4 = (const float4*)g_agg;
    const int NT = (NN + 127) / 128;
    u64 acc[4][4];
    float4 a0 = *(float4*)&b1[8 * tc], a1 = *(float4*)&b1[8 * tc + 4];
    float4 bb0 = *(float4*)&b2[8 * tc], bb1 = *(float4*)&b2[8 * tc + 4];
    float4 cc0 = *(float4*)&b3[8 * tc], cc1 = *(float4*)&b3[8 * tc + 4];
    for (int tile = blockIdx.x; tile < NT; tile += gridDim.x) {
        const int base = tile * 128;
        for (int i = tid; i < 2048; i += 256) {
            int r = i >> 4, g = i & 15;
            int n = base + r;
            int s = (r >> 2) & 7;
            float4 vx = make_float4(0.f, 0.f, 0.f, 0.f), va = vx;
            if (n < NN) { vx = x4[n * 16 + g]; va = Ag4[n * 16 + g]; }
            As4[r * 32 + (g ^ s)]        = vx;
            As4[r * 32 + 16 + (g ^ s)]   = va;
        }
        __syncthreads();
        // layer 1 (K=128)
        gemm_core<128, 32>(As4, W1v, tr, tc, acc);
        __syncthreads();
#pragma unroll
        for (int rr = 0; rr < 4; rr++) {
            int r = r0 + rr;
            float2 p0 = upk(acc[rr][0]), p1 = upk(acc[rr][1]),
                   p2 = upk(acc[rr][2]), p3 = upk(acc[rr][3]);
            As4[r * 32 + ((2 * tc) ^ sw)] =
                make_float4(fmaxf(p0.x + a0.x, 0.f), fmaxf(p0.y + a0.y, 0.f),
                            fmaxf(p1.x + a0.z, 0.f), fmaxf(p1.y + a0.w, 0.f));
            As4[r * 32 + ((2 * tc + 1) ^ sw)] =
                make_float4(fmaxf(p2.x + a1.x, 0.f), fmaxf(p2.y + a1.y, 0.f),
                            fmaxf(p3.x + a1.z, 0.f), fmaxf(p3.y + a1.w, 0.f));
        }
        __syncthreads();
        // layer 2
        gemm_core<64, 32>(As4, W2v, tr, tc, acc);
        __syncthreads();
#pragma unroll
        for (int rr = 0; rr < 4; rr++) {
            int r = r0 + rr;
            float2 p0 = upk(acc[rr][0]), p1 = upk(acc[rr][1]),
                   p2 = upk(acc[rr][2]), p3 = upk(acc[rr][3]);
            As4[r * 32 + ((2 * tc) ^ sw)] =
                make_float4(fmaxf(p0.x + bb0.x, 0.f), fmaxf(p0.y + bb0.y, 0.f),
                            fmaxf(p1.x + bb0.z, 0.f), fmaxf(p1.y + bb0.w, 0.f));
            As4[r * 32 + ((2 * tc + 1) ^ sw)] =
                make_float4(fmaxf(p2.x + bb1.x, 0.f), fmaxf(p2.y + bb1.y, 0.f),
                            fmaxf(p3.x + bb1.z, 0.f), fmaxf(p3.y + bb1.w, 0.f));
        }
        __syncthreads();
        // layer 3 -> out
        gemm_core<64, 32>(As4, W3v, tr, tc, acc);
#pragma unroll
        for (int rr = 0; rr < 4; rr++) {
            int n = base + r0 + rr;
            if (n < NN) {
                float2 p0 = upk(acc[rr][0]), p1 = upk(acc[rr][1]),
                       p2 = upk(acc[rr][2]), p3 = upk(acc[rr][3]);
                *(float4*)&out[n * 64 + 8 * tc] =
                    make_float4(p0.x + cc0.x, p0.y + cc0.y, p1.x + cc0.z, p1.y + cc0.w);
                *(float4*)&out[n * 64 + 8 * tc + 4] =
                    make_float4(p2.x + cc1.x, p2.y + cc1.y, p3.x + cc1.z, p3.y + cc1.w);
            }
        }
        __syncthreads();
    }
}

// ---------------------------------------------------------------------------
extern "C" void kernel_launch(void* const* d_in, const int* in_sizes, int n_in,
                              void* d_out, int out_size) {
    const float* x         = (const float*)d_in[0];
    const float* e         = (const float*)d_in[1];
    const int*   senders   = (const int*)d_in[2];
    const int*   receivers = (const int*)d_in[3];
    const float* We1 = (const float*)d_in[4];
    const float* be1 = (const float*)d_in[5];
    const float* We2 = (const float*)d_in[6];
    const float* be2 = (const float*)d_in[7];
    const float* We3 = (const float*)d_in[8];
    const float* be3 = (const float*)d_in[9];
    const float* Wn1 = (const float*)d_in[10];
    const float* bn1 = (const float*)d_in[11];
    const float* Wn2 = (const float*)d_in[12];
    const float* bn2 = (const float*)d_in[13];
    const float* Wn3 = (const float*)d_in[14];
    const float* bn3 = (const float*)d_in[15];
    float* out = (float*)d_out;

    const int PRE_SMEM  = 16448 * 4;   // 65792 B
    const int EDGE_SMEM = 28928 * 4;   // 115712 B
    const int NODE_SMEM = 32960 * 4;   // 131840 B
    cudaFuncSetAttribute(precompute_kernel, cudaFuncAttributeMaxDynamicSharedMemorySize, PRE_SMEM);
    cudaFuncSetAttribute(edge_kernel,       cudaFuncAttributeMaxDynamicSharedMemorySize, EDGE_SMEM);
    cudaFuncSetAttribute(node_kernel,       cudaFuncAttributeMaxDynamicSharedMemorySize, NODE_SMEM);

    zero_agg_kernel<<<304, 256>>>();
    precompute_kernel<<<304, 256, PRE_SMEM>>>(x, We1, be1);
    edge_kernel<<<152, 256, EDGE_SMEM>>>(e, senders, receivers, We1, We2, be2, We3, be3);
    node_kernel<<<152, 256, NODE_SMEM>>>(x, Wn1, bn1, Wn2, bn2, Wn3, bn3, out);
}

// round 5
// speedup vs baseline: 2.6528x; 1.3050x over previous
#include <cuda_runtime.h>
#include <cuda_bf16.h>
#include <cstdint>

#define NN 100000
#define NE 1600000
using u64 = unsigned long long;

// TC_PATH=1 on the sm_103a device pass (tcgen05 available) and on the host pass;
// 0 on any family/PTX device pass (falls back to the scalar f32x2 implementation).
#if !defined(__CUDA_ARCH__) || defined(__CUDA_ARCH_FEAT_SM103_ALL)
#define TC_PATH 1
#else
#define TC_PATH 0
#endif

// scratch (static device globals: allocation-free)
__device__ float g_agg[NN * 64];
__device__ float g_Xs[NN * 64];   // scalar path
__device__ float g_Xr[NN * 64];   // scalar path
__device__ uint4 g_xh[NN * 8];    // TC path: x split bf16 hi
__device__ uint4 g_xl[NN * 8];    // TC path: x split bf16 lo

// ===================== common helpers =====================
__device__ __forceinline__ void red_add_v4(float* a, float x, float y, float z, float w) {
    asm volatile("red.global.add.v4.f32 [%0], {%1, %2, %3, %4};"
                 :: "l"(a), "f"(x), "f"(y), "f"(z), "f"(w) : "memory");
}

// ===================== scalar (f32x2) machinery =====================
__device__ __forceinline__ u64 pk2(float lo, float hi) {
    u64 r; asm("mov.b64 %0, {%1, %2};" : "=l"(r) : "f"(lo), "f"(hi)); return r;
}
__device__ __forceinline__ void fma2s(u64& d, u64 a, u64 b) {
    asm("fma.rn.f32x2 %0, %1, %2, %0;" : "+l"(d) : "l"(a), "l"(b));
}
__device__ __forceinline__ float2 upk(u64 v) {
    float2 f; asm("mov.b64 {%0, %1}, %2;" : "=f"(f.x), "=f"(f.y) : "l"(v)); return f;
}
template<int K, int SGR>
__device__ __forceinline__ void gemm_core(const float4* __restrict__ As4,
                                          const ulonglong2* __restrict__ Wv,
                                          int tr, int tc, u64 acc[4][4]) {
#pragma unroll
    for (int r = 0; r < 4; r++)
#pragma unroll
        for (int j = 0; j < 4; j++) acc[r][j] = 0ull;
    const int sw = tr & 7;
    const int r0 = tr * 4;
#pragma unroll 4
    for (int kg = 0; kg < K / 4; kg++) {
        float4 av[4];
#pragma unroll
        for (int rr = 0; rr < 4; rr++) av[rr] = As4[(r0 + rr) * SGR + (kg ^ sw)];
#pragma unroll
        for (int j = 0; j < 4; j++) {
            const int k = kg * 4 + j;
            ulonglong2 wa = Wv[k * 16 + tc];
            ulonglong2 wb = Wv[k * 16 + 8 + tc];
#pragma unroll
            for (int rr = 0; rr < 4; rr++) {
                float a = (j == 0) ? av[rr].x : (j == 1) ? av[rr].y : (j == 2) ? av[rr].z : av[rr].w;
                u64 aa = pk2(a, a);
                fma2s(acc[rr][0], aa, wa.x);
                fma2s(acc[rr][1], aa, wa.y);
                fma2s(acc[rr][2], aa, wb.x);
                fma2s(acc[rr][3], aa, wb.y);
            }
        }
    }
}
__device__ __forceinline__ void load_w(float* dst, const float* __restrict__ src,
                                       int nelem, int tid) {
    for (int i = tid; i < nelem; i += 256) {
        int k = i >> 6, g = (i >> 2) & 15, w = i & 3;
        dst[k * 64 + ((((g & 1) << 3) | (g >> 1)) << 2) + w] = src[i];
    }
}

// ===================== tcgen05 machinery (sm_103a only) =====================
#if TC_PATH
__device__ __forceinline__ uint32_t smem_u32(const void* p) {
    return (uint32_t)__cvta_generic_to_shared(p);
}
__device__ __forceinline__ bool elect1() {
    uint32_t pr;
    asm volatile("{\n\t.reg .pred p;\n\telect.sync _|p, 0xFFFFFFFF;\n\tselp.b32 %0, 1, 0, p;\n\t}" : "=r"(pr));
    return pr != 0;
}
#define TC_ALLOC(a, n)  asm volatile("tcgen05.alloc.cta_group::1.sync.aligned.shared::cta.b32 [%0], %1;" :: "r"(a), "r"((uint32_t)(n)) : "memory")
#define TC_DEALLOC(t, n) asm volatile("tcgen05.dealloc.cta_group::1.sync.aligned.b32 %0, %1;" :: "r"(t), "r"((uint32_t)(n)))
#define TC_COMMIT(mb)   asm volatile("tcgen05.commit.cta_group::1.mbarrier::arrive::one.shared::cluster.b64 [%0];" :: "r"(mb) : "memory")
#define TC_FA()         asm volatile("tcgen05.fence::after_thread_sync;" ::: "memory")
#define TC_FB()         asm volatile("tcgen05.fence::before_thread_sync;" ::: "memory")
#define TC_WLD()        asm volatile("tcgen05.wait::ld.sync.aligned;" ::: "memory")
#define FENCE_ASYNC()   asm volatile("fence.proxy.async.shared::cta;" ::: "memory")
#define MB_INIT(mb, c)  asm volatile("mbarrier.init.shared.b64 [%0], %1;" :: "r"(mb), "r"((uint32_t)(c)) : "memory")
#define MB_WAIT(mb, ph) do { \
    uint32_t _m = (mb), _p = (ph), _d; \
    asm volatile("{\n\t.reg .pred p;\n\tmbarrier.try_wait.parity.acquire.cta.shared::cta.b64 p, [%1], %2;\n\tselp.b32 %0, 1, 0, p;\n\t}" \
        : "=r"(_d) : "r"(_m), "r"(_p) : "memory"); \
    if (!_d) { \
        asm volatile("{\n\t.reg .pred P1;\n\tWL_%=:\n\tmbarrier.try_wait.parity.acquire.cta.shared::cta.b64 P1, [%0], %1, 0x989680;\n\t@P1 bra.uni WD_%=;\n\tbra.uni WL_%=;\n\tWD_%=:\n\t}" \
            :: "r"(_m), "r"(_p) : "memory"); } \
} while (0)
#define TC_LD_X32(r, tm) \
    asm volatile("tcgen05.ld.sync.aligned.32x32b.x32.b32 " \
        "{%0,%1,%2,%3,%4,%5,%6,%7,%8,%9,%10,%11,%12,%13,%14,%15," \
        "%16,%17,%18,%19,%20,%21,%22,%23,%24,%25,%26,%27,%28,%29,%30,%31}, [%32];" \
        : "=r"((r)[0]),"=r"((r)[1]),"=r"((r)[2]),"=r"((r)[3]),"=r"((r)[4]),"=r"((r)[5]),"=r"((r)[6]),"=r"((r)[7]), \
          "=r"((r)[8]),"=r"((r)[9]),"=r"((r)[10]),"=r"((r)[11]),"=r"((r)[12]),"=r"((r)[13]),"=r"((r)[14]),"=r"((r)[15]), \
          "=r"((r)[16]),"=r"((r)[17]),"=r"((r)[18]),"=r"((r)[19]),"=r"((r)[20]),"=r"((r)[21]),"=r"((r)[22]),"=r"((r)[23]), \
          "=r"((r)[24]),"=r"((r)[25]),"=r"((r)[26]),"=r"((r)[27]),"=r"((r)[28]),"=r"((r)[29]),"=r"((r)[30]),"=r"((r)[31]) \
        : "r"(tm))

#define SWZ(b) ((b) ^ (((b) >> 3) & 0x70))
// A tile (K-major bf16, SW128 blocked atoms, 128 rows): row r, 64-col block c, 16B granule g
#define OFFA(r, c, g) ((uint32_t)(((c) * 16u + ((uint32_t)(r) >> 3)) * 1024u + SWZ((uint32_t)((((r) & 7) * 128) + (g) * 16))))
// B (weights, 64 N-rows): n row, k element
#define OFFB(n, k) ((uint32_t)(((uint32_t)((k) >> 6) * 8u + ((uint32_t)(n) >> 3)) * 1024u + SWZ((uint32_t)((((n) & 7) * 128) + ((k) & 63) * 2))))

static __device__ __forceinline__ u64 mkdesc(uint32_t a) {
    return (2ULL << 61) | (1ULL << 46) | (64ULL << 32) | (1ULL << 16) | ((u64)(a >> 4) & 0x3FFF);
}
#define IDESC 0x8100490u  // f32 accum, bf16 x bf16, M=128, N=64
__device__ __forceinline__ void mma_ss(uint32_t d, u64 ad, u64 bd, uint32_t en) {
    asm volatile("{\n\t.reg .pred p;\n\tsetp.ne.u32 p, %5, 0;\n\t"
                 "tcgen05.mma.cta_group::1.kind::f16 [%0], %1, %2, %3, {%4, %4, %4, %4}, p;\n\t}"
                 :: "r"(d), "l"(ad), "l"(bd), "r"(IDESC), "r"(0u), "r"(en) : "memory");
}
// 3-pass split-bf16: D = Ah*Bh + Al*Bh + Ah*Bl  (nks K=16 steps per pass)
__device__ __forceinline__ void mma_layer(uint32_t d, u64 ah, u64 al, u64 bh, u64 bl, int nks) {
#pragma unroll
    for (int p = 0; p < 3; p++) {
        u64 A = (p == 1) ? al : ah;
        u64 B = (p == 2) ? bl : bh;
        for (int ks = 0; ks < nks; ks++)
            mma_ss(d, A + (ks >> 2) * 1024 + (ks & 3) * 2, B + (ks >> 2) * 512 + (ks & 3) * 2,
                   (p | ks) ? 1u : 0u);
    }
}
__device__ __forceinline__ void split2(float a, float b, uint32_t& hi, uint32_t& lo) {
    __nv_bfloat162 h = __floats2bfloat162_rn(a, b);
    float2 hf = __bfloat1622float2(h);
    __nv_bfloat162 l = __floats2bfloat162_rn(a - hf.x, b - hf.y);
    hi = *(uint32_t*)&h;
    lo = *(uint32_t*)&l;
}
__device__ __forceinline__ void pack8f(float4 u, float4 v, uint4& hi, uint4& lo) {
    split2(u.x, u.y, hi.x, lo.x);
    split2(u.z, u.w, hi.y, lo.y);
    split2(v.x, v.y, hi.z, lo.z);
    split2(v.z, v.w, hi.w, lo.w);
}
__device__ __forceinline__ void store_wsplit(char* smc, int oh, int ol, uint32_t off, float v) {
    __nv_bfloat16 h = __float2bfloat16(v);
    __nv_bfloat16 l = __float2bfloat16(v - __bfloat162float(h));
    *(unsigned short*)(smc + oh + off) = __bfloat16_as_ushort(h);
    *(unsigned short*)(smc + ol + off) = __bfloat16_as_ushort(l);
}
// relu(d + bias) -> split -> store cols c0..c0+31 of row r into A atom-col 0
__device__ __forceinline__ void epi_relu(char* smc, int AH, int AL, const uint32_t* d,
                                         const float* bias, int r, int c0) {
#pragma unroll
    for (int jj = 0; jj < 4; jj++) {
        float h[8];
#pragma unroll
        for (int j = 0; j < 8; j++)
            h[j] = fmaxf(__uint_as_float(d[jj * 8 + j]) + bias[c0 + jj * 8 + j], 0.f);
        uint4 hi, lo;
        pack8f(make_float4(h[0], h[1], h[2], h[3]), make_float4(h[4], h[5], h[6], h[7]), hi, lo);
        uint32_t off = OFFA(r, 0, (c0 >> 3) + jj);
        *(uint4*)(smc + AH + off) = hi;
        *(uint4*)(smc + AL + off) = lo;
    }
}
#endif  // TC_PATH

// ===================== small kernels =====================
__global__ void zero_agg_kernel() {
    int i = blockIdx.x * blockDim.x + threadIdx.x;
    float4* p = (float4*)g_agg;
    for (; i < NN * 16; i += gridDim.x * blockDim.x) p[i] = make_float4(0.f, 0.f, 0.f, 0.f);
}

__global__ void split_x_kernel(const float* __restrict__ x) {
#if TC_PATH
    int i = blockIdx.x * blockDim.x + threadIdx.x;
    const float4* x4 = (const float4*)x;
    for (; i < NN * 8; i += gridDim.x * blockDim.x) {
        uint4 hi, lo;
        pack8f(x4[2 * i], x4[2 * i + 1], hi, lo);
        g_xh[i] = hi;
        g_xl[i] = lo;
    }
#endif
}

// precompute (scalar fallback only): Xs = x@We1[64:128], Xr = x@We1[128:192] + be1
__global__ __launch_bounds__(256)
void precompute_kernel(const float* __restrict__ x,
                       const float* __restrict__ We1,
                       const float* __restrict__ be1) {
#if !TC_PATH
    extern __shared__ float sm[];
    float* Ws = sm;
    float* Wr = sm + 4096;
    float* b1 = sm + 8192;
    float* As = sm + 8256;
    const int tid = threadIdx.x;
    load_w(Ws, We1 + 64 * 64, 4096, tid);
    load_w(Wr, We1 + 128 * 64, 4096, tid);
    if (tid < 64) b1[tid] = be1[tid];
    __syncthreads();
    const int tr = tid >> 3, tc = tid & 7, r0 = tr * 4;
    float4* As4 = (float4*)As;
    const ulonglong2* Wsv = (const ulonglong2*)Ws;
    const ulonglong2* Wrv = (const ulonglong2*)Wr;
    const float4* x4 = (const float4*)x;
    float4* Xs4 = (float4*)g_Xs;
    float4* Xr4 = (float4*)g_Xr;
    const int NT = (NN + 127) / 128;
    u64 acc[4][4];
    float4 bb0 = *(float4*)&b1[8 * tc];
    float4 bb1 = *(float4*)&b1[8 * tc + 4];
    for (int tile = blockIdx.x; tile < NT; tile += gridDim.x) {
        const int base = tile * 128;
        for (int i = tid; i < 2048; i += 256) {
            int r = i >> 4, g = i & 15;
            int n = base + r;
            As4[r * 16 + (g ^ ((r >> 2) & 7))] =
                (n < NN) ? x4[n * 16 + g] : make_float4(0.f, 0.f, 0.f, 0.f);
        }
        __syncthreads();
        gemm_core<64, 16>(As4, Wsv, tr, tc, acc);
#pragma unroll
        for (int rr = 0; rr < 4; rr++) {
            int n = base + r0 + rr;
            if (n < NN) {
                float2 p0 = upk(acc[rr][0]), p1 = upk(acc[rr][1]),
                       p2 = upk(acc[rr][2]), p3 = upk(acc[rr][3]);
                Xs4[n * 16 + 2 * tc]     = make_float4(p0.x, p0.y, p1.x, p1.y);
                Xs4[n * 16 + 2 * tc + 1] = make_float4(p2.x, p2.y, p3.x, p3.y);
            }
        }
        gemm_core<64, 16>(As4, Wrv, tr, tc, acc);
#pragma unroll
        for (int rr = 0; rr < 4; rr++) {
            int n = base + r0 + rr;
            if (n < NN) {
                float2 p0 = upk(acc[rr][0]), p1 = upk(acc[rr][1]),
                       p2 = upk(acc[rr][2]), p3 = upk(acc[rr][3]);
                Xr4[n * 16 + 2 * tc]     = make_float4(p0.x + bb0.x, p0.y + bb0.y, p1.x + bb0.z, p1.y + bb0.w);
                Xr4[n * 16 + 2 * tc + 1] = make_float4(p2.x + bb1.x, p2.y + bb1.y, p3.x + bb1.z, p3.y + bb1.w);
            }
        }
        __syncthreads();
    }
#endif
}

// ===================== edge kernel =====================
#define E_TP 0
#define E_MB 16
#define E_B1 64
#define E_B2 320
#define E_B3 576
#define E_SS 832
#define E_TT 1344
#define E_AH 4096
#define E_AL 53248
#define E_W1H 102400
#define E_W1L 126976
#define E_W2H 151552
#define E_W2L 159744
#define E_W3H 167936
#define E_W3L 176128
#define E_SZ 184320

__global__ __launch_bounds__(256)
void edge_mma_kernel(const float* __restrict__ e,
                     const int* __restrict__ senders,
                     const int* __restrict__ receivers,
                     const float* __restrict__ We1, const float* __restrict__ be1,
                     const float* __restrict__ We2, const float* __restrict__ be2,
                     const float* __restrict__ We3, const float* __restrict__ be3) {
    extern __shared__ char smc[];
    const int tid = threadIdx.x;
#if TC_PATH
    const uint32_t sb = smem_u32(smc);
    const int wid = tid >> 5, lane = tid & 31;

    if (wid == 0) TC_ALLOC(sb + E_TP, 64);
    if (tid == 0) MB_INIT(sb + E_MB, 1);
    float* b1s = (float*)(smc + E_B1);
    float* b2s = (float*)(smc + E_B2);
    float* b3s = (float*)(smc + E_B3);
    int* ss = (int*)(smc + E_SS);
    int* tt = (int*)(smc + E_TT);
    if (tid < 64) { b1s[tid] = be1[tid]; b2s[tid] = be2[tid]; b3s[tid] = be3[tid]; }
    for (int i = tid; i < 12288; i += 256) {
        int k = i >> 6, n = i & 63;
        store_wsplit(smc, E_W1H, E_W1L, OFFB(n, k), We1[i]);
    }
    for (int i = tid; i < 4096; i += 256) {
        int k = i >> 6, n = i & 63;
        uint32_t o = OFFB(n, k);
        store_wsplit(smc, E_W2H, E_W2L, o, We2[i]);
        store_wsplit(smc, E_W3H, E_W3L, o, We3[i]);
    }
    __syncthreads();
    uint32_t tmem;
    asm volatile("ld.shared.b32 %0, [%1];" : "=r"(tmem) : "r"(sb + E_TP));

    const u64 dAh = mkdesc(sb + E_AH), dAl = mkdesc(sb + E_AL);
    const u64 dW1h = mkdesc(sb + E_W1H), dW1l = mkdesc(sb + E_W1L);
    const u64 dW2h = mkdesc(sb + E_W2H), dW2l = mkdesc(sb + E_W2L);
    const u64 dW3h = mkdesc(sb + E_W3H), dW3l = mkdesc(sb + E_W3L);
    const float4* e4 = (const float4*)e;
    uint32_t ph = 0;
    const int row = (wid & 3) * 32 + lane;
    const int c0 = (wid >= 4) ? 32 : 0;
    uint32_t d[32];

    for (int tile = blockIdx.x; tile < NE / 128; tile += gridDim.x) {
        const int base = tile * 128;
        if (tid < 128) { ss[tid] = senders[base + tid]; tt[tid] = receivers[base + tid]; }
        __syncthreads();
        for (int i = tid; i < 1024; i += 256) {
            int r = i >> 3, g = i & 7;
            uint4 hi, lo;
            pack8f(e4[(base + r) * 16 + 2 * g], e4[(base + r) * 16 + 2 * g + 1], hi, lo);
            uint32_t o0 = OFFA(r, 0, g);
            *(uint4*)(smc + E_AH + o0) = hi;
            *(uint4*)(smc + E_AL + o0) = lo;
            int s = ss[r], t = tt[r];
            uint32_t o1 = OFFA(r, 1, g);
            *(uint4*)(smc + E_AH + o1) = g_xh[s * 8 + g];
            *(uint4*)(smc + E_AL + o1) = g_xl[s * 8 + g];
            uint32_t o2 = OFFA(r, 2, g);
            *(uint4*)(smc + E_AH + o2) = g_xh[t * 8 + g];
            *(uint4*)(smc + E_AL + o2) = g_xl[t * 8 + g];
        }
        FENCE_ASYNC();
        __syncthreads();
        // layer 1 (K=192)
        if (wid == 0 && elect1()) { mma_layer(tmem, dAh, dAl, dW1h, dW1l, 12); TC_COMMIT(sb + E_MB); }
        MB_WAIT(sb + E_MB, ph); ph ^= 1;
        TC_FA();
        TC_LD_X32(d, tmem + c0);
        TC_WLD(); TC_FB();
        epi_relu(smc, E_AH, E_AL, d, b1s, row, c0);
        FENCE_ASYNC();
        __syncthreads();
        // layer 2 (K=64)
        if (wid == 0 && elect1()) { mma_layer(tmem, dAh, dAl, dW2h, dW2l, 4); TC_COMMIT(sb + E_MB); }
        MB_WAIT(sb + E_MB, ph); ph ^= 1;
        TC_FA();
        TC_LD_X32(d, tmem + c0);
        TC_WLD(); TC_FB();
        epi_relu(smc, E_AH, E_AL, d, b2s, row, c0);
        FENCE_ASYNC();
        __syncthreads();
        // layer 3 (K=64) -> atomic segment sum
        if (wid == 0 && elect1()) { mma_layer(tmem, dAh, dAl, dW3h, dW3l, 4); TC_COMMIT(sb + E_MB); }
        MB_WAIT(sb + E_MB, ph); ph ^= 1;
        TC_FA();
        TC_LD_X32(d, tmem + c0);
        TC_WLD(); TC_FB();
        {
            float* p = &g_agg[(size_t)tt[row] * 64 + c0];
#pragma unroll
            for (int jj = 0; jj < 4; jj++) {
                float v[8];
#pragma unroll
                for (int j = 0; j < 8; j++)
                    v[j] = __uint_as_float(d[jj * 8 + j]) + b3s[c0 + jj * 8 + j];
                red_add_v4(p + jj * 8, v[0], v[1], v[2], v[3]);
                red_add_v4(p + jj * 8 + 4, v[4], v[5], v[6], v[7]);
            }
        }
        __syncthreads();
    }
    if (wid == 0) TC_DEALLOC(tmem, 64);
#else
    // ---------- scalar fallback (R2) ----------
    float* sm = (float*)smc;
    float* W1 = sm;
    float* W2 = sm + 4096;
    float* W3 = sm + 8192;
    float* b2 = sm + 12288;
    float* b3 = sm + 12352;
    int*   rv = (int*)(sm + 12416);
    float* As = sm + 12544;
    float* Bx = sm + 20736;
    load_w(W1, We1, 4096, tid);
    load_w(W2, We2, 4096, tid);
    load_w(W3, We3, 4096, tid);
    if (tid < 64) { b2[tid] = be2[tid]; b3[tid] = be3[tid]; }
    __syncthreads();
    const int tr = tid >> 3, tc = tid & 7, sw = tr & 7, r0 = tr * 4;
    float4* As4 = (float4*)As;
    float4* Bx4 = (float4*)Bx;
    const ulonglong2* W1v = (const ulonglong2*)W1;
    const ulonglong2* W2v = (const ulonglong2*)W2;
    const ulonglong2* W3v = (const ulonglong2*)W3;
    const float4* e4  = (const float4*)e;
    const float4* Xs4 = (const float4*)g_Xs;
    const float4* Xr4 = (const float4*)g_Xr;
    u64 acc[4][4];
    float4 bb0 = *(float4*)&b2[8 * tc];
    float4 bb1 = *(float4*)&b2[8 * tc + 4];
    float4 cc0 = *(float4*)&b3[8 * tc];
    float4 cc1 = *(float4*)&b3[8 * tc + 4];
    for (int tile = blockIdx.x; tile < NE / 128; tile += gridDim.x) {
        const int base = tile * 128;
        if (tid < 128) rv[tid] = receivers[base + tid];
        for (int i = tid; i < 2048; i += 256) {
            int r = i >> 4, g = i & 15;
            As4[r * 16 + (g ^ ((r >> 2) & 7))] = e4[(base + r) * 16 + g];
        }
        for (int i = tid; i < 2048; i += 256) {
            int r = i >> 4, g = i & 15;
            int s = senders[base + r], t = receivers[base + r];
            float4 a = Xs4[s * 16 + g], b = Xr4[t * 16 + g];
            Bx4[r * 16 + (g ^ ((r >> 2) & 7))] =
                make_float4(a.x + b.x, a.y + b.y, a.z + b.z, a.w + b.w);
        }
        __syncthreads();
        gemm_core<64, 16>(As4, W1v, tr, tc, acc);
        __syncthreads();
#pragma unroll
        for (int rr = 0; rr < 4; rr++) {
            int r = r0 + rr;
            float4 x0 = Bx4[r * 16 + ((2 * tc) ^ sw)];
            float4 x1 = Bx4[r * 16 + ((2 * tc + 1) ^ sw)];
            float2 p0 = upk(acc[rr][0]), p1 = upk(acc[rr][1]),
                   p2 = upk(acc[rr][2]), p3 = upk(acc[rr][3]);
            As4[r * 16 + ((2 * tc) ^ sw)] =
                make_float4(fmaxf(p0.x + x0.x, 0.f), fmaxf(p0.y + x0.y, 0.f),
                            fmaxf(p1.x + x0.z, 0.f), fmaxf(p1.y + x0.w, 0.f));
            As4[r * 16 + ((2 * tc + 1) ^ sw)] =
                make_float4(fmaxf(p2.x + x1.x, 0.f), fmaxf(p2.y + x1.y, 0.f),
                            fmaxf(p3.x + x1.z, 0.f), fmaxf(p3.y + x1.w, 0.f));
        }
        __syncthreads();
        gemm_core<64, 16>(As4, W2v, tr, tc, acc);
        __syncthreads();
#pragma unroll
        for (int rr = 0; rr < 4; rr++) {
            int r = r0 + rr;
            float2 p0 = upk(acc[rr][0]), p1 = upk(acc[rr][1]),
                   p2 = upk(acc[rr][2]), p3 = upk(acc[rr][3]);
            As4[r * 16 + ((2 * tc) ^ sw)] =
                make_float4(fmaxf(p0.x + bb0.x, 0.f), fmaxf(p0.y + bb0.y, 0.f),
                            fmaxf(p1.x + bb0.z, 0.f), fmaxf(p1.y + bb0.w, 0.f));
            As4[r * 16 + ((2 * tc + 1) ^ sw)] =
                make_float4(fmaxf(p2.x + bb1.x, 0.f), fmaxf(p2.y + bb1.y, 0.f),
                            fmaxf(p3.x + bb1.z, 0.f), fmaxf(p3.y + bb1.w, 0.f));
        }
        __syncthreads();
        gemm_core<64, 16>(As4, W3v, tr, tc, acc);
#pragma unroll
        for (int rr = 0; rr < 4; rr++) {
            float2 p0 = upk(acc[rr][0]), p1 = upk(acc[rr][1]),
                   p2 = upk(acc[rr][2]), p3 = upk(acc[rr][3]);
            float* p = &g_agg[rv[r0 + rr] * 64 + 8 * tc];
            red_add_v4(p,     p0.x + cc0.x, p0.y + cc0.y, p1.x + cc0.z, p1.y + cc0.w);
            red_add_v4(p + 4, p2.x + cc1.x, p2.y + cc1.y, p3.x + cc1.z, p3.y + cc1.w);
        }
        __syncthreads();
    }
#endif
}

// ===================== node kernel =====================
#define N_TP 0
#define N_MB 16
#define N_B1 64
#define N_B2 320
#define N_B3 576
#define N_AH 1024
#define N_AL 33792
#define N_W1H 66560
#define N_W1L 82944
#define N_W2H 99328
#define N_W2L 107520
#define N_W3H 115712
#define N_W3L 123904
#define N_SZ 132096

__global__ __launch_bounds__(256)
void node_mma_kernel(const float* __restrict__ x,
                     const float* __restrict__ Wn1, const float* __restrict__ bn1,
                     const float* __restrict__ Wn2, const float* __restrict__ bn2,
                     const float* __restrict__ Wn3, const float* __restrict__ bn3,
                     float* __restrict__ out) {
    extern __shared__ char smc[];
    const int tid = threadIdx.x;
#if TC_PATH
    const uint32_t sb = smem_u32(smc);
    const int wid = tid >> 5, lane = tid & 31;

    if (wid == 0) TC_ALLOC(sb + N_TP, 64);
    if (tid == 0) MB_INIT(sb + N_MB, 1);
    float* b1s = (float*)(smc + N_B1);
    float* b2s = (float*)(smc + N_B2);
    float* b3s = (float*)(smc + N_B3);
    if (tid < 64) { b1s[tid] = bn1[tid]; b2s[tid] = bn2[tid]; b3s[tid] = bn3[tid]; }
    for (int i = tid; i < 8192; i += 256) {
        int k = i >> 6, n = i & 63;
        store_wsplit(smc, N_W1H, N_W1L, OFFB(n, k), Wn1[i]);
    }
    for (int i = tid; i < 4096; i += 256) {
        int k = i >> 6, n = i & 63;
        uint32_t o = OFFB(n, k);
        store_wsplit(smc, N_W2H, N_W2L, o, Wn2[i]);
        store_wsplit(smc, N_W3H, N_W3L, o, Wn3[i]);
    }
    __syncthreads();
    uint32_t tmem;
    asm volatile("ld.shared.b32 %0, [%1];" : "=r"(tmem) : "r"(sb + N_TP));

    const u64 dAh = mkdesc(sb + N_AH), dAl = mkdesc(sb + N_AL);
    const u64 dW1h = mkdesc(sb + N_W1H), dW1l = mkdesc(sb + N_W1L);
    const u64 dW2h = mkdesc(sb + N_W2H), dW2l = mkdesc(sb + N_W2L);
    const u64 dW3h = mkdesc(sb + N_W3H), dW3l = mkdesc(sb + N_W3L);
    const float4* ag4 = (const float4*)g_agg;
    uint32_t ph = 0;
    const int row = (wid & 3) * 32 + lane;
    const int c0 = (wid >= 4) ? 32 : 0;
    uint32_t d[32];
    const int NT = (NN + 127) / 128;

    for (int tile = blockIdx.x; tile < NT; tile += gridDim.x) {
        const int base = tile * 128;
        for (int i = tid; i < 1024; i += 256) {
            int r = i >> 3, g = i & 7, n = base + r;
            uint4 xh = make_uint4(0, 0, 0, 0), xl = xh, ah = xh, al = xh;
            if (n < NN) {
                xh = g_xh[n * 8 + g];
                xl = g_xl[n * 8 + g];
                pack8f(ag4[n * 16 + 2 * g], ag4[n * 16 + 2 * g + 1], ah, al);
            }
            uint32_t o0 = OFFA(r, 0, g);
            *(uint4*)(smc + N_AH + o0) = xh;
            *(uint4*)(smc + N_AL + o0) = xl;
            uint32_t o1 = OFFA(r, 1, g);
            *(uint4*)(smc + N_AH + o1) = ah;
            *(uint4*)(smc + N_AL + o1) = al;
        }
        FENCE_ASYNC();
        __syncthreads();
        // layer 1 (K=128)
        if (wid == 0 && elect1()) { mma_layer(tmem, dAh, dAl, dW1h, dW1l, 8); TC_COMMIT(sb + N_MB); }
        MB_WAIT(sb + N_MB, ph); ph ^= 1;
        TC_FA();
        TC_LD_X32(d, tmem + c0);
        TC_WLD(); TC_FB();
        epi_relu(smc, N_AH, N_AL, d, b1s, row, c0);
        FENCE_ASYNC();
        __syncthreads();
        // layer 2
        if (wid == 0 && elect1()) { mma_layer(tmem, dAh, dAl, dW2h, dW2l, 4); TC_COMMIT(sb + N_MB); }
        MB_WAIT(sb + N_MB, ph); ph ^= 1;
        TC_FA();
        TC_LD_X32(d, tmem + c0);
        TC_WLD(); TC_FB();
        epi_relu(smc, N_AH, N_AL, d, b2s, row, c0);
        FENCE_ASYNC();
        __syncthreads();
        // layer 3 -> out
        if (wid == 0 && elect1()) { mma_layer(tmem, dAh, dAl, dW3h, dW3l, 4); TC_COMMIT(sb + N_MB); }
        MB_WAIT(sb + N_MB, ph); ph ^= 1;
        TC_FA();
        TC_LD_X32(d, tmem + c0);
        TC_WLD(); TC_FB();
        {
            int n = base + row;
            if (n < NN) {
#pragma unroll
                for (int jj = 0; jj < 4; jj++) {
                    float v[8];
#pragma unroll
                    for (int j = 0; j < 8; j++)
                        v[j] = __uint_as_float(d[jj * 8 + j]) + b3s[c0 + jj * 8 + j];
                    *(float4*)&out[n * 64 + c0 + jj * 8]     = make_float4(v[0], v[1], v[2], v[3]);
                    *(float4*)&out[n * 64 + c0 + jj * 8 + 4] = make_float4(v[4], v[5], v[6], v[7]);
                }
            }
        }
        __syncthreads();
    }
    if (wid == 0) TC_DEALLOC(tmem, 64);
#else
    // ---------- scalar fallback (R2) ----------
    float* sm = (float*)smc;
    float* W1 = sm;
    float* W2 = sm + 8192;
    float* W3 = sm + 12288;
    float* b1 = sm + 16384;
    float* b2 = sm + 16448;
    float* b3 = sm + 16512;
    float* As = sm + 16576;
    load_w(W1, Wn1, 8192, tid);
    load_w(W2, Wn2, 4096, tid);
    load_w(W3, Wn3, 4096, tid);
    if (tid < 64) { b1[tid] = bn1[tid]; b2[tid] = bn2[tid]; b3[tid] = bn3[tid]; }
    __syncthreads();
    const int tr = tid >> 3, tc = tid & 7, sw = tr & 7, r0 = tr * 4;
    float4* As4 = (float4*)As;
    const ulonglong2* W1v = (const ulonglong2*)W1;
    const ulonglong2* W2v = (const ulonglong2*)W2;
    const ulonglong2* W3v = (const ulonglong2*)W3;
    const float4* x4 = (const float4*)x;
    const float4* Ag4 = (const float4*)g_agg;
    const int NT = (NN + 127) / 128;
    u64 acc[4][4];
    float4 a0 = *(float4*)&b1[8 * tc], a1 = *(float4*)&b1[8 * tc + 4];
    float4 bb0 = *(float4*)&b2[8 * tc], bb1 = *(float4*)&b2[8 * tc + 4];
    float4 cc0 = *(float4*)&b3[8 * tc], cc1 = *(float4*)&b3[8 * tc + 4];
    for (int tile = blockIdx.x; tile < NT; tile += gridDim.x) {
        const int base = tile * 128;
        for (int i = tid; i < 2048; i += 256) {
            int r = i >> 4, g = i & 15;
            int n = base + r;
            int s = (r >> 2) & 7;
            float4 vx = make_float4(0.f, 0.f, 0.f, 0.f), va = vx;
            if (n < NN) { vx = x4[n * 16 + g]; va = Ag4[n * 16 + g]; }
            As4[r * 32 + (g ^ s)]      = vx;
            As4[r * 32 + 16 + (g ^ s)] = va;
        }
        __syncthreads();
        gemm_core<128, 32>(As4, W1v, tr, tc, acc);
        __syncthreads();
#pragma unroll
        for (int rr = 0; rr < 4; rr++) {
            int r = r0 + rr;
            float2 p0 = upk(acc[rr][0]), p1 = upk(acc[rr][1]),
                   p2 = upk(acc[rr][2]), p3 = upk(acc[rr][3]);
            As4[r * 32 + ((2 * tc) ^ sw)] =
                make_float4(fmaxf(p0.x + a0.x, 0.f), fmaxf(p0.y + a0.y, 0.f),
                            fmaxf(p1.x + a0.z, 0.f), fmaxf(p1.y + a0.w, 0.f));
            As4[r * 32 + ((2 * tc + 1) ^ sw)] =
                make_float4(fmaxf(p2.x + a1.x, 0.f), fmaxf(p2.y + a1.y, 0.f),
                            fmaxf(p3.x + a1.z, 0.f), fmaxf(p3.y + a1.w, 0.f));
        }
        __syncthreads();
        gemm_core<64, 32>(As4, W2v, tr, tc, acc);
        __syncthreads();
#pragma unroll
        for (int rr = 0; rr < 4; rr++) {
            int r = r0 + rr;
            float2 p0 = upk(acc[rr][0]), p1 = upk(acc[rr][1]),
                   p2 = upk(acc[rr][2]), p3 = upk(acc[rr][3]);
            As4[r * 32 + ((2 * tc) ^ sw)] =
                make_float4(fmaxf(p0.x + bb0.x, 0.f), fmaxf(p0.y + bb0.y, 0.f),
                            fmaxf(p1.x + bb0.z, 0.f), fmaxf(p1.y + bb0.w, 0.f));
            As4[r * 32 + ((2 * tc + 1) ^ sw)] =
                make_float4(fmaxf(p2.x + bb1.x, 0.f), fmaxf(p2.y + bb1.y, 0.f),
                            fmaxf(p3.x + bb1.z, 0.f), fmaxf(p3.y + bb1.w, 0.f));
        }
        __syncthreads();
        gemm_core<64, 32>(As4, W3v, tr, tc, acc);
#pragma unroll
        for (int rr = 0; rr < 4; rr++) {
            int n = base + r0 + rr;
            if (n < NN) {
                float2 p0 = upk(acc[rr][0]), p1 = upk(acc[rr][1]),
                       p2 = upk(acc[rr][2]), p3 = upk(acc[rr][3]);
                *(float4*)&out[n * 64 + 8 * tc] =
                    make_float4(p0.x + cc0.x, p0.y + cc0.y, p1.x + cc0.z, p1.y + cc0.w);
                *(float4*)&out[n * 64 + 8 * tc + 4] =
                    make_float4(p2.x + cc1.x, p2.y + cc1.y, p3.x + cc1.z, p3.y + cc1.w);
            }
        }
        __syncthreads();
    }
#endif
}

// ===================== launch =====================
extern "C" void kernel_launch(void* const* d_in, const int* in_sizes, int n_in,
                              void* d_out, int out_size) {
    const float* x         = (const float*)d_in[0];
    const float* e         = (const float*)d_in[1];
    const int*   senders   = (const int*)d_in[2];
    const int*   receivers = (const int*)d_in[3];
    const float* We1 = (const float*)d_in[4];
    const float* be1 = (const float*)d_in[5];
    const float* We2 = (const float*)d_in[6];
    const float* be2 = (const float*)d_in[7];
    const float* We3 = (const float*)d_in[8];
    const float* be3 = (const float*)d_in[9];
    const float* Wn1 = (const float*)d_in[10];
    const float* bn1 = (const float*)d_in[11];
    const float* Wn2 = (const float*)d_in[12];
    const float* bn2 = (const float*)d_in[13];
    const float* Wn3 = (const float*)d_in[14];
    const float* bn3 = (const float*)d_in[15];
    float* out = (float*)d_out;

    const int PRE_SMEM = 16448 * 4;  // 65792 B (scalar fallback)
    cudaFuncSetAttribute(precompute_kernel, cudaFuncAttributeMaxDynamicSharedMemorySize, PRE_SMEM);
    cudaFuncSetAttribute(edge_mma_kernel,   cudaFuncAttributeMaxDynamicSharedMemorySize, E_SZ);
    cudaFuncSetAttribute(node_mma_kernel,   cudaFuncAttributeMaxDynamicSharedMemorySize, N_SZ);

    zero_agg_kernel<<<304, 256>>>();
    split_x_kernel<<<304, 256>>>(x);
    precompute_kernel<<<304, 256, PRE_SMEM>>>(x, We1, be1);
    edge_mma_kernel<<<152, 256, E_SZ>>>(e, senders, receivers, We1, be1, We2, be2, We3, be3);
    node_mma_kernel<<<152, 256, N_SZ>>>(x, Wn1, bn1, Wn2, bn2, Wn3, bn3, out);
}

// round 6
// speedup vs baseline: 3.9777x; 1.4994x over previous
#include <cuda_runtime.h>
#include <cuda_bf16.h>
#include <cstdint>

#define NN 100000
#define NE 1600000
using u64 = unsigned long long;

// TC_PATH=1 on the sm_103a device pass (tcgen05 available) and on the host pass.
#if !defined(__CUDA_ARCH__) || defined(__CUDA_ARCH_FEAT_SM103_ALL)
#define TC_PATH 1
#else
#define TC_PATH 0
#endif

// scratch (static device globals: allocation-free)
__device__ float g_agg[NN * 64];
__device__ uint4 g_xh[NN * 8];    // x split: bf16 hi (32 bf16x2 = 8 uint4 per row)
__device__ uint4 g_xl[NN * 8];    // bf16 residual

__device__ __forceinline__ void red_add_v4(float* a, float x, float y, float z, float w) {
    asm volatile("red.global.add.v4.f32 [%0], {%1, %2, %3, %4};"
                 :: "l"(a), "f"(x), "f"(y), "f"(z), "f"(w) : "memory");
}

#if TC_PATH
// ===================== tcgen05 machinery (sm_103a only) =====================
__device__ __forceinline__ uint32_t smem_u32(const void* p) {
    return (uint32_t)__cvta_generic_to_shared(p);
}
__device__ __forceinline__ bool elect1() {
    uint32_t pr;
    asm volatile("{\n\t.reg .pred p;\n\telect.sync _|p, 0xFFFFFFFF;\n\tselp.b32 %0, 1, 0, p;\n\t}" : "=r"(pr));
    return pr != 0;
}
#define TC_ALLOC(a, n)  asm volatile("tcgen05.alloc.cta_group::1.sync.aligned.shared::cta.b32 [%0], %1;" :: "r"(a), "r"((uint32_t)(n)) : "memory")
#define TC_DEALLOC(t, n) asm volatile("tcgen05.dealloc.cta_group::1.sync.aligned.b32 %0, %1;" :: "r"(t), "r"((uint32_t)(n)))
#define TC_COMMIT(mb)   asm volatile("tcgen05.commit.cta_group::1.mbarrier::arrive::one.shared::cluster.b64 [%0];" :: "r"(mb) : "memory")
#define TC_FA()         asm volatile("tcgen05.fence::after_thread_sync;" ::: "memory")
#define TC_FB()         asm volatile("tcgen05.fence::before_thread_sync;" ::: "memory")
#define TC_WLD()        asm volatile("tcgen05.wait::ld.sync.aligned;" ::: "memory")
#define TC_WST()        asm volatile("tcgen05.wait::st.sync.aligned;" ::: "memory")
#define MB_INIT(mb, c)  asm volatile("mbarrier.init.shared.b64 [%0], %1;" :: "r"(mb), "r"((uint32_t)(c)) : "memory")
#define MB_WAIT(mb, ph) do { \
    uint32_t _m = (mb), _p = (ph), _d; \
    asm volatile("{\n\t.reg .pred p;\n\tmbarrier.try_wait.parity.acquire.cta.shared::cta.b64 p, [%1], %2;\n\tselp.b32 %0, 1, 0, p;\n\t}" \
        : "=r"(_d) : "r"(_m), "r"(_p) : "memory"); \
    if (!_d) { \
        asm volatile("{\n\t.reg .pred P1;\n\tWL_%=:\n\tmbarrier.try_wait.parity.acquire.cta.shared::cta.b64 P1, [%0], %1, 0x989680;\n\t@P1 bra.uni WD_%=;\n\tbra.uni WL_%=;\n\tWD_%=:\n\t}" \
            :: "r"(_m), "r"(_p) : "memory"); } \
} while (0)
#define TC_LD_X32(r, tm) \
    asm volatile("tcgen05.ld.sync.aligned.32x32b.x32.b32 " \
        "{%0,%1,%2,%3,%4,%5,%6,%7,%8,%9,%10,%11,%12,%13,%14,%15," \
        "%16,%17,%18,%19,%20,%21,%22,%23,%24,%25,%26,%27,%28,%29,%30,%31}, [%32];" \
        : "=r"((r)[0]),"=r"((r)[1]),"=r"((r)[2]),"=r"((r)[3]),"=r"((r)[4]),"=r"((r)[5]),"=r"((r)[6]),"=r"((r)[7]), \
          "=r"((r)[8]),"=r"((r)[9]),"=r"((r)[10]),"=r"((r)[11]),"=r"((r)[12]),"=r"((r)[13]),"=r"((r)[14]),"=r"((r)[15]), \
          "=r"((r)[16]),"=r"((r)[17]),"=r"((r)[18]),"=r"((r)[19]),"=r"((r)[20]),"=r"((r)[21]),"=r"((r)[22]),"=r"((r)[23]), \
          "=r"((r)[24]),"=r"((r)[25]),"=r"((r)[26]),"=r"((r)[27]),"=r"((r)[28]),"=r"((r)[29]),"=r"((r)[30]),"=r"((r)[31]) \
        : "r"(tm))
#define TC_ST_X32(tm, r) \
    asm volatile("tcgen05.st.sync.aligned.32x32b.x32.b32 [%0], " \
        "{%1,%2,%3,%4,%5,%6,%7,%8,%9,%10,%11,%12,%13,%14,%15,%16," \
        "%17,%18,%19,%20,%21,%22,%23,%24,%25,%26,%27,%28,%29,%30,%31,%32};" \
        :: "r"(tm), \
           "r"((r)[0]),"r"((r)[1]),"r"((r)[2]),"r"((r)[3]),"r"((r)[4]),"r"((r)[5]),"r"((r)[6]),"r"((r)[7]), \
           "r"((r)[8]),"r"((r)[9]),"r"((r)[10]),"r"((r)[11]),"r"((r)[12]),"r"((r)[13]),"r"((r)[14]),"r"((r)[15]), \
           "r"((r)[16]),"r"((r)[17]),"r"((r)[18]),"r"((r)[19]),"r"((r)[20]),"r"((r)[21]),"r"((r)[22]),"r"((r)[23]), \
           "r"((r)[24]),"r"((r)[25]),"r"((r)[26]),"r"((r)[27]),"r"((r)[28]),"r"((r)[29]),"r"((r)[30]),"r"((r)[31]) \
        : "memory")
#define TC_ST_X16(tm, r) \
    asm volatile("tcgen05.st.sync.aligned.32x32b.x16.b32 [%0], " \
        "{%1,%2,%3,%4,%5,%6,%7,%8,%9,%10,%11,%12,%13,%14,%15,%16};" \
        :: "r"(tm), \
           "r"((r)[0]),"r"((r)[1]),"r"((r)[2]),"r"((r)[3]),"r"((r)[4]),"r"((r)[5]),"r"((r)[6]),"r"((r)[7]), \
           "r"((r)[8]),"r"((r)[9]),"r"((r)[10]),"r"((r)[11]),"r"((r)[12]),"r"((r)[13]),"r"((r)[14]),"r"((r)[15]) \
        : "memory")

#define SWZ(b) ((b) ^ (((b) >> 3) & 0x70))
// B (weights in smem, 64 N-rows, K-major, SW128 blocked atoms): n row, k element
#define OFFB(n, k) ((uint32_t)(((uint32_t)((k) >> 6) * 8u + ((uint32_t)(n) >> 3)) * 1024u + SWZ((uint32_t)((((n) & 7) * 128) + ((k) & 63) * 2))))

static __device__ __forceinline__ u64 mkdesc(uint32_t a) {
    return (2ULL << 61) | (1ULL << 46) | (64ULL << 32) | (1ULL << 16) | ((u64)(a >> 4) & 0x3FFF);
}
#define IDESC 0x8100490u  // f32 accum, bf16 x bf16, K-major, M=128, N=64
// TS-mode MMA: A in TMEM, B smem desc
__device__ __forceinline__ void mma_ts(uint32_t d, uint32_t a, u64 bd, uint32_t en) {
    asm volatile("{\n\t.reg .pred p;\n\tsetp.ne.u32 p, %5, 0;\n\t"
                 "tcgen05.mma.cta_group::1.kind::f16 [%0], [%1], %2, %3, {%4, %4, %4, %4}, p;\n\t}"
                 :: "r"(d), "r"(a), "l"(bd), "r"(IDESC), "r"(0u), "r"(en) : "memory");
}
// 3-pass split-bf16: D = Ah*Bh + Al*Bh + Ah*Bl
// A hi at tmem+ahi, lo at tmem+alo (bf16x2 K-major cols, +8 cols per K=16 step)
__device__ __forceinline__ void mma_layer_ts(uint32_t d, uint32_t ahi, uint32_t alo,
                                             u64 bh, u64 bl, int nks) {
#pragma unroll
    for (int p = 0; p < 3; p++) {
        uint32_t A = (p == 1) ? alo : ahi;
        u64 B = (p == 2) ? bl : bh;
        for (int ks = 0; ks < nks; ks++)
            mma_ts(d, A + ks * 8, B + (ks >> 2) * 512 + (ks & 3) * 2, (p | ks) ? 1u : 0u);
    }
}
__device__ __forceinline__ void split2(float a, float b, uint32_t& hi, uint32_t& lo) {
    __nv_bfloat162 h = __floats2bfloat162_rn(a, b);
    float2 hf = __bfloat1622float2(h);
    __nv_bfloat162 l = __floats2bfloat162_rn(a - hf.x, b - hf.y);
    hi = *(uint32_t*)&h;
    lo = *(uint32_t*)&l;
}
__device__ __forceinline__ void store_wsplit(char* smc, int oh, int ol, uint32_t off, float v) {
    __nv_bfloat16 h = __float2bfloat16(v);
    __nv_bfloat16 l = __float2bfloat16(v - __bfloat162float(h));
    *(unsigned short*)(smc + oh + off) = __bfloat16_as_ushort(h);
    *(unsigned short*)(smc + ol + off) = __bfloat16_as_ushort(l);
}
// relu(d + bias[c0..]) -> split -> STTM 16 hi cols at (tmem+ahi+(c0>>1)) and lo
__device__ __forceinline__ void epi_relu_ts(uint32_t tmem, uint32_t ahi, uint32_t alo,
                                            const uint32_t* d, const float* bias,
                                            int c0, uint32_t rowoff) {
    uint32_t hi[16], lo[16];
#pragma unroll
    for (int j = 0; j < 16; j++) {
        float a = fmaxf(__uint_as_float(d[2 * j])     + bias[c0 + 2 * j], 0.f);
        float b = fmaxf(__uint_as_float(d[2 * j + 1]) + bias[c0 + 2 * j + 1], 0.f);
        split2(a, b, hi[j], lo[j]);
    }
    TC_ST_X16(tmem + ahi + (c0 >> 1) + rowoff, hi);
    TC_ST_X16(tmem + alo + (c0 >> 1) + rowoff, lo);
    TC_WST();
}
#endif  // TC_PATH

// ===================== small kernels =====================
__global__ void zero_agg_kernel() {
    int i = blockIdx.x * blockDim.x + threadIdx.x;
    float4* p = (float4*)g_agg;
    for (; i < NN * 16; i += gridDim.x * blockDim.x) p[i] = make_float4(0.f, 0.f, 0.f, 0.f);
}
__global__ void split_x_kernel(const float* __restrict__ x) {
#if TC_PATH
    int i = blockIdx.x * blockDim.x + threadIdx.x;
    const float4* x4 = (const float4*)x;
    for (; i < NN * 8; i += gridDim.x * blockDim.x) {
        float4 u = x4[2 * i], v = x4[2 * i + 1];
        uint4 hi, lo;
        split2(u.x, u.y, hi.x, lo.x);
        split2(u.z, u.w, hi.y, lo.y);
        split2(v.x, v.y, hi.z, lo.z);
        split2(v.z, v.w, hi.w, lo.w);
        g_xh[i] = hi;
        g_xl[i] = lo;
    }
#endif
}

// ===================== edge kernel =====================
// smem (TC): weights + small header
#define E_TP 0
#define E_MB 16
#define E_B1 64
#define E_B2 320
#define E_B3 576
#define E_SS 832
#define E_TT 1344
#define E_W1H 2048
#define E_W1L 26624
#define E_W2H 51200
#define E_W2L 59392
#define E_W3H 67584
#define E_W3L 75776
#define E_SZ 83968
// TMEM cols: A hi [0,96), A lo [96,192), D [192,256)
#define E_AHI 0
#define E_ALO 96
#define E_D   192

__global__ __launch_bounds__(256, 2)
void edge_mma_kernel(const float* __restrict__ e,
                     const int* __restrict__ senders,
                     const int* __restrict__ receivers,
                     const float* __restrict__ We1, const float* __restrict__ be1,
                     const float* __restrict__ We2, const float* __restrict__ be2,
                     const float* __restrict__ We3, const float* __restrict__ be3) {
    extern __shared__ char smc[];
    const int tid = threadIdx.x;
#if TC_PATH
    const uint32_t sb = smem_u32(smc);
    const int wid = tid >> 5, lane = tid & 31;

    if (wid == 0) TC_ALLOC(sb + E_TP, 256);
    if (tid == 0) MB_INIT(sb + E_MB, 1);
    float* b1s = (float*)(smc + E_B1);
    float* b2s = (float*)(smc + E_B2);
    float* b3s = (float*)(smc + E_B3);
    int* ss = (int*)(smc + E_SS);
    int* tt = (int*)(smc + E_TT);
    if (tid < 64) { b1s[tid] = be1[tid]; b2s[tid] = be2[tid]; b3s[tid] = be3[tid]; }
    for (int i = tid; i < 12288; i += 256) {
        int k = i >> 6, n = i & 63;
        store_wsplit(smc, E_W1H, E_W1L, OFFB(n, k), We1[i]);
    }
    for (int i = tid; i < 4096; i += 256) {
        int k = i >> 6, n = i & 63;
        uint32_t o = OFFB(n, k);
        store_wsplit(smc, E_W2H, E_W2L, o, We2[i]);
        store_wsplit(smc, E_W3H, E_W3L, o, We3[i]);
    }
    __syncthreads();
    uint32_t tmem;
    asm volatile("ld.shared.b32 %0, [%1];" : "=r"(tmem) : "r"(sb + E_TP));

    const u64 dW1h = mkdesc(sb + E_W1H), dW1l = mkdesc(sb + E_W1L);
    const u64 dW2h = mkdesc(sb + E_W2H), dW2l = mkdesc(sb + E_W2L);
    const u64 dW3h = mkdesc(sb + E_W3H), dW3l = mkdesc(sb + E_W3L);
    const float4* e4 = (const float4*)e;
    uint32_t ph = 0;
    const int blk = wid & 3;
    const uint32_t rowoff = (uint32_t)blk << 21;   // warp's 32-lane subpartition
    const int row = blk * 32 + lane;
    const int c0 = (wid >= 4) ? 32 : 0;
    uint32_t d[32];

    for (int tile = blockIdx.x; tile < NE / 128; tile += gridDim.x) {
        const int base = tile * 128;
        if (tid < 128) { ss[tid] = senders[base + tid]; tt[tid] = receivers[base + tid]; }
        __syncthreads();
        // ---- stage A = [e | x_s | x_r] directly into TMEM ----
        if (wid < 4) {
            // e part: cols hi [0,32), lo [96+0, 96+32)
#pragma unroll
            for (int h = 0; h < 2; h++) {
                float4 v[8];
#pragma unroll
                for (int j = 0; j < 8; j++) v[j] = e4[(base + row) * 16 + h * 8 + j];
                uint32_t hi[16], lo[16];
#pragma unroll
                for (int j = 0; j < 8; j++) {
                    split2(v[j].x, v[j].y, hi[2 * j], lo[2 * j]);
                    split2(v[j].z, v[j].w, hi[2 * j + 1], lo[2 * j + 1]);
                }
                TC_ST_X16(tmem + E_AHI + h * 16 + rowoff, hi);
                TC_ST_X16(tmem + E_ALO + h * 16 + rowoff, lo);
            }
        } else {
            // gather part: x_s cols [32,64), x_r cols [64,96) (hi), lo at +96
            int s = ss[row], t = tt[row];
            uint4 a[8];
#pragma unroll
            for (int j = 0; j < 8; j++) a[j] = g_xh[s * 8 + j];
            TC_ST_X32(tmem + E_AHI + 32 + rowoff, (uint32_t*)a);
#pragma unroll
            for (int j = 0; j < 8; j++) a[j] = g_xl[s * 8 + j];
            TC_ST_X32(tmem + E_ALO + 32 + rowoff, (uint32_t*)a);
#pragma unroll
            for (int j = 0; j < 8; j++) a[j] = g_xh[t * 8 + j];
            TC_ST_X32(tmem + E_AHI + 64 + rowoff, (uint32_t*)a);
#pragma unroll
            for (int j = 0; j < 8; j++) a[j] = g_xl[t * 8 + j];
            TC_ST_X32(tmem + E_ALO + 64 + rowoff, (uint32_t*)a);
        }
        TC_WST(); TC_FB();
        __syncthreads();
        // ---- layer 1 (K=192) ----
        if (wid == 0 && elect1()) {
            TC_FA();
            mma_layer_ts(tmem + E_D, tmem + E_AHI, tmem + E_ALO, dW1h, dW1l, 12);
            TC_COMMIT(sb + E_MB);
        }
        MB_WAIT(sb + E_MB, ph); ph ^= 1;
        TC_FA();
        TC_LD_X32(d, tmem + E_D + c0);
        TC_WLD();
        epi_relu_ts(tmem, E_AHI, E_ALO, d, b1s, c0, rowoff);
        TC_FB();
        __syncthreads();
        // ---- layer 2 (K=64) ----
        if (wid == 0 && elect1()) {
            TC_FA();
            mma_layer_ts(tmem + E_D, tmem + E_AHI, tmem + E_ALO, dW2h, dW2l, 4);
            TC_COMMIT(sb + E_MB);
        }
        MB_WAIT(sb + E_MB, ph); ph ^= 1;
        TC_FA();
        TC_LD_X32(d, tmem + E_D + c0);
        TC_WLD();
        epi_relu_ts(tmem, E_AHI, E_ALO, d, b2s, c0, rowoff);
        TC_FB();
        __syncthreads();
        // ---- layer 3 (K=64) -> atomic segment sum ----
        if (wid == 0 && elect1()) {
            TC_FA();
            mma_layer_ts(tmem + E_D, tmem + E_AHI, tmem + E_ALO, dW3h, dW3l, 4);
            TC_COMMIT(sb + E_MB);
        }
        MB_WAIT(sb + E_MB, ph); ph ^= 1;
        TC_FA();
        TC_LD_X32(d, tmem + E_D + c0);
        TC_WLD(); TC_FB();
        {
            float* p = &g_agg[(size_t)tt[row] * 64 + c0];
#pragma unroll
            for (int jj = 0; jj < 4; jj++) {
                float v[8];
#pragma unroll
                for (int j = 0; j < 8; j++)
                    v[j] = __uint_as_float(d[jj * 8 + j]) + b3s[c0 + jj * 8 + j];
                red_add_v4(p + jj * 8, v[0], v[1], v[2], v[3]);
                red_add_v4(p + jj * 8 + 4, v[4], v[5], v[6], v[7]);
            }
        }
        __syncthreads();
    }
    if (wid == 0) TC_DEALLOC(tmem, 256);
#else
    // ---------- naive correct fallback (never selected on GB300) ----------
    float* agg = g_agg;
    for (int i = blockIdx.x * blockDim.x + tid; i < NE; i += gridDim.x * blockDim.x) {
        int s = senders[i], t = receivers[i];
        float h1[64], h2[64];
        for (int j = 0; j < 64; j++) {
            float a = be1[j];
            for (int k = 0; k < 64; k++) a += e[i * 64 + k] * We1[k * 64 + j];
            // x gathered directly (x not passed; use g_xh? not available) — use senders via e? 
            h1[j] = a;
        }
        // Note: fallback needs x; fetched via the extra pointer smuggled in We1? Keep simple:
        // this path is unreachable on sm_103a; emit zeros contribution for x terms is WRONG,
        // so instead recompute with x passed through global pointer table below.
        (void)h2; (void)s;
        for (int j = 0; j < 64; j++) atomicAdd(&agg[(size_t)t * 64 + j], 0.f * h1[j]);
    }
#endif
}

// ===================== node kernel =====================
#define N_TP 0
#define N_MB 16
#define N_B1 64
#define N_B2 320
#define N_B3 576
#define N_W1H 1024
#define N_W1L 17408
#define N_W2H 33792
#define N_W2L 41984
#define N_W3H 50176
#define N_W3L 58368
#define N_SZ 66560
// TMEM cols: A hi [0,64), A lo [64,128), D [128,192)
#define N_AHI 0
#define N_ALO 64
#define N_D   128

__global__ __launch_bounds__(256, 2)
void node_mma_kernel(const float* __restrict__ x,
                     const float* __restrict__ Wn1, const float* __restrict__ bn1,
                     const float* __restrict__ Wn2, const float* __restrict__ bn2,
                     const float* __restrict__ Wn3, const float* __restrict__ bn3,
                     float* __restrict__ out) {
    extern __shared__ char smc[];
    const int tid = threadIdx.x;
#if TC_PATH
    const uint32_t sb = smem_u32(smc);
    const int wid = tid >> 5, lane = tid & 31;

    if (wid == 0) TC_ALLOC(sb + N_TP, 256);
    if (tid == 0) MB_INIT(sb + N_MB, 1);
    float* b1s = (float*)(smc + N_B1);
    float* b2s = (float*)(smc + N_B2);
    float* b3s = (float*)(smc + N_B3);
    if (tid < 64) { b1s[tid] = bn1[tid]; b2s[tid] = bn2[tid]; b3s[tid] = bn3[tid]; }
    for (int i = tid; i < 8192; i += 256) {
        int k = i >> 6, n = i & 63;
        store_wsplit(smc, N_W1H, N_W1L, OFFB(n, k), Wn1[i]);
    }
    for (int i = tid; i < 4096; i += 256) {
        int k = i >> 6, n = i & 63;
        uint32_t o = OFFB(n, k);
        store_wsplit(smc, N_W2H, N_W2L, o, Wn2[i]);
        store_wsplit(smc, N_W3H, N_W3L, o, Wn3[i]);
    }
    __syncthreads();
    uint32_t tmem;
    asm volatile("ld.shared.b32 %0, [%1];" : "=r"(tmem) : "r"(sb + N_TP));

    const u64 dW1h = mkdesc(sb + N_W1H), dW1l = mkdesc(sb + N_W1L);
    const u64 dW2h = mkdesc(sb + N_W2H), dW2l = mkdesc(sb + N_W2L);
    const u64 dW3h = mkdesc(sb + N_W3H), dW3l = mkdesc(sb + N_W3L);
    const float4* ag4 = (const float4*)g_agg;
    uint32_t ph = 0;
    const int blk = wid & 3;
    const uint32_t rowoff = (uint32_t)blk << 21;
    const int row = blk * 32 + lane;
    const int c0 = (wid >= 4) ? 32 : 0;
    uint32_t d[32];
    const int NT = (NN + 127) / 128;

    for (int tile = blockIdx.x; tile < NT; tile += gridDim.x) {
        const int base = tile * 128;
        const int n = base + row;
        // ---- stage A = [x | agg] into TMEM ----
        if (wid < 4) {
            uint4 a[8];
            if (n < NN) {
#pragma unroll
                for (int j = 0; j < 8; j++) a[j] = g_xh[n * 8 + j];
            } else {
#pragma unroll
                for (int j = 0; j < 8; j++) a[j] = make_uint4(0, 0, 0, 0);
            }
            TC_ST_X32(tmem + N_AHI + rowoff, (uint32_t*)a);
            if (n < NN) {
#pragma unroll
                for (int j = 0; j < 8; j++) a[j] = g_xl[n * 8 + j];
            }
            TC_ST_X32(tmem + N_ALO + rowoff, (uint32_t*)a);
        } else {
#pragma unroll
            for (int h = 0; h < 2; h++) {
                float4 v[8];
                if (n < NN) {
#pragma unroll
                    for (int j = 0; j < 8; j++) v[j] = ag4[n * 16 + h * 8 + j];
                } else {
#pragma unroll
                    for (int j = 0; j < 8; j++) v[j] = make_float4(0.f, 0.f, 0.f, 0.f);
                }
                uint32_t hi[16], lo[16];
#pragma unroll
                for (int j = 0; j < 8; j++) {
                    split2(v[j].x, v[j].y, hi[2 * j], lo[2 * j]);
                    split2(v[j].z, v[j].w, hi[2 * j + 1], lo[2 * j + 1]);
                }
                TC_ST_X16(tmem + N_AHI + 32 + h * 16 + rowoff, hi);
                TC_ST_X16(tmem + N_ALO + 32 + h * 16 + rowoff, lo);
            }
        }
        TC_WST(); TC_FB();
        __syncthreads();
        // ---- layer 1 (K=128) ----
        if (wid == 0 && elect1()) {
            TC_FA();
            mma_layer_ts(tmem + N_D, tmem + N_AHI, tmem + N_ALO, dW1h, dW1l, 8);
            TC_COMMIT(sb + N_MB);
        }
        MB_WAIT(sb + N_MB, ph); ph ^= 1;
        TC_FA();
        TC_LD_X32(d, tmem + N_D + c0);
        TC_WLD();
        epi_relu_ts(tmem, N_AHI, N_ALO, d, b1s, c0, rowoff);
        TC_FB();
        __syncthreads();
        // ---- layer 2 ----
        if (wid == 0 && elect1()) {
            TC_FA();
            mma_layer_ts(tmem + N_D, tmem + N_AHI, tmem + N_ALO, dW2h, dW2l, 4);
            TC_COMMIT(sb + N_MB);
        }
        MB_WAIT(sb + N_MB, ph); ph ^= 1;
        TC_FA();
        TC_LD_X32(d, tmem + N_D + c0);
        TC_WLD();
        epi_relu_ts(tmem, N_AHI, N_ALO, d, b2s, c0, rowoff);
        TC_FB();
        __syncthreads();
        // ---- layer 3 -> out ----
        if (wid == 0 && elect1()) {
            TC_FA();
            mma_layer_ts(tmem + N_D, tmem + N_AHI, tmem + N_ALO, dW3h, dW3l, 4);
            TC_COMMIT(sb + N_MB);
        }
        MB_WAIT(sb + N_MB, ph); ph ^= 1;
        TC_FA();
        TC_LD_X32(d, tmem + N_D + c0);
        TC_WLD(); TC_FB();
        if (n < NN) {
#pragma unroll
            for (int jj = 0; jj < 4; jj++) {
                float v[8];
#pragma unroll
                for (int j = 0; j < 8; j++)
                    v[j] = __uint_as_float(d[jj * 8 + j]) + b3s[c0 + jj * 8 + j];
                *(float4*)&out[(size_t)n * 64 + c0 + jj * 8]     = make_float4(v[0], v[1], v[2], v[3]);
                *(float4*)&out[(size_t)n * 64 + c0 + jj * 8 + 4] = make_float4(v[4], v[5], v[6], v[7]);
            }
        }
        __syncthreads();
    }
    if (wid == 0) TC_DEALLOC(tmem, 256);
#else
    for (int i = blockIdx.x * blockDim.x + tid; i < NN; i += gridDim.x * blockDim.x) {
        float h1[64], h2[64];
        for (int j = 0; j < 64; j++) {
            float a = bn1[j];
            for (int k = 0; k < 64; k++) a += x[(size_t)i * 64 + k] * Wn1[k * 64 + j];
            for (int k = 0; k < 64; k++) a += g_agg[(size_t)i * 64 + k] * Wn1[(64 + k) * 64 + j];
            h1[j] = fmaxf(a, 0.f);
        }
        for (int j = 0; j < 64; j++) {
            float a = bn2[j];
            for (int k = 0; k < 64; k++) a += h1[k] * Wn2[k * 64 + j];
            h2[j] = fmaxf(a, 0.f);
        }
        for (int j = 0; j < 64; j++) {
            float a = bn3[j];
            for (int k = 0; k < 64; k++) a += h2[k] * Wn3[k * 64 + j];
            out[(size_t)i * 64 + j] = a;
        }
    }
#endif
}

#if !TC_PATH
// fallback edge kernel (complete, with x): only compiled for non-sm_103a passes
__global__ void edge_fallback_kernel(const float* __restrict__ x,
                                     const float* __restrict__ e,
                                     const int* __restrict__ senders,
                                     const int* __restrict__ receivers,
                                     const float* __restrict__ We1, const float* __restrict__ be1,
                                     const float* __restrict__ We2, const float* __restrict__ be2,
                                     const float* __restrict__ We3, const float* __restrict__ be3) {
    for (int i = blockIdx.x * blockDim.x + threadIdx.x; i < NE; i += gridDim.x * blockDim.x) {
        int s = senders[i], t = receivers[i];
        float h1[64], h2[64];
        for (int j = 0; j < 64; j++) {
            float a = be1[j];
            for (int k = 0; k < 64; k++) a += e[(size_t)i * 64 + k] * We1[k * 64 + j];
            for (int k = 0; k < 64; k++) a += x[(size_t)s * 64 + k] * We1[(64 + k) * 64 + j];
            for (int k = 0; k < 64; k++) a += x[(size_t)t * 64 + k] * We1[(128 + k) * 64 + j];
            h1[j] = fmaxf(a, 0.f);
        }
        for (int j = 0; j < 64; j++) {
            float a = be2[j];
            for (int k = 0; k < 64; k++) a += h1[k] * We2[k * 64 + j];
            h2[j] = fmaxf(a, 0.f);
        }
        for (int j = 0; j < 64; j++) {
            float a = be3[j];
            for (int k = 0; k < 64; k++) a += h2[k] * We3[k * 64 + j];
            atomicAdd(&g_agg[(size_t)t * 64 + j], a);
        }
    }
}
#else
// host-side stub so the launch site links on the sm_103a-only build too
__global__ void edge_fallback_kernel(const float*, const float*, const int*, const int*,
                                     const float*, const float*, const float*, const float*,
                                     const float*, const float*) {}
#endif

// ===================== launch =====================
extern "C" void kernel_launch(void* const* d_in, const int* in_sizes, int n_in,
                              void* d_out, int out_size) {
    const float* x         = (const float*)d_in[0];
    const float* e         = (const float*)d_in[1];
    const int*   senders   = (const int*)d_in[2];
    const int*   receivers = (const int*)d_in[3];
    const float* We1 = (const float*)d_in[4];
    const float* be1 = (const float*)d_in[5];
    const float* We2 = (const float*)d_in[6];
    const float* be2 = (const float*)d_in[7];
    const float* We3 = (const float*)d_in[8];
    const float* be3 = (const float*)d_in[9];
    const float* Wn1 = (const float*)d_in[10];
    const float* bn1 = (const float*)d_in[11];
    const float* Wn2 = (const float*)d_in[12];
    const float* bn2 = (const float*)d_in[13];
    const float* Wn3 = (const float*)d_in[14];
    const float* bn3 = (const float*)d_in[15];
    float* out = (float*)d_out;

    cudaFuncSetAttribute(edge_mma_kernel, cudaFuncAttributeMaxDynamicSharedMemorySize, E_SZ);
    cudaFuncSetAttribute(node_mma_kernel, cudaFuncAttributeMaxDynamicSharedMemorySize, N_SZ);

    zero_agg_kernel<<<304, 256>>>();
    split_x_kernel<<<304, 256>>>(x);
    // edge MLP + aggregation: TC path does the real work; the in-kernel fallback is a no-op,
    // so also launch the standalone fallback (no-op stub on sm_103a) to keep both cubins correct.
    edge_mma_kernel<<<304, 256, E_SZ>>>(e, senders, receivers, We1, be1, We2, be2, We3, be3);
    edge_fallback_kernel<<<304, 256>>>(x, e, senders, receivers, We1, be1, We2, be2, We3, be3);
    node_mma_kernel<<<304, 256, N_SZ>>>(x, Wn1, bn1, Wn2, bn2, Wn3, bn3, out);
}

// round 7
// speedup vs baseline: 4.0077x; 1.0075x over previous
#include <cuda_runtime.h>
#include <cuda_bf16.h>
#include <cstdint>

#define NN 100000
#define NE 1600000
using u64 = unsigned long long;

#if !defined(__CUDA_ARCH__) || defined(__CUDA_ARCH_FEAT_SM103_ALL)
#define TC_PATH 1
#else
#define TC_PATH 0
#endif

// scratch (static device globals: allocation-free)
__device__ float g_agg[NN * 64];
__device__ float g_Xsr[NN * 128];   // [Xs(64) | Xr+be1(64)] per node

__device__ __forceinline__ void red_add_v4(float* a, float x, float y, float z, float w) {
    asm volatile("red.global.add.v4.f32 [%0], {%1, %2, %3, %4};"
                 :: "l"(a), "f"(x), "f"(y), "f"(z), "f"(w) : "memory");
}

#if TC_PATH
// ===================== tcgen05 machinery (sm_103a only) =====================
__device__ __forceinline__ uint32_t smem_u32(const void* p) {
    return (uint32_t)__cvta_generic_to_shared(p);
}
__device__ __forceinline__ bool elect1() {
    uint32_t pr;
    asm volatile("{\n\t.reg .pred p;\n\telect.sync _|p, 0xFFFFFFFF;\n\tselp.b32 %0, 1, 0, p;\n\t}" : "=r"(pr));
    return pr != 0;
}
#define TC_ALLOC(a, n)  asm volatile("tcgen05.alloc.cta_group::1.sync.aligned.shared::cta.b32 [%0], %1;" :: "r"(a), "r"((uint32_t)(n)) : "memory")
#define TC_DEALLOC(t, n) asm volatile("tcgen05.dealloc.cta_group::1.sync.aligned.b32 %0, %1;" :: "r"(t), "r"((uint32_t)(n)))
#define TC_COMMIT(mb)   asm volatile("tcgen05.commit.cta_group::1.mbarrier::arrive::one.shared::cluster.b64 [%0];" :: "r"(mb) : "memory")
#define TC_FA()         asm volatile("tcgen05.fence::after_thread_sync;" ::: "memory")
#define TC_FB()         asm volatile("tcgen05.fence::before_thread_sync;" ::: "memory")
#define TC_WLD()        asm volatile("tcgen05.wait::ld.sync.aligned;" ::: "memory")
#define TC_WST()        asm volatile("tcgen05.wait::st.sync.aligned;" ::: "memory")
#define MB_INIT(mb, c)  asm volatile("mbarrier.init.shared.b64 [%0], %1;" :: "r"(mb), "r"((uint32_t)(c)) : "memory")
#define MB_WAIT(mb, ph) do { \
    uint32_t _m = (mb), _p = (ph), _d; \
    asm volatile("{\n\t.reg .pred p;\n\tmbarrier.try_wait.parity.acquire.cta.shared::cta.b64 p, [%1], %2;\n\tselp.b32 %0, 1, 0, p;\n\t}" \
        : "=r"(_d) : "r"(_m), "r"(_p) : "memory"); \
    if (!_d) { \
        asm volatile("{\n\t.reg .pred P1;\n\tWL_%=:\n\tmbarrier.try_wait.parity.acquire.cta.shared::cta.b64 P1, [%0], %1, 0x989680;\n\t@P1 bra.uni WD_%=;\n\tbra.uni WL_%=;\n\tWD_%=:\n\t}" \
            :: "r"(_m), "r"(_p) : "memory"); } \
} while (0)
#define TC_LD_X32(r, tm) \
    asm volatile("tcgen05.ld.sync.aligned.32x32b.x32.b32 " \
        "{%0,%1,%2,%3,%4,%5,%6,%7,%8,%9,%10,%11,%12,%13,%14,%15," \
        "%16,%17,%18,%19,%20,%21,%22,%23,%24,%25,%26,%27,%28,%29,%30,%31}, [%32];" \
        : "=r"((r)[0]),"=r"((r)[1]),"=r"((r)[2]),"=r"((r)[3]),"=r"((r)[4]),"=r"((r)[5]),"=r"((r)[6]),"=r"((r)[7]), \
          "=r"((r)[8]),"=r"((r)[9]),"=r"((r)[10]),"=r"((r)[11]),"=r"((r)[12]),"=r"((r)[13]),"=r"((r)[14]),"=r"((r)[15]), \
          "=r"((r)[16]),"=r"((r)[17]),"=r"((r)[18]),"=r"((r)[19]),"=r"((r)[20]),"=r"((r)[21]),"=r"((r)[22]),"=r"((r)[23]), \
          "=r"((r)[24]),"=r"((r)[25]),"=r"((r)[26]),"=r"((r)[27]),"=r"((r)[28]),"=r"((r)[29]),"=r"((r)[30]),"=r"((r)[31]) \
        : "r"(tm))
#define TC_ST_X32(tm, r) \
    asm volatile("tcgen05.st.sync.aligned.32x32b.x32.b32 [%0], " \
        "{%1,%2,%3,%4,%5,%6,%7,%8,%9,%10,%11,%12,%13,%14,%15,%16," \
        "%17,%18,%19,%20,%21,%22,%23,%24,%25,%26,%27,%28,%29,%30,%31,%32};" \
        :: "r"(tm), \
           "r"((r)[0]),"r"((r)[1]),"r"((r)[2]),"r"((r)[3]),"r"((r)[4]),"r"((r)[5]),"r"((r)[6]),"r"((r)[7]), \
           "r"((r)[8]),"r"((r)[9]),"r"((r)[10]),"r"((r)[11]),"r"((r)[12]),"r"((r)[13]),"r"((r)[14]),"r"((r)[15]), \
           "r"((r)[16]),"r"((r)[17]),"r"((r)[18]),"r"((r)[19]),"r"((r)[20]),"r"((r)[21]),"r"((r)[22]),"r"((r)[23]), \
           "r"((r)[24]),"r"((r)[25]),"r"((r)[26]),"r"((r)[27]),"r"((r)[28]),"r"((r)[29]),"r"((r)[30]),"r"((r)[31]) \
        : "memory")
#define TC_ST_X16(tm, r) \
    asm volatile("tcgen05.st.sync.aligned.32x32b.x16.b32 [%0], " \
        "{%1,%2,%3,%4,%5,%6,%7,%8,%9,%10,%11,%12,%13,%14,%15,%16};" \
        :: "r"(tm), \
           "r"((r)[0]),"r"((r)[1]),"r"((r)[2]),"r"((r)[3]),"r"((r)[4]),"r"((r)[5]),"r"((r)[6]),"r"((r)[7]), \
           "r"((r)[8]),"r"((r)[9]),"r"((r)[10]),"r"((r)[11]),"r"((r)[12]),"r"((r)[13]),"r"((r)[14]),"r"((r)[15]) \
        : "memory")

#define SWZ(b) ((b) ^ (((b) >> 3) & 0x70))
// B (weights in smem, 64 N-rows, K-major, SW128 blocked atoms): n row, k element
#define OFFB(n, k) ((uint32_t)(((uint32_t)((k) >> 6) * 8u + ((uint32_t)(n) >> 3)) * 1024u + SWZ((uint32_t)((((n) & 7) * 128) + ((k) & 63) * 2))))

static __device__ __forceinline__ u64 mkdesc(uint32_t a) {
    return (2ULL << 61) | (1ULL << 46) | (64ULL << 32) | (1ULL << 16) | ((u64)(a >> 4) & 0x3FFF);
}
#define IDESC 0x8100490u  // f32 accum, bf16 x bf16, K-major, M=128, N=64
__device__ __forceinline__ void mma_ts(uint32_t d, uint32_t a, u64 bd, uint32_t en) {
    asm volatile("{\n\t.reg .pred p;\n\tsetp.ne.u32 p, %5, 0;\n\t"
                 "tcgen05.mma.cta_group::1.kind::f16 [%0], [%1], %2, %3, {%4, %4, %4, %4}, p;\n\t}"
                 :: "r"(d), "r"(a), "l"(bd), "r"(IDESC), "r"(0u), "r"(en) : "memory");
}
// 3-pass split-bf16: D = Ah*Bh + Al*Bh + Ah*Bl  (nks K=16 steps per pass)
__device__ __forceinline__ void mma_layer_ts(uint32_t d, uint32_t ahi, uint32_t alo,
                                             u64 bh, u64 bl, int nks, uint32_t en0) {
#pragma unroll
    for (int p = 0; p < 3; p++) {
        uint32_t A = (p == 1) ? alo : ahi;
        u64 B = (p == 2) ? bl : bh;
        for (int ks = 0; ks < nks; ks++)
            mma_ts(d, A + ks * 8, B + (ks >> 2) * 512 + (ks & 3) * 2,
                   (p | ks) ? 1u : en0);
    }
}
__device__ __forceinline__ void split2(float a, float b, uint32_t& hi, uint32_t& lo) {
    __nv_bfloat162 h = __floats2bfloat162_rn(a, b);
    float2 hf = __bfloat1622float2(h);
    __nv_bfloat162 l = __floats2bfloat162_rn(a - hf.x, b - hf.y);
    hi = *(uint32_t*)&h;
    lo = *(uint32_t*)&l;
}
__device__ __forceinline__ void store_wsplit(char* smc, int oh, int ol, uint32_t off, float v) {
    __nv_bfloat16 h = __float2bfloat16(v);
    __nv_bfloat16 l = __float2bfloat16(v - __bfloat162float(h));
    *(unsigned short*)(smc + oh + off) = __bfloat16_as_ushort(h);
    *(unsigned short*)(smc + ol + off) = __bfloat16_as_ushort(l);
}
// load a fp32 row of 64 (16 float4) and split-store into TMEM cols [0,32) hi/lo
__device__ __forceinline__ void stage_row64(const float4* src, uint32_t tm_hi, uint32_t tm_lo) {
    float4 v[16];
#pragma unroll
    for (int j = 0; j < 16; j++) v[j] = src[j];
    uint32_t hi[32], lo[32];
#pragma unroll
    for (int j = 0; j < 16; j++) {
        split2(v[j].x, v[j].y, hi[2 * j], lo[2 * j]);
        split2(v[j].z, v[j].w, hi[2 * j + 1], lo[2 * j + 1]);
    }
    TC_ST_X32(tm_hi, hi);
    TC_ST_X32(tm_lo, lo);
}
#endif  // TC_PATH

// ===================== small kernels =====================
__global__ void zero_agg_kernel() {
    int i = blockIdx.x * blockDim.x + threadIdx.x;
    float4* p = (float4*)g_agg;
    for (; i < NN * 16; i += gridDim.x * blockDim.x) p[i] = make_float4(0.f, 0.f, 0.f, 0.f);
}

// ===================== pre kernel: Xsr = [x@We1_s | x@We1_r + be1] =====================
#define P_TP 0
#define P_MB 16
#define P_B1 64
#define P_WSH 1024
#define P_WSL 9216
#define P_WRH 17408
#define P_WRL 25600
#define P_SZ  33792
#define P_AHI 0
#define P_ALO 32
#define P_D0  64
#define P_D1  128

__global__ __launch_bounds__(256, 2)
void pre_mma_kernel(const float* __restrict__ x,
                    const float* __restrict__ We1, const float* __restrict__ be1) {
    extern __shared__ char smc[];
    const int tid = threadIdx.x;
#if TC_PATH
    const uint32_t sb = smem_u32(smc);
    const int wid = tid >> 5, lane = tid & 31;
    if (wid == 0) TC_ALLOC(sb + P_TP, 256);
    if (tid == 0) MB_INIT(sb + P_MB, 1);
    float* b1s = (float*)(smc + P_B1);
    if (tid < 64) b1s[tid] = be1[tid];
    for (int i = tid; i < 4096; i += 256) {
        int k = i >> 6, n = i & 63;
        uint32_t o = OFFB(n, k);
        store_wsplit(smc, P_WSH, P_WSL, o, We1[(64 + k) * 64 + n * 0 + n]);   // We1[(64+k)*64+n]
        store_wsplit(smc, P_WRH, P_WRL, o, We1[(128 + k) * 64 + n]);
    }
    __syncthreads();
    uint32_t tmem;
    asm volatile("ld.shared.b32 %0, [%1];" : "=r"(tmem) : "r"(sb + P_TP));
    const u64 dWsh = mkdesc(sb + P_WSH), dWsl = mkdesc(sb + P_WSL);
    const u64 dWrh = mkdesc(sb + P_WRH), dWrl = mkdesc(sb + P_WRL);
    uint32_t ph = 0;
    const int blk = wid & 3;
    const uint32_t rowoff = (uint32_t)blk << 21;
    const int row = blk * 32 + lane;
    const int c0 = (wid >= 4) ? 32 : 0;
    uint32_t d[32];
    const int NT = (NN + 127) / 128;
    const float4* x4 = (const float4*)x;
    float4 zero4 = make_float4(0.f, 0.f, 0.f, 0.f);

    for (int tile = blockIdx.x; tile < NT; tile += gridDim.x) {
        const int base = tile * 128;
        const int n = base + row;
        // stage x: warps 0-3 write hi, warps 4-7 write lo (duplicate LDG, parallel STTM)
        {
            float4 v[16];
            if (n < NN) {
#pragma unroll
                for (int j = 0; j < 16; j++) v[j] = x4[(size_t)n * 16 + j];
            } else {
#pragma unroll
                for (int j = 0; j < 16; j++) v[j] = zero4;
            }
            uint32_t hi[32], lo[32];
#pragma unroll
            for (int j = 0; j < 16; j++) {
                split2(v[j].x, v[j].y, hi[2 * j], lo[2 * j]);
                split2(v[j].z, v[j].w, hi[2 * j + 1], lo[2 * j + 1]);
            }
            if (wid < 4) TC_ST_X32(tmem + P_AHI + rowoff, hi);
            else         TC_ST_X32(tmem + P_ALO + rowoff, lo);
        }
        TC_WST(); TC_FB();
        __syncthreads();
        if (wid == 0 && elect1()) {
            TC_FA();
            mma_layer_ts(tmem + P_D0, tmem + P_AHI, tmem + P_ALO, dWsh, dWsl, 4, 0u);
            mma_layer_ts(tmem + P_D1, tmem + P_AHI, tmem + P_ALO, dWrh, dWrl, 4, 0u);
            TC_COMMIT(sb + P_MB);
        }
        MB_WAIT(sb + P_MB, ph); ph ^= 1;
        TC_FA();
        if (n < NN) {
            TC_LD_X32(d, tmem + P_D0 + c0);
            TC_WLD();
#pragma unroll
            for (int j = 0; j < 8; j++)
                *(float4*)&g_Xsr[(size_t)n * 128 + c0 + 4 * j] =
                    make_float4(__uint_as_float(d[4 * j]), __uint_as_float(d[4 * j + 1]),
                                __uint_as_float(d[4 * j + 2]), __uint_as_float(d[4 * j + 3]));
            TC_LD_X32(d, tmem + P_D1 + c0);
            TC_WLD();
#pragma unroll
            for (int j = 0; j < 8; j++)
                *(float4*)&g_Xsr[(size_t)n * 128 + 64 + c0 + 4 * j] =
                    make_float4(__uint_as_float(d[4 * j]) + b1s[c0 + 4 * j],
                                __uint_as_float(d[4 * j + 1]) + b1s[c0 + 4 * j + 1],
                                __uint_as_float(d[4 * j + 2]) + b1s[c0 + 4 * j + 2],
                                __uint_as_float(d[4 * j + 3]) + b1s[c0 + 4 * j + 3]);
        } else {
            TC_LD_X32(d, tmem + P_D0 + c0); TC_WLD();
            TC_LD_X32(d, tmem + P_D1 + c0); TC_WLD();
        }
        TC_FB();
        __syncthreads();
    }
    if (wid == 0) TC_DEALLOC(tmem, 256);
#else
    for (int i = blockIdx.x * blockDim.x + tid; i < NN; i += gridDim.x * blockDim.x)
        for (int j = 0; j < 64; j++) {
            float s = 0.f, r = be1[j];
            for (int k = 0; k < 64; k++) {
                s += x[(size_t)i * 64 + k] * We1[(64 + k) * 64 + j];
                r += x[(size_t)i * 64 + k] * We1[(128 + k) * 64 + j];
            }
            g_Xsr[(size_t)i * 128 + j] = s;
            g_Xsr[(size_t)i * 128 + 64 + j] = r;
        }
#endif
}

// ===================== edge kernel =====================
#define E_TP 0
#define E_MB 16
#define E_B2 64
#define E_B3 320
#define E_SS 576
#define E_TT 1088
#define E_W1H 2048
#define E_W1L 10240
#define E_W2H 18432
#define E_W2L 26624
#define E_W3H 34816
#define E_W3L 43008
#define E_BX  51200
#define E_SZ  86016
#define E_AHI 0
#define E_ALO 32
#define E_D   64

__global__ __launch_bounds__(256, 2)
void edge_mma_kernel(const float* __restrict__ x,
                     const float* __restrict__ e,
                     const int* __restrict__ senders,
                     const int* __restrict__ receivers,
                     const float* __restrict__ We1, const float* __restrict__ be1,
                     const float* __restrict__ We2, const float* __restrict__ be2,
                     const float* __restrict__ We3, const float* __restrict__ be3) {
    extern __shared__ char smc[];
    const int tid = threadIdx.x;
#if TC_PATH
    const uint32_t sb = smem_u32(smc);
    const int wid = tid >> 5, lane = tid & 31;
    if (wid == 0) TC_ALLOC(sb + E_TP, 128);
    if (tid == 0) MB_INIT(sb + E_MB, 1);
    float* b2s = (float*)(smc + E_B2);
    float* b3s = (float*)(smc + E_B3);
    int* ss = (int*)(smc + E_SS);
    int* tt = (int*)(smc + E_TT);
    float* Bx = (float*)(smc + E_BX);    // 128 rows x 68 stride
    if (tid < 64) { b2s[tid] = be2[tid]; b3s[tid] = be3[tid]; }
    for (int i = tid; i < 4096; i += 256) {
        int k = i >> 6, n = i & 63;
        uint32_t o = OFFB(n, k);
        store_wsplit(smc, E_W1H, E_W1L, o, We1[k * 64 + n]);   // e-part rows [0,64)
        store_wsplit(smc, E_W2H, E_W2L, o, We2[i]);
        store_wsplit(smc, E_W3H, E_W3L, o, We3[i]);
    }
    __syncthreads();
    uint32_t tmem;
    asm volatile("ld.shared.b32 %0, [%1];" : "=r"(tmem) : "r"(sb + E_TP));
    const u64 dW1h = mkdesc(sb + E_W1H), dW1l = mkdesc(sb + E_W1L);
    const u64 dW2h = mkdesc(sb + E_W2H), dW2l = mkdesc(sb + E_W2L);
    const u64 dW3h = mkdesc(sb + E_W3H), dW3l = mkdesc(sb + E_W3L);
    const float4* e4 = (const float4*)e;
    const float4* Xsr4 = (const float4*)g_Xsr;
    uint32_t ph = 0;
    const int blk = wid & 3;
    const uint32_t rowoff = (uint32_t)blk << 21;
    const int row = blk * 32 + lane;
    const int c0 = (wid >= 4) ? 32 : 0;
    uint32_t d[32];

    for (int tile = blockIdx.x; tile < NE / 128; tile += gridDim.x) {
        const int base = tile * 128;
        if (tid < 128) { ss[tid] = senders[base + tid]; tt[tid] = receivers[base + tid]; }
        __syncthreads();
        if (wid < 4) {
            // warps 0-3: stage e rows -> TMEM (hi+lo)
            stage_row64(&e4[(size_t)(base + row) * 16],
                        tmem + E_AHI + rowoff, tmem + E_ALO + rowoff);
            TC_WST(); TC_FB();
        } else {
            // warps 4-7: gather Bx[r] = Xs[s[r]] + Xrb[t[r]] -> smem (row = tid-128)
            const int g = tid - 128;
            const int s = ss[g], t = tt[g];
            const float4* ps = &Xsr4[(size_t)s * 32];
            const float4* pt = &Xsr4[(size_t)t * 32 + 16];
            float4* pb = (float4*)&Bx[g * 68];
#pragma unroll
            for (int j = 0; j < 16; j++) {
                float4 a = ps[j], b = pt[j];
                pb[j] = make_float4(a.x + b.x, a.y + b.y, a.z + b.z, a.w + b.w);
            }
        }
        __syncthreads();
        // ---- layer 1: e@W1e (K=64) ----
        if (wid == 0 && elect1()) {
            TC_FA();
            mma_layer_ts(tmem + E_D, tmem + E_AHI, tmem + E_ALO, dW1h, dW1l, 4, 0u);
            TC_COMMIT(sb + E_MB);
        }
        MB_WAIT(sb + E_MB, ph); ph ^= 1;
        TC_FA();
        TC_LD_X32(d, tmem + E_D + c0);
        TC_WLD();
        {
            uint32_t hi[16], lo[16];
            const float* bx = &Bx[row * 68 + c0];
#pragma unroll
            for (int j = 0; j < 16; j++) {
                float a = fmaxf(__uint_as_float(d[2 * j])     + bx[2 * j], 0.f);
                float b = fmaxf(__uint_as_float(d[2 * j + 1]) + bx[2 * j + 1], 0.f);
                split2(a, b, hi[j], lo[j]);
            }
            TC_ST_X16(tmem + E_AHI + (c0 >> 1) + rowoff, hi);
            TC_ST_X16(tmem + E_ALO + (c0 >> 1) + rowoff, lo);
            TC_WST();
        }
        TC_FB();
        __syncthreads();
        // ---- layer 2 ----
        if (wid == 0 && elect1()) {
            TC_FA();
            mma_layer_ts(tmem + E_D, tmem + E_AHI, tmem + E_ALO, dW2h, dW2l, 4, 0u);
            TC_COMMIT(sb + E_MB);
        }
        MB_WAIT(sb + E_MB, ph); ph ^= 1;
        TC_FA();
        TC_LD_X32(d, tmem + E_D + c0);
        TC_WLD();
        {
            uint32_t hi[16], lo[16];
#pragma unroll
            for (int j = 0; j < 16; j++) {
                float a = fmaxf(__uint_as_float(d[2 * j])     + b2s[c0 + 2 * j], 0.f);
                float b = fmaxf(__uint_as_float(d[2 * j + 1]) + b2s[c0 + 2 * j + 1], 0.f);
                split2(a, b, hi[j], lo[j]);
            }
            TC_ST_X16(tmem + E_AHI + (c0 >> 1) + rowoff, hi);
            TC_ST_X16(tmem + E_ALO + (c0 >> 1) + rowoff, lo);
            TC_WST();
        }
        TC_FB();
        __syncthreads();
        // ---- layer 3 -> atomic segment sum ----
        if (wid == 0 && elect1()) {
            TC_FA();
            mma_layer_ts(tmem + E_D, tmem + E_AHI, tmem + E_ALO, dW3h, dW3l, 4, 0u);
            TC_COMMIT(sb + E_MB);
        }
        MB_WAIT(sb + E_MB, ph); ph ^= 1;
        TC_FA();
        TC_LD_X32(d, tmem + E_D + c0);
        TC_WLD(); TC_FB();
        {
            float* p = &g_agg[(size_t)tt[row] * 64 + c0];
#pragma unroll
            for (int jj = 0; jj < 4; jj++) {
                float v[8];
#pragma unroll
                for (int j = 0; j < 8; j++)
                    v[j] = __uint_as_float(d[jj * 8 + j]) + b3s[c0 + jj * 8 + j];
                red_add_v4(p + jj * 8, v[0], v[1], v[2], v[3]);
                red_add_v4(p + jj * 8 + 4, v[4], v[5], v[6], v[7]);
            }
        }
        __syncthreads();
    }
    if (wid == 0) TC_DEALLOC(tmem, 128);
#else
    // naive correct fallback (compiled for non-sm_103a passes only)
    for (int i = blockIdx.x * blockDim.x + tid; i < NE; i += gridDim.x * blockDim.x) {
        int s = senders[i], t = receivers[i];
        float h1[64], h2[64];
        for (int j = 0; j < 64; j++) {
            float a = be1[j];
            for (int k = 0; k < 64; k++) a += e[(size_t)i * 64 + k] * We1[k * 64 + j];
            for (int k = 0; k < 64; k++) a += x[(size_t)s * 64 + k] * We1[(64 + k) * 64 + j];
            for (int k = 0; k < 64; k++) a += x[(size_t)t * 64 + k] * We1[(128 + k) * 64 + j];
            h1[j] = fmaxf(a, 0.f);
        }
        for (int j = 0; j < 64; j++) {
            float a = be2[j];
            for (int k = 0; k < 64; k++) a += h1[k] * We2[k * 64 + j];
            h2[j] = fmaxf(a, 0.f);
        }
        for (int j = 0; j < 64; j++) {
            float a = be3[j];
            for (int k = 0; k < 64; k++) a += h2[k] * We3[k * 64 + j];
            atomicAdd(&g_agg[(size_t)t * 64 + j], a);
        }
    }
#endif
}

// ===================== node kernel =====================
#define N_TP 0
#define N_MB 16
#define N_B1 64
#define N_B2 320
#define N_B3 576
#define N_W1H 1024
#define N_W1L 17408
#define N_W2H 33792
#define N_W2L 41984
#define N_W3H 50176
#define N_W3L 58368
#define N_SZ 66560
#define N_AHI 0
#define N_ALO 64
#define N_D   128

__global__ __launch_bounds__(256, 2)
void node_mma_kernel(const float* __restrict__ x,
                     const float* __restrict__ Wn1, const float* __restrict__ bn1,
                     const float* __restrict__ Wn2, const float* __restrict__ bn2,
                     const float* __restrict__ Wn3, const float* __restrict__ bn3,
                     float* __restrict__ out) {
    extern __shared__ char smc[];
    const int tid = threadIdx.x;
#if TC_PATH
    const uint32_t sb = smem_u32(smc);
    const int wid = tid >> 5, lane = tid & 31;
    if (wid == 0) TC_ALLOC(sb + N_TP, 256);
    if (tid == 0) MB_INIT(sb + N_MB, 1);
    float* b1s = (float*)(smc + N_B1);
    float* b2s = (float*)(smc + N_B2);
    float* b3s = (float*)(smc + N_B3);
    if (tid < 64) { b1s[tid] = bn1[tid]; b2s[tid] = bn2[tid]; b3s[tid] = bn3[tid]; }
    for (int i = tid; i < 8192; i += 256) {
        int k = i >> 6, n = i & 63;
        store_wsplit(smc, N_W1H, N_W1L, OFFB(n, k), Wn1[i]);
    }
    for (int i = tid; i < 4096; i += 256) {
        int k = i >> 6, n = i & 63;
        uint32_t o = OFFB(n, k);
        store_wsplit(smc, N_W2H, N_W2L, o, Wn2[i]);
        store_wsplit(smc, N_W3H, N_W3L, o, Wn3[i]);
    }
    __syncthreads();
    uint32_t tmem;
    asm volatile("ld.shared.b32 %0, [%1];" : "=r"(tmem) : "r"(sb + N_TP));
    const u64 dW1h = mkdesc(sb + N_W1H), dW1l = mkdesc(sb + N_W1L);
    const u64 dW2h = mkdesc(sb + N_W2H), dW2l = mkdesc(sb + N_W2L);
    const u64 dW3h = mkdesc(sb + N_W3H), dW3l = mkdesc(sb + N_W3L);
    const float4* x4 = (const float4*)x;
    const float4* ag4 = (const float4*)g_agg;
    uint32_t ph = 0;
    const int blk = wid & 3;
    const uint32_t rowoff = (uint32_t)blk << 21;
    const int row = blk * 32 + lane;
    const int c0 = (wid >= 4) ? 32 : 0;
    uint32_t d[32];
    const int NT = (NN + 127) / 128;
    float4 zero4 = make_float4(0.f, 0.f, 0.f, 0.f);

    for (int tile = blockIdx.x; tile < NT; tile += gridDim.x) {
        const int base = tile * 128;
        const int n = base + row;
        // stage A = [x | agg]: warps 0-3 x -> cols [0,32), warps 4-7 agg -> cols [32,64)
        {
            const float4* src = (wid < 4) ? &x4[(size_t)n * 16] : &ag4[(size_t)n * 16];
            float4 v[16];
            if (n < NN) {
#pragma unroll
                for (int j = 0; j < 16; j++) v[j] = src[j];
            } else {
#pragma unroll
                for (int j = 0; j < 16; j++) v[j] = zero4;
            }
            uint32_t hi[32], lo[32];
#pragma unroll
            for (int j = 0; j < 16; j++) {
                split2(v[j].x, v[j].y, hi[2 * j], lo[2 * j]);
                split2(v[j].z, v[j].w, hi[2 * j + 1], lo[2 * j + 1]);
            }
            uint32_t off = (wid < 4) ? 0u : 32u;
            TC_ST_X32(tmem + N_AHI + off + rowoff, hi);
            TC_ST_X32(tmem + N_ALO + off + rowoff, lo);
        }
        TC_WST(); TC_FB();
        __syncthreads();
        // ---- layer 1 (K=128) ----
        if (wid == 0 && elect1()) {
            TC_FA();
            mma_layer_ts(tmem + N_D, tmem + N_AHI, tmem + N_ALO, dW1h, dW1l, 8, 0u);
            TC_COMMIT(sb + N_MB);
        }
        MB_WAIT(sb + N_MB, ph); ph ^= 1;
        TC_FA();
        TC_LD_X32(d, tmem + N_D + c0);
        TC_WLD();
        {
            uint32_t hi[16], lo[16];
#pragma unroll
            for (int j = 0; j < 16; j++) {
                float a = fmaxf(__uint_as_float(d[2 * j])     + b1s[c0 + 2 * j], 0.f);
                float b = fmaxf(__uint_as_float(d[2 * j + 1]) + b1s[c0 + 2 * j + 1], 0.f);
                split2(a, b, hi[j], lo[j]);
            }
            TC_ST_X16(tmem + N_AHI + (c0 >> 1) + rowoff, hi);
            TC_ST_X16(tmem + N_ALO + (c0 >> 1) + rowoff, lo);
            TC_WST();
        }
        TC_FB();
        __syncthreads();
        // ---- layer 2 (K=64, reads A cols [0,32)) ----
        if (wid == 0 && elect1()) {
            TC_FA();
            mma_layer_ts(tmem + N_D, tmem + N_AHI, tmem + N_ALO, dW2h, dW2l, 4, 0u);
            TC_COMMIT(sb + N_MB);
        }
        MB_WAIT(sb + N_MB, ph); ph ^= 1;
        TC_FA();
        TC_LD_X32(d, tmem + N_D + c0);
        TC_WLD();
        {
            uint32_t hi[16], lo[16];
#pragma unroll
            for (int j = 0; j < 16; j++) {
                float a = fmaxf(__uint_as_float(d[2 * j])     + b2s[c0 + 2 * j], 0.f);
                float b = fmaxf(__uint_as_float(d[2 * j + 1]) + b2s[c0 + 2 * j + 1], 0.f);
                split2(a, b, hi[j], lo[j]);
            }
            TC_ST_X16(tmem + N_AHI + (c0 >> 1) + rowoff, hi);
            TC_ST_X16(tmem + N_ALO + (c0 >> 1) + rowoff, lo);
            TC_WST();
        }
        TC_FB();
        __syncthreads();
        // ---- layer 3 -> out ----
        if (wid == 0 && elect1()) {
            TC_FA();
            mma_layer_ts(tmem + N_D, tmem + N_AHI, tmem + N_ALO, dW3h, dW3l, 4, 0u);
            TC_COMMIT(sb + N_MB);
        }
        MB_WAIT(sb + N_MB, ph); ph ^= 1;
        TC_FA();
        TC_LD_X32(d, tmem + N_D + c0);
        TC_WLD(); TC_FB();
        if (n < NN) {
#pragma unroll
            for (int jj = 0; jj < 4; jj++) {
                float v[8];
#pragma unroll
                for (int j = 0; j < 8; j++)
                    v[j] = __uint_as_float(d[jj * 8 + j]) + b3s[c0 + jj * 8 + j];
                *(float4*)&out[(size_t)n * 64 + c0 + jj * 8]     = make_float4(v[0], v[1], v[2], v[3]);
                *(float4*)&out[(size_t)n * 64 + c0 + jj * 8 + 4] = make_float4(v[4], v[5], v[6], v[7]);
            }
        }
        __syncthreads();
    }
    if (wid == 0) TC_DEALLOC(tmem, 256);
#else
    for (int i = blockIdx.x * blockDim.x + tid; i < NN; i += gridDim.x * blockDim.x) {
        float h1[64], h2[64];
        for (int j = 0; j < 64; j++) {
            float a = bn1[j];
            for (int k = 0; k < 64; k++) a += x[(size_t)i * 64 + k] * Wn1[k * 64 + j];
            for (int k = 0; k < 64; k++) a += g_agg[(size_t)i * 64 + k] * Wn1[(64 + k) * 64 + j];
            h1[j] = fmaxf(a, 0.f);
        }
        for (int j = 0; j < 64; j++) {
            float a = bn2[j];
            for (int k = 0; k < 64; k++) a += h1[k] * Wn2[k * 64 + j];
            h2[j] = fmaxf(a, 0.f);
        }
        for (int j = 0; j < 64; j++) {
            float a = bn3[j];
            for (int k = 0; k < 64; k++) a += h2[k] * Wn3[k * 64 + j];
            out[(size_t)i * 64 + j] = a;
        }
    }
#endif
}

// ===================== launch =====================
extern "C" void kernel_launch(void* const* d_in, const int* in_sizes, int n_in,
                              void* d_out, int out_size) {
    const float* x         = (const float*)d_in[0];
    const float* e         = (const float*)d_in[1];
    const int*   senders   = (const int*)d_in[2];
    const int*   receivers = (const int*)d_in[3];
    const float* We1 = (const float*)d_in[4];
    const float* be1 = (const float*)d_in[5];
    const float* We2 = (const float*)d_in[6];
    const float* be2 = (const float*)d_in[7];
    const float* We3 = (const float*)d_in[8];
    const float* be3 = (const float*)d_in[9];
    const float* Wn1 = (const float*)d_in[10];
    const float* bn1 = (const float*)d_in[11];
    const float* Wn2 = (const float*)d_in[12];
    const float* bn2 = (const float*)d_in[13];
    const float* Wn3 = (const float*)d_in[14];
    const float* bn3 = (const float*)d_in[15];
    float* out = (float*)d_out;

    cudaFuncSetAttribute(pre_mma_kernel,  cudaFuncAttributeMaxDynamicSharedMemorySize, P_SZ);
    cudaFuncSetAttribute(edge_mma_kernel, cudaFuncAttributeMaxDynamicSharedMemorySize, E_SZ);
    cudaFuncSetAttribute(node_mma_kernel, cudaFuncAttributeMaxDynamicSharedMemorySize, N_SZ);

    zero_agg_kernel<<<304, 256>>>();
    pre_mma_kernel<<<304, 256, P_SZ>>>(x, We1, be1);
    edge_mma_kernel<<<304, 256, E_SZ>>>(x, e, senders, receivers,
                                        We1, be1, We2, be2, We3, be3);
    node_mma_kernel<<<304, 256, N_SZ>>>(x, Wn1, bn1, Wn2, bn2, Wn3, bn3, out);
}

// round 8
// speedup vs baseline: 4.9042x; 1.2237x over previous
#include <cuda_runtime.h>
#include <cuda_bf16.h>
#include <cstdint>

#define NN 100000
#define NE 1600000
using u64 = unsigned long long;

#if !defined(__CUDA_ARCH__) || defined(__CUDA_ARCH_FEAT_SM103_ALL)
#define TC_PATH 1
#else
#define TC_PATH 0
#endif

// scratch (static device globals: allocation-free)
__device__ float g_agg[NN * 64];
__device__ float g_Xsr[NN * 128];   // [Xs(64) | Xr+be1(64)] per node

__device__ __forceinline__ void red_add_v4(float* a, float x, float y, float z, float w) {
    asm volatile("red.global.add.v4.f32 [%0], {%1, %2, %3, %4};"
                 :: "l"(a), "f"(x), "f"(y), "f"(z), "f"(w) : "memory");
}

#if TC_PATH
// ===================== tcgen05 machinery (sm_103a only) =====================
__device__ __forceinline__ uint32_t smem_u32(const void* p) {
    return (uint32_t)__cvta_generic_to_shared(p);
}
__device__ __forceinline__ bool elect1() {
    uint32_t pr;
    asm volatile("{\n\t.reg .pred p;\n\telect.sync _|p, 0xFFFFFFFF;\n\tselp.b32 %0, 1, 0, p;\n\t}" : "=r"(pr));
    return pr != 0;
}
#define TC_ALLOC(a, n)  asm volatile("tcgen05.alloc.cta_group::1.sync.aligned.shared::cta.b32 [%0], %1;" :: "r"(a), "r"((uint32_t)(n)) : "memory")
#define TC_RELINQ()     asm volatile("tcgen05.relinquish_alloc_permit.cta_group::1.sync.aligned;")
#define TC_DEALLOC(t, n) asm volatile("tcgen05.dealloc.cta_group::1.sync.aligned.b32 %0, %1;" :: "r"(t), "r"((uint32_t)(n)))
#define TC_COMMIT(mb)   asm volatile("tcgen05.commit.cta_group::1.mbarrier::arrive::one.shared::cluster.b64 [%0];" :: "r"(mb) : "memory")
#define TC_FA()         asm volatile("tcgen05.fence::after_thread_sync;" ::: "memory")
#define TC_FB()         asm volatile("tcgen05.fence::before_thread_sync;" ::: "memory")
#define TC_WLD()        asm volatile("tcgen05.wait::ld.sync.aligned;" ::: "memory")
#define TC_WST()        asm volatile("tcgen05.wait::st.sync.aligned;" ::: "memory")
#define MB_INIT(mb, c)  asm volatile("mbarrier.init.shared.b64 [%0], %1;" :: "r"(mb), "r"((uint32_t)(c)) : "memory")
#define MB_WAIT(mb, ph) do { \
    uint32_t _m = (mb), _p = (ph), _d; \
    asm volatile("{\n\t.reg .pred p;\n\tmbarrier.try_wait.parity.acquire.cta.shared::cta.b64 p, [%1], %2;\n\tselp.b32 %0, 1, 0, p;\n\t}" \
        : "=r"(_d) : "r"(_m), "r"(_p) : "memory"); \
    if (!_d) { \
        asm volatile("{\n\t.reg .pred P1;\n\tWL_%=:\n\tmbarrier.try_wait.parity.acquire.cta.shared::cta.b64 P1, [%0], %1, 0x989680;\n\t@P1 bra.uni WD_%=;\n\tbra.uni WL_%=;\n\tWD_%=:\n\t}" \
            :: "r"(_m), "r"(_p) : "memory"); } \
} while (0)
#define TC_LD_X32(r, tm) \
    asm volatile("tcgen05.ld.sync.aligned.32x32b.x32.b32 " \
        "{%0,%1,%2,%3,%4,%5,%6,%7,%8,%9,%10,%11,%12,%13,%14,%15," \
        "%16,%17,%18,%19,%20,%21,%22,%23,%24,%25,%26,%27,%28,%29,%30,%31}, [%32];" \
        : "=r"((r)[0]),"=r"((r)[1]),"=r"((r)[2]),"=r"((r)[3]),"=r"((r)[4]),"=r"((r)[5]),"=r"((r)[6]),"=r"((r)[7]), \
          "=r"((r)[8]),"=r"((r)[9]),"=r"((r)[10]),"=r"((r)[11]),"=r"((r)[12]),"=r"((r)[13]),"=r"((r)[14]),"=r"((r)[15]), \
          "=r"((r)[16]),"=r"((r)[17]),"=r"((r)[18]),"=r"((r)[19]),"=r"((r)[20]),"=r"((r)[21]),"=r"((r)[22]),"=r"((r)[23]), \
          "=r"((r)[24]),"=r"((r)[25]),"=r"((r)[26]),"=r"((r)[27]),"=r"((r)[28]),"=r"((r)[29]),"=r"((r)[30]),"=r"((r)[31]) \
        : "r"(tm))
#define TC_ST_X32(tm, r) \
    asm volatile("tcgen05.st.sync.aligned.32x32b.x32.b32 [%0], " \
        "{%1,%2,%3,%4,%5,%6,%7,%8,%9,%10,%11,%12,%13,%14,%15,%16," \
        "%17,%18,%19,%20,%21,%22,%23,%24,%25,%26,%27,%28,%29,%30,%31,%32};" \
        :: "r"(tm), \
           "r"((r)[0]),"r"((r)[1]),"r"((r)[2]),"r"((r)[3]),"r"((r)[4]),"r"((r)[5]),"r"((r)[6]),"r"((r)[7]), \
           "r"((r)[8]),"r"((r)[9]),"r"((r)[10]),"r"((r)[11]),"r"((r)[12]),"r"((r)[13]),"r"((r)[14]),"r"((r)[15]), \
           "r"((r)[16]),"r"((r)[17]),"r"((r)[18]),"r"((r)[19]),"r"((r)[20]),"r"((r)[21]),"r"((r)[22]),"r"((r)[23]), \
           "r"((r)[24]),"r"((r)[25]),"r"((r)[26]),"r"((r)[27]),"r"((r)[28]),"r"((r)[29]),"r"((r)[30]),"r"((r)[31]) \
        : "memory")
#define TC_ST_X16(tm, r) \
    asm volatile("tcgen05.st.sync.aligned.32x32b.x16.b32 [%0], " \
        "{%1,%2,%3,%4,%5,%6,%7,%8,%9,%10,%11,%12,%13,%14,%15,%16};" \
        :: "r"(tm), \
           "r"((r)[0]),"r"((r)[1]),"r"((r)[2]),"r"((r)[3]),"r"((r)[4]),"r"((r)[5]),"r"((r)[6]),"r"((r)[7]), \
           "r"((r)[8]),"r"((r)[9]),"r"((r)[10]),"r"((r)[11]),"r"((r)[12]),"r"((r)[13]),"r"((r)[14]),"r"((r)[15]) \
        : "memory")

#define SWZ(b) ((b) ^ (((b) >> 3) & 0x70))
// B (weights in smem, 64 N-rows, K-major, SW128 blocked atoms): n row, k element
#define OFFB(n, k) ((uint32_t)(((uint32_t)((k) >> 6) * 8u + ((uint32_t)(n) >> 3)) * 1024u + SWZ((uint32_t)((((n) & 7) * 128) + ((k) & 63) * 2))))

static __device__ __forceinline__ u64 mkdesc(uint32_t a) {
    return (2ULL << 61) | (1ULL << 46) | (64ULL << 32) | (1ULL << 16) | ((u64)(a >> 4) & 0x3FFF);
}
#define IDESC 0x8100490u  // f32 accum, bf16 x bf16, K-major, M=128, N=64
__device__ __forceinline__ void mma_ts(uint32_t d, uint32_t a, u64 bd, uint32_t en) {
    asm volatile("{\n\t.reg .pred p;\n\tsetp.ne.u32 p, %5, 0;\n\t"
                 "tcgen05.mma.cta_group::1.kind::f16 [%0], [%1], %2, %3, {%4, %4, %4, %4}, p;\n\t}"
                 :: "r"(d), "r"(a), "l"(bd), "r"(IDESC), "r"(0u), "r"(en) : "memory");
}
// 3-pass split-bf16: D = Ah*Bh + Al*Bh + Ah*Bl  (nks K=16 steps per pass)
__device__ __forceinline__ void mma_layer_ts(uint32_t d, uint32_t ahi, uint32_t alo,
                                             u64 bh, u64 bl, int nks, uint32_t en0) {
#pragma unroll
    for (int p = 0; p < 3; p++) {
        uint32_t A = (p == 1) ? alo : ahi;
        u64 B = (p == 2) ? bl : bh;
        for (int ks = 0; ks < nks; ks++)
            mma_ts(d, A + ks * 8, B + (ks >> 2) * 512 + (ks & 3) * 2,
                   (p | ks) ? 1u : en0);
    }
}
__device__ __forceinline__ void split2(float a, float b, uint32_t& hi, uint32_t& lo) {
    __nv_bfloat162 h = __floats2bfloat162_rn(a, b);
    float2 hf = __bfloat1622float2(h);
    __nv_bfloat162 l = __floats2bfloat162_rn(a - hf.x, b - hf.y);
    hi = *(uint32_t*)&h;
    lo = *(uint32_t*)&l;
}
__device__ __forceinline__ void store_wsplit(char* smc, int oh, int ol, uint32_t off, float v) {
    __nv_bfloat16 h = __float2bfloat16(v);
    __nv_bfloat16 l = __float2bfloat16(v - __bfloat162float(h));
    *(unsigned short*)(smc + oh + off) = __bfloat16_as_ushort(h);
    *(unsigned short*)(smc + ol + off) = __bfloat16_as_ushort(l);
}
// load a fp32 row of 64 (16 float4) and split-store into TMEM cols [0,32) hi/lo
__device__ __forceinline__ void stage_row64(const float4* src, uint32_t tm_hi, uint32_t tm_lo) {
    float4 v[16];
#pragma unroll
    for (int j = 0; j < 16; j++) v[j] = src[j];
    uint32_t hi[32], lo[32];
#pragma unroll
    for (int j = 0; j < 16; j++) {
        split2(v[j].x, v[j].y, hi[2 * j], lo[2 * j]);
        split2(v[j].z, v[j].w, hi[2 * j + 1], lo[2 * j + 1]);
    }
    TC_ST_X32(tm_hi, hi);
    TC_ST_X32(tm_lo, lo);
}
#endif  // TC_PATH

// ===================== small kernels =====================
__global__ void zero_agg_kernel() {
    int i = blockIdx.x * blockDim.x + threadIdx.x;
    float4* p = (float4*)g_agg;
    for (; i < NN * 16; i += gridDim.x * blockDim.x) p[i] = make_float4(0.f, 0.f, 0.f, 0.f);
}

// ===================== pre kernel: Xsr = [x@We1_s | x@We1_r + be1] =====================
#define P_TP 0
#define P_MB 16
#define P_B1 64
#define P_WSH 1024
#define P_WSL 9216
#define P_WRH 17408
#define P_WRL 25600
#define P_SZ  33792
#define P_AHI 0
#define P_ALO 32
#define P_D0  64
#define P_D1  128

__global__ __launch_bounds__(256, 2)
void pre_mma_kernel(const float* __restrict__ x,
                    const float* __restrict__ We1, const float* __restrict__ be1) {
    extern __shared__ char smc[];
    const int tid = threadIdx.x;
#if TC_PATH
    const uint32_t sb = smem_u32(smc);
    const int wid = tid >> 5, lane = tid & 31;
    if (wid == 0) { TC_ALLOC(sb + P_TP, 256); TC_RELINQ(); }
    if (tid == 0) MB_INIT(sb + P_MB, 1);
    float* b1s = (float*)(smc + P_B1);
    if (tid < 64) b1s[tid] = be1[tid];
    for (int i = tid; i < 4096; i += 256) {
        int k = i >> 6, n = i & 63;
        uint32_t o = OFFB(n, k);
        store_wsplit(smc, P_WSH, P_WSL, o, We1[(64 + k) * 64 + n]);
        store_wsplit(smc, P_WRH, P_WRL, o, We1[(128 + k) * 64 + n]);
    }
    __syncthreads();
    uint32_t tmem;
    asm volatile("ld.shared.b32 %0, [%1];" : "=r"(tmem) : "r"(sb + P_TP));
    const u64 dWsh = mkdesc(sb + P_WSH), dWsl = mkdesc(sb + P_WSL);
    const u64 dWrh = mkdesc(sb + P_WRH), dWrl = mkdesc(sb + P_WRL);
    uint32_t ph = 0;
    const int blk = wid & 3;
    const uint32_t rowoff = (uint32_t)blk << 21;
    const int row = blk * 32 + lane;
    const int c0 = (wid >= 4) ? 32 : 0;
    uint32_t d[32];
    const int NT = (NN + 127) / 128;
    const float4* x4 = (const float4*)x;
    float4 zero4 = make_float4(0.f, 0.f, 0.f, 0.f);

    for (int tile = blockIdx.x; tile < NT; tile += gridDim.x) {
        const int base = tile * 128;
        const int n = base + row;
        // stage x: warps 0-3 write hi, warps 4-7 write lo
        {
            float4 v[16];
            if (n < NN) {
#pragma unroll
                for (int j = 0; j < 16; j++) v[j] = x4[(size_t)n * 16 + j];
            } else {
#pragma unroll
                for (int j = 0; j < 16; j++) v[j] = zero4;
            }
            uint32_t hi[32], lo[32];
#pragma unroll
            for (int j = 0; j < 16; j++) {
                split2(v[j].x, v[j].y, hi[2 * j], lo[2 * j]);
                split2(v[j].z, v[j].w, hi[2 * j + 1], lo[2 * j + 1]);
            }
            if (wid < 4) TC_ST_X32(tmem + P_AHI + rowoff, hi);
            else         TC_ST_X32(tmem + P_ALO + rowoff, lo);
        }
        TC_WST(); TC_FB();
        __syncthreads();
        if (wid == 0 && elect1()) {
            TC_FA();
            mma_layer_ts(tmem + P_D0, tmem + P_AHI, tmem + P_ALO, dWsh, dWsl, 4, 0u);
            mma_layer_ts(tmem + P_D1, tmem + P_AHI, tmem + P_ALO, dWrh, dWrl, 4, 0u);
            TC_COMMIT(sb + P_MB);
        }
        MB_WAIT(sb + P_MB, ph); ph ^= 1;
        TC_FA();
        if (n < NN) {
            TC_LD_X32(d, tmem + P_D0 + c0);
            TC_WLD();
#pragma unroll
            for (int j = 0; j < 8; j++)
                *(float4*)&g_Xsr[(size_t)n * 128 + c0 + 4 * j] =
                    make_float4(__uint_as_float(d[4 * j]), __uint_as_float(d[4 * j + 1]),
                                __uint_as_float(d[4 * j + 2]), __uint_as_float(d[4 * j + 3]));
            TC_LD_X32(d, tmem + P_D1 + c0);
            TC_WLD();
#pragma unroll
            for (int j = 0; j < 8; j++)
                *(float4*)&g_Xsr[(size_t)n * 128 + 64 + c0 + 4 * j] =
                    make_float4(__uint_as_float(d[4 * j]) + b1s[c0 + 4 * j],
                                __uint_as_float(d[4 * j + 1]) + b1s[c0 + 4 * j + 1],
                                __uint_as_float(d[4 * j + 2]) + b1s[c0 + 4 * j + 2],
                                __uint_as_float(d[4 * j + 3]) + b1s[c0 + 4 * j + 3]);
        } else {
            TC_LD_X32(d, tmem + P_D0 + c0); TC_WLD();
            TC_LD_X32(d, tmem + P_D1 + c0); TC_WLD();
        }
        TC_FB();
        __syncthreads();
    }
    if (wid == 0) TC_DEALLOC(tmem, 256);
#else
    for (int i = blockIdx.x * blockDim.x + tid; i < NN; i += gridDim.x * blockDim.x)
        for (int j = 0; j < 64; j++) {
            float s = 0.f, r = be1[j];
            for (int k = 0; k < 64; k++) {
                s += x[(size_t)i * 64 + k] * We1[(64 + k) * 64 + j];
                r += x[(size_t)i * 64 + k] * We1[(128 + k) * 64 + j];
            }
            g_Xsr[(size_t)i * 128 + j] = s;
            g_Xsr[(size_t)i * 128 + 64 + j] = r;
        }
#endif
}

// ===================== edge kernel =====================
#define E_TP 0
#define E_MB 16
#define E_B2 64
#define E_B3 320
#define E_SS 576
#define E_TT 1088
#define E_W1H 2048
#define E_W1L 10240
#define E_W2H 18432
#define E_W2L 26624
#define E_W3H 34816
#define E_W3L 43008
#define E_BX  51200
#define E_SZ  86016
#define E_AHI 0
#define E_ALO 32
#define E_D   64

__global__ __launch_bounds__(256, 2)
void edge_mma_kernel(const float* __restrict__ x,
                     const float* __restrict__ e,
                     const int* __restrict__ senders,
                     const int* __restrict__ receivers,
                     const float* __restrict__ We1, const float* __restrict__ be1,
                     const float* __restrict__ We2, const float* __restrict__ be2,
                     const float* __restrict__ We3, const float* __restrict__ be3) {
    extern __shared__ char smc[];
    const int tid = threadIdx.x;
#if TC_PATH
    const uint32_t sb = smem_u32(smc);
    const int wid = tid >> 5, lane = tid & 31;
    if (wid == 0) { TC_ALLOC(sb + E_TP, 128); TC_RELINQ(); }
    if (tid == 0) MB_INIT(sb + E_MB, 1);
    float* b2s = (float*)(smc + E_B2);
    float* b3s = (float*)(smc + E_B3);
    int* ss = (int*)(smc + E_SS);
    int* tt = (int*)(smc + E_TT);
    float* Bx = (float*)(smc + E_BX);    // 128 rows x 68 stride
    if (tid < 64) { b2s[tid] = be2[tid]; b3s[tid] = be3[tid]; }
    for (int i = tid; i < 4096; i += 256) {
        int k = i >> 6, n = i & 63;
        uint32_t o = OFFB(n, k);
        store_wsplit(smc, E_W1H, E_W1L, o, We1[k * 64 + n]);   // e-part rows [0,64)
        store_wsplit(smc, E_W2H, E_W2L, o, We2[i]);
        store_wsplit(smc, E_W3H, E_W3L, o, We3[i]);
    }
    __syncthreads();
    uint32_t tmem;
    asm volatile("ld.shared.b32 %0, [%1];" : "=r"(tmem) : "r"(sb + E_TP));
    const u64 dW1h = mkdesc(sb + E_W1H), dW1l = mkdesc(sb + E_W1L);
    const u64 dW2h = mkdesc(sb + E_W2H), dW2l = mkdesc(sb + E_W2L);
    const u64 dW3h = mkdesc(sb + E_W3H), dW3l = mkdesc(sb + E_W3L);
    const float4* e4 = (const float4*)e;
    const float4* Xsr4 = (const float4*)g_Xsr;
    uint32_t ph = 0;
    const int blk = wid & 3;
    const uint32_t rowoff = (uint32_t)blk << 21;
    const int row = blk * 32 + lane;
    const int c0 = (wid >= 4) ? 32 : 0;
    uint32_t d[32];

    for (int tile = blockIdx.x; tile < NE / 128; tile += gridDim.x) {
        const int base = tile * 128;
        if (tid < 128) { ss[tid] = senders[base + tid]; tt[tid] = receivers[base + tid]; }
        __syncthreads();
        if (wid < 4) {
            // warps 0-3: stage e rows -> TMEM (hi+lo)
            stage_row64(&e4[(size_t)(base + row) * 16],
                        tmem + E_AHI + rowoff, tmem + E_ALO + rowoff);
            TC_WST(); TC_FB();
        } else {
            // warps 4-7: gather Bx[r] = Xs[s[r]] + Xrb[t[r]] -> smem
            const int g = tid - 128;
            const int s = ss[g], t = tt[g];
            const float4* ps = &Xsr4[(size_t)s * 32];
            const float4* pt = &Xsr4[(size_t)t * 32 + 16];
            float4* pb = (float4*)&Bx[g * 68];
#pragma unroll
            for (int j = 0; j < 16; j++) {
                float4 a = ps[j], b = pt[j];
                pb[j] = make_float4(a.x + b.x, a.y + b.y, a.z + b.z, a.w + b.w);
            }
        }
        __syncthreads();
        // ---- layer 1: e@W1e (K=64) ----
        if (wid == 0 && elect1()) {
            TC_FA();
            mma_layer_ts(tmem + E_D, tmem + E_AHI, tmem + E_ALO, dW1h, dW1l, 4, 0u);
            TC_COMMIT(sb + E_MB);
        }
        MB_WAIT(sb + E_MB, ph); ph ^= 1;
        TC_FA();
        TC_LD_X32(d, tmem + E_D + c0);
        TC_WLD();
        {
            uint32_t hi[16], lo[16];
            const float* bx = &Bx[row * 68 + c0];
#pragma unroll
            for (int j = 0; j < 16; j++) {
                float a = fmaxf(__uint_as_float(d[2 * j])     + bx[2 * j], 0.f);
                float b = fmaxf(__uint_as_float(d[2 * j + 1]) + bx[2 * j + 1], 0.f);
                split2(a, b, hi[j], lo[j]);
            }
            TC_ST_X16(tmem + E_AHI + (c0 >> 1) + rowoff, hi);
            TC_ST_X16(tmem + E_ALO + (c0 >> 1) + rowoff, lo);
            TC_WST();
        }
        TC_FB();
        __syncthreads();
        // ---- layer 2 ----
        if (wid == 0 && elect1()) {
            TC_FA();
            mma_layer_ts(tmem + E_D, tmem + E_AHI, tmem + E_ALO, dW2h, dW2l, 4, 0u);
            TC_COMMIT(sb + E_MB);
        }
        MB_WAIT(sb + E_MB, ph); ph ^= 1;
        TC_FA();
        TC_LD_X32(d, tmem + E_D + c0);
        TC_WLD();
        {
            uint32_t hi[16], lo[16];
#pragma unroll
            for (int j = 0; j < 16; j++) {
                float a = fmaxf(__uint_as_float(d[2 * j])     + b2s[c0 + 2 * j], 0.f);
                float b = fmaxf(__uint_as_float(d[2 * j + 1]) + b2s[c0 + 2 * j + 1], 0.f);
                split2(a, b, hi[j], lo[j]);
            }
            TC_ST_X16(tmem + E_AHI + (c0 >> 1) + rowoff, hi);
            TC_ST_X16(tmem + E_ALO + (c0 >> 1) + rowoff, lo);
            TC_WST();
        }
        TC_FB();
        __syncthreads();
        // ---- layer 3 -> atomic segment sum ----
        if (wid == 0 && elect1()) {
            TC_FA();
            mma_layer_ts(tmem + E_D, tmem + E_AHI, tmem + E_ALO, dW3h, dW3l, 4, 0u);
            TC_COMMIT(sb + E_MB);
        }
        MB_WAIT(sb + E_MB, ph); ph ^= 1;
        TC_FA();
        TC_LD_X32(d, tmem + E_D + c0);
        TC_WLD(); TC_FB();
        {
            float* p = &g_agg[(size_t)tt[row] * 64 + c0];
#pragma unroll
            for (int jj = 0; jj < 4; jj++) {
                float v[8];
#pragma unroll
                for (int j = 0; j < 8; j++)
                    v[j] = __uint_as_float(d[jj * 8 + j]) + b3s[c0 + jj * 8 + j];
                red_add_v4(p + jj * 8, v[0], v[1], v[2], v[3]);
                red_add_v4(p + jj * 8 + 4, v[4], v[5], v[6], v[7]);
            }
        }
        __syncthreads();
    }
    if (wid == 0) TC_DEALLOC(tmem, 128);
#else
    // naive correct fallback (compiled for non-sm_103a passes only)
    for (int i = blockIdx.x * blockDim.x + tid; i < NE; i += gridDim.x * blockDim.x) {
        int s = senders[i], t = receivers[i];
        float h1[64], h2[64];
        for (int j = 0; j < 64; j++) {
            float a = be1[j];
            for (int k = 0; k < 64; k++) a += e[(size_t)i * 64 + k] * We1[k * 64 + j];
            for (int k = 0; k < 64; k++) a += x[(size_t)s * 64 + k] * We1[(64 + k) * 64 + j];
            for (int k = 0; k < 64; k++) a += x[(size_t)t * 64 + k] * We1[(128 + k) * 64 + j];
            h1[j] = fmaxf(a, 0.f);
        }
        for (int j = 0; j < 64; j++) {
            float a = be2[j];
            for (int k = 0; k < 64; k++) a += h1[k] * We2[k * 64 + j];
            h2[j] = fmaxf(a, 0.f);
        }
        for (int j = 0; j < 64; j++) {
            float a = be3[j];
            for (int k = 0; k < 64; k++) a += h2[k] * We3[k * 64 + j];
            atomicAdd(&g_agg[(size_t)t * 64 + j], a);
        }
    }
#endif
}

// ===================== node kernel =====================
#define N_TP 0
#define N_MB 16
#define N_B1 64
#define N_B2 320
#define N_B3 576
#define N_W1H 1024
#define N_W1L 17408
#define N_W2H 33792
#define N_W2L 41984
#define N_W3H 50176
#define N_W3L 58368
#define N_SZ 66560
#define N_AHI 0
#define N_ALO 64
#define N_D   128

__global__ __launch_bounds__(256, 2)
void node_mma_kernel(const float* __restrict__ x,
                     const float* __restrict__ Wn1, const float* __restrict__ bn1,
                     const float* __restrict__ Wn2, const float* __restrict__ bn2,
                     const float* __restrict__ Wn3, const float* __restrict__ bn3,
                     float* __restrict__ out) {
    extern __shared__ char smc[];
    const int tid = threadIdx.x;
#if TC_PATH
    const uint32_t sb = smem_u32(smc);
    const int wid = tid >> 5, lane = tid & 31;
    if (wid == 0) { TC_ALLOC(sb + N_TP, 256); TC_RELINQ(); }
    if (tid == 0) MB_INIT(sb + N_MB, 1);
    float* b1s = (float*)(smc + N_B1);
    float* b2s = (float*)(smc + N_B2);
    float* b3s = (float*)(smc + N_B3);
    if (tid < 64) { b1s[tid] = bn1[tid]; b2s[tid] = bn2[tid]; b3s[tid] = bn3[tid]; }
    for (int i = tid; i < 8192; i += 256) {
        int k = i >> 6, n = i & 63;
        store_wsplit(smc, N_W1H, N_W1L, OFFB(n, k), Wn1[i]);
    }
    for (int i = tid; i < 4096; i += 256) {
        int k = i >> 6, n = i & 63;
        uint32_t o = OFFB(n, k);
        store_wsplit(smc, N_W2H, N_W2L, o, Wn2[i]);
        store_wsplit(smc, N_W3H, N_W3L, o, Wn3[i]);
    }
    __syncthreads();
    uint32_t tmem;
    asm volatile("ld.shared.b32 %0, [%1];" : "=r"(tmem) : "r"(sb + N_TP));
    const u64 dW1h = mkdesc(sb + N_W1H), dW1l = mkdesc(sb + N_W1L);
    const u64 dW2h = mkdesc(sb + N_W2H), dW2l = mkdesc(sb + N_W2L);
    const u64 dW3h = mkdesc(sb + N_W3H), dW3l = mkdesc(sb + N_W3L);
    const float4* x4 = (const float4*)x;
    const float4* ag4 = (const float4*)g_agg;
    uint32_t ph = 0;
    const int blk = wid & 3;
    const uint32_t rowoff = (uint32_t)blk << 21;
    const int row = blk * 32 + lane;
    const int c0 = (wid >= 4) ? 32 : 0;
    uint32_t d[32];
    const int NT = (NN + 127) / 128;
    float4 zero4 = make_float4(0.f, 0.f, 0.f, 0.f);

    for (int tile = blockIdx.x; tile < NT; tile += gridDim.x) {
        const int base = tile * 128;
        const int n = base + row;
        // stage A = [x | agg]: warps 0-3 x -> cols [0,32), warps 4-7 agg -> cols [32,64)
        {
            const float4* src = (wid < 4) ? &x4[(size_t)n * 16] : &ag4[(size_t)n * 16];
            float4 v[16];
            if (n < NN) {
#pragma unroll
                for (int j = 0; j < 16; j++) v[j] = src[j];
            } else {
#pragma unroll
                for (int j = 0; j < 16; j++) v[j] = zero4;
            }
            uint32_t hi[32], lo[32];
#pragma unroll
            for (int j = 0; j < 16; j++) {
                split2(v[j].x, v[j].y, hi[2 * j], lo[2 * j]);
                split2(v[j].z, v[j].w, hi[2 * j + 1], lo[2 * j + 1]);
            }
            uint32_t off = (wid < 4) ? 0u : 32u;
            TC_ST_X32(tmem + N_AHI + off + rowoff, hi);
            TC_ST_X32(tmem + N_ALO + off + rowoff, lo);
        }
        TC_WST(); TC_FB();
        __syncthreads();
        // ---- layer 1 (K=128) ----
        if (wid == 0 && elect1()) {
            TC_FA();
            mma_layer_ts(tmem + N_D, tmem + N_AHI, tmem + N_ALO, dW1h, dW1l, 8, 0u);
            TC_COMMIT(sb + N_MB);
        }
        MB_WAIT(sb + N_MB, ph); ph ^= 1;
        TC_FA();
        TC_LD_X32(d, tmem + N_D + c0);
        TC_WLD();
        {
            uint32_t hi[16], lo[16];
#pragma unroll
            for (int j = 0; j < 16; j++) {
                float a = fmaxf(__uint_as_float(d[2 * j])     + b1s[c0 + 2 * j], 0.f);
                float b = fmaxf(__uint_as_float(d[2 * j + 1]) + b1s[c0 + 2 * j + 1], 0.f);
                split2(a, b, hi[j], lo[j]);
            }
            TC_ST_X16(tmem + N_AHI + (c0 >> 1) + rowoff, hi);
            TC_ST_X16(tmem + N_ALO + (c0 >> 1) + rowoff, lo);
            TC_WST();
        }
        TC_FB();
        __syncthreads();
        // ---- layer 2 (K=64) ----
        if (wid == 0 && elect1()) {
            TC_FA();
            mma_layer_ts(tmem + N_D, tmem + N_AHI, tmem + N_ALO, dW2h, dW2l, 4, 0u);
            TC_COMMIT(sb + N_MB);
        }
        MB_WAIT(sb + N_MB, ph); ph ^= 1;
        TC_FA();
        TC_LD_X32(d, tmem + N_D + c0);
        TC_WLD();
        {
            uint32_t hi[16], lo[16];
#pragma unroll
            for (int j = 0; j < 16; j++) {
                float a = fmaxf(__uint_as_float(d[2 * j])     + b2s[c0 + 2 * j], 0.f);
                float b = fmaxf(__uint_as_float(d[2 * j + 1]) + b2s[c0 + 2 * j + 1], 0.f);
                split2(a, b, hi[j], lo[j]);
            }
            TC_ST_X16(tmem + N_AHI + (c0 >> 1) + rowoff, hi);
            TC_ST_X16(tmem + N_ALO + (c0 >> 1) + rowoff, lo);
            TC_WST();
        }
        TC_FB();
        __syncthreads();
        // ---- layer 3 -> out ----
        if (wid == 0 && elect1()) {
            TC_FA();
            mma_layer_ts(tmem + N_D, tmem + N_AHI, tmem + N_ALO, dW3h, dW3l, 4, 0u);
            TC_COMMIT(sb + N_MB);
        }
        MB_WAIT(sb + N_MB, ph); ph ^= 1;
        TC_FA();
        TC_LD_X32(d, tmem + N_D + c0);
        TC_WLD(); TC_FB();
        if (n < NN) {
#pragma unroll
            for (int jj = 0; jj < 4; jj++) {
                float v[8];
#pragma unroll
                for (int j = 0; j < 8; j++)
                    v[j] = __uint_as_float(d[jj * 8 + j]) + b3s[c0 + jj * 8 + j];
                *(float4*)&out[(size_t)n * 64 + c0 + jj * 8]     = make_float4(v[0], v[1], v[2], v[3]);
                *(float4*)&out[(size_t)n * 64 + c0 + jj * 8 + 4] = make_float4(v[4], v[5], v[6], v[7]);
            }
        }
        __syncthreads();
    }
    if (wid == 0) TC_DEALLOC(tmem, 256);
#else
    for (int i = blockIdx.x * blockDim.x + tid; i < NN; i += gridDim.x * blockDim.x) {
        float h1[64], h2[64];
        for (int j = 0; j < 64; j++) {
            float a = bn1[j];
            for (int k = 0; k < 64; k++) a += x[(size_t)i * 64 + k] * Wn1[k * 64 + j];
            for (int k = 0; k < 64; k++) a += g_agg[(size_t)i * 64 + k] * Wn1[(64 + k) * 64 + j];
            h1[j] = fmaxf(a, 0.f);
        }
        for (int j = 0; j < 64; j++) {
            float a = bn2[j];
            for (int k = 0; k < 64; k++) a += h1[k] * Wn2[k * 64 + j];
            h2[j] = fmaxf(a, 0.f);
        }
        for (int j = 0; j < 64; j++) {
            float a = bn3[j];
            for (int k = 0; k < 64; k++) a += h2[k] * Wn3[k * 64 + j];
            out[(size_t)i * 64 + j] = a;
        }
    }
#endif
}

// ===================== launch =====================
extern "C" void kernel_launch(void* const* d_in, const int* in_sizes, int n_in,
                              void* d_out, int out_size) {
    const float* x         = (const float*)d_in[0];
    const float* e         = (const float*)d_in[1];
    const int*   senders   = (const int*)d_in[2];
    const int*   receivers = (const int*)d_in[3];
    const float* We1 = (const float*)d_in[4];
    const float* be1 = (const float*)d_in[5];
    const float* We2 = (const float*)d_in[6];
    const float* be2 = (const float*)d_in[7];
    const float* We3 = (const float*)d_in[8];
    const float* be3 = (const float*)d_in[9];
    const float* Wn1 = (const float*)d_in[10];
    const float* bn1 = (const float*)d_in[11];
    const float* Wn2 = (const float*)d_in[12];
    const float* bn2 = (const float*)d_in[13];
    const float* Wn3 = (const float*)d_in[14];
    const float* bn3 = (const float*)d_in[15];
    float* out = (float*)d_out;

    cudaFuncSetAttribute(pre_mma_kernel,  cudaFuncAttributeMaxDynamicSharedMemorySize, P_SZ);
    cudaFuncSetAttribute(edge_mma_kernel, cudaFuncAttributeMaxDynamicSharedMemorySize, E_SZ);
    cudaFuncSetAttribute(node_mma_kernel, cudaFuncAttributeMaxDynamicSharedMemorySize, N_SZ);

    zero_agg_kernel<<<304, 256>>>();
    pre_mma_kernel<<<304, 256, P_SZ>>>(x, We1, be1);
    edge_mma_kernel<<<304, 256, E_SZ>>>(x, e, senders, receivers,
                                        We1, be1, We2, be2, We3, be3);
    node_mma_kernel<<<304, 256, N_SZ>>>(x, Wn1, bn1, Wn2, bn2, Wn3, bn3, out);
}

// round 9
// speedup vs baseline: 5.0760x; 1.0350x over previous
#include <cuda_runtime.h>
#include <cuda_bf16.h>
#include <cstdint>

#define NN 100000
#define NE 1600000
using u64 = unsigned long long;

#if !defined(__CUDA_ARCH__) || defined(__CUDA_ARCH_FEAT_SM103_ALL)
#define TC_PATH 1
#else
#define TC_PATH 0
#endif

// scratch (static device globals: allocation-free)
__device__ float g_agg[NN * 64];
__device__ float g_Xsr[NN * 128];   // [Xs(64) | Xr+be1(64)] per node

__device__ __forceinline__ void red_add_v4(float* a, float x, float y, float z, float w) {
    asm volatile("red.global.add.v4.f32 [%0], {%1, %2, %3, %4};"
                 :: "l"(a), "f"(x), "f"(y), "f"(z), "f"(w) : "memory");
}

#if TC_PATH
// ===================== tcgen05 machinery (sm_103a only) =====================
__device__ __forceinline__ uint32_t smem_u32(const void* p) {
    return (uint32_t)__cvta_generic_to_shared(p);
}
__device__ __forceinline__ bool elect1() {
    uint32_t pr;
    asm volatile("{\n\t.reg .pred p;\n\telect.sync _|p, 0xFFFFFFFF;\n\tselp.b32 %0, 1, 0, p;\n\t}" : "=r"(pr));
    return pr != 0;
}
#define TC_ALLOC(a, n)  asm volatile("tcgen05.alloc.cta_group::1.sync.aligned.shared::cta.b32 [%0], %1;" :: "r"(a), "r"((uint32_t)(n)) : "memory")
#define TC_RELINQ()     asm volatile("tcgen05.relinquish_alloc_permit.cta_group::1.sync.aligned;")
#define TC_DEALLOC(t, n) asm volatile("tcgen05.dealloc.cta_group::1.sync.aligned.b32 %0, %1;" :: "r"(t), "r"((uint32_t)(n)))
#define TC_COMMIT(mb)   asm volatile("tcgen05.commit.cta_group::1.mbarrier::arrive::one.shared::cluster.b64 [%0];" :: "r"(mb) : "memory")
#define TC_FA()         asm volatile("tcgen05.fence::after_thread_sync;" ::: "memory")
#define TC_FB()         asm volatile("tcgen05.fence::before_thread_sync;" ::: "memory")
#define TC_WLD()        asm volatile("tcgen05.wait::ld.sync.aligned;" ::: "memory")
#define TC_WST()        asm volatile("tcgen05.wait::st.sync.aligned;" ::: "memory")
#define MB_INIT(mb, c)  asm volatile("mbarrier.init.shared.b64 [%0], %1;" :: "r"(mb), "r"((uint32_t)(c)) : "memory")
#define MB_WAIT(mb, ph) do { \
    uint32_t _m = (mb), _p = (ph), _d; \
    asm volatile("{\n\t.reg .pred p;\n\tmbarrier.try_wait.parity.acquire.cta.shared::cta.b64 p, [%1], %2;\n\tselp.b32 %0, 1, 0, p;\n\t}" \
        : "=r"(_d) : "r"(_m), "r"(_p) : "memory"); \
    if (!_d) { \
        asm volatile("{\n\t.reg .pred P1;\n\tWL_%=:\n\tmbarrier.try_wait.parity.acquire.cta.shared::cta.b64 P1, [%0], %1, 0x989680;\n\t@P1 bra.uni WD_%=;\n\tbra.uni WL_%=;\n\tWD_%=:\n\t}" \
            :: "r"(_m), "r"(_p) : "memory"); } \
} while (0)
#define TC_LD_X32(r, tm) \
    asm volatile("tcgen05.ld.sync.aligned.32x32b.x32.b32 " \
        "{%0,%1,%2,%3,%4,%5,%6,%7,%8,%9,%10,%11,%12,%13,%14,%15," \
        "%16,%17,%18,%19,%20,%21,%22,%23,%24,%25,%26,%27,%28,%29,%30,%31}, [%32];" \
        : "=r"((r)[0]),"=r"((r)[1]),"=r"((r)[2]),"=r"((r)[3]),"=r"((r)[4]),"=r"((r)[5]),"=r"((r)[6]),"=r"((r)[7]), \
          "=r"((r)[8]),"=r"((r)[9]),"=r"((r)[10]),"=r"((r)[11]),"=r"((r)[12]),"=r"((r)[13]),"=r"((r)[14]),"=r"((r)[15]), \
          "=r"((r)[16]),"=r"((r)[17]),"=r"((r)[18]),"=r"((r)[19]),"=r"((r)[20]),"=r"((r)[21]),"=r"((r)[22]),"=r"((r)[23]), \
          "=r"((r)[24]),"=r"((r)[25]),"=r"((r)[26]),"=r"((r)[27]),"=r"((r)[28]),"=r"((r)[29]),"=r"((r)[30]),"=r"((r)[31]) \
        : "r"(tm))
#define TC_ST_X32(tm, r) \
    asm volatile("tcgen05.st.sync.aligned.32x32b.x32.b32 [%0], " \
        "{%1,%2,%3,%4,%5,%6,%7,%8,%9,%10,%11,%12,%13,%14,%15,%16," \
        "%17,%18,%19,%20,%21,%22,%23,%24,%25,%26,%27,%28,%29,%30,%31,%32};" \
        :: "r"(tm), \
           "r"((r)[0]),"r"((r)[1]),"r"((r)[2]),"r"((r)[3]),"r"((r)[4]),"r"((r)[5]),"r"((r)[6]),"r"((r)[7]), \
           "r"((r)[8]),"r"((r)[9]),"r"((r)[10]),"r"((r)[11]),"r"((r)[12]),"r"((r)[13]),"r"((r)[14]),"r"((r)[15]), \
           "r"((r)[16]),"r"((r)[17]),"r"((r)[18]),"r"((r)[19]),"r"((r)[20]),"r"((r)[21]),"r"((r)[22]),"r"((r)[23]), \
           "r"((r)[24]),"r"((r)[25]),"r"((r)[26]),"r"((r)[27]),"r"((r)[28]),"r"((r)[29]),"r"((r)[30]),"r"((r)[31]) \
        : "memory")
#define TC_ST_X16(tm, r) \
    asm volatile("tcgen05.st.sync.aligned.32x32b.x16.b32 [%0], " \
        "{%1,%2,%3,%4,%5,%6,%7,%8,%9,%10,%11,%12,%13,%14,%15,%16};" \
        :: "r"(tm), \
           "r"((r)[0]),"r"((r)[1]),"r"((r)[2]),"r"((r)[3]),"r"((r)[4]),"r"((r)[5]),"r"((r)[6]),"r"((r)[7]), \
           "r"((r)[8]),"r"((r)[9]),"r"((r)[10]),"r"((r)[11]),"r"((r)[12]),"r"((r)[13]),"r"((r)[14]),"r"((r)[15]) \
        : "memory")

#define SWZ(b) ((b) ^ (((b) >> 3) & 0x70))
// B (weights in smem, 64 N-rows, K-major, SW128 blocked atoms): n row, k element
#define OFFB(n, k) ((uint32_t)(((uint32_t)((k) >> 6) * 8u + ((uint32_t)(n) >> 3)) * 1024u + SWZ((uint32_t)((((n) & 7) * 128) + ((k) & 63) * 2))))

static __device__ __forceinline__ u64 mkdesc(uint32_t a) {
    return (2ULL << 61) | (1ULL << 46) | (64ULL << 32) | (1ULL << 16) | ((u64)(a >> 4) & 0x3FFF);
}
#define IDESC 0x8100490u  // f32 accum, bf16 x bf16, K-major, M=128, N=64
__device__ __forceinline__ void mma_ts(uint32_t d, uint32_t a, u64 bd, uint32_t en) {
    asm volatile("{\n\t.reg .pred p;\n\tsetp.ne.u32 p, %5, 0;\n\t"
                 "tcgen05.mma.cta_group::1.kind::f16 [%0], [%1], %2, %3, {%4, %4, %4, %4}, p;\n\t}"
                 :: "r"(d), "r"(a), "l"(bd), "r"(IDESC), "r"(0u), "r"(en) : "memory");
}
// 3-pass split-bf16: D = Ah*Bh + Al*Bh + Ah*Bl  (nks K=16 steps per pass)
__device__ __forceinline__ void mma_layer_ts(uint32_t d, uint32_t ahi, uint32_t alo,
                                             u64 bh, u64 bl, int nks, uint32_t en0) {
#pragma unroll
    for (int p = 0; p < 3; p++) {
        uint32_t A = (p == 1) ? alo : ahi;
        u64 B = (p == 2) ? bl : bh;
        for (int ks = 0; ks < nks; ks++)
            mma_ts(d, A + ks * 8, B + (ks >> 2) * 512 + (ks & 3) * 2,
                   (p | ks) ? 1u : en0);
    }
}
__device__ __forceinline__ void split2(float a, float b, uint32_t& hi, uint32_t& lo) {
    __nv_bfloat162 h = __floats2bfloat162_rn(a, b);
    float2 hf = __bfloat1622float2(h);
    __nv_bfloat162 l = __floats2bfloat162_rn(a - hf.x, b - hf.y);
    hi = *(uint32_t*)&h;
    lo = *(uint32_t*)&l;
}
__device__ __forceinline__ void store_wsplit(char* smc, int oh, int ol, uint32_t off, float v) {
    __nv_bfloat16 h = __float2bfloat16(v);
    __nv_bfloat16 l = __float2bfloat16(v - __bfloat162float(h));
    *(unsigned short*)(smc + oh + off) = __bfloat16_as_ushort(h);
    *(unsigned short*)(smc + ol + off) = __bfloat16_as_ushort(l);
}
// load a fp32 row of 64 (16 float4) and split-store into TMEM cols [0,32) hi/lo
__device__ __forceinline__ void stage_row64(const float4* src, uint32_t tm_hi, uint32_t tm_lo) {
    float4 v[16];
#pragma unroll
    for (int j = 0; j < 16; j++) v[j] = src[j];
    uint32_t hi[32], lo[32];
#pragma unroll
    for (int j = 0; j < 16; j++) {
        split2(v[j].x, v[j].y, hi[2 * j], lo[2 * j]);
        split2(v[j].z, v[j].w, hi[2 * j + 1], lo[2 * j + 1]);
    }
    TC_ST_X32(tm_hi, hi);
    TC_ST_X32(tm_lo, lo);
}
#endif  // TC_PATH

// ===================== small kernels =====================
__global__ void zero_agg_kernel() {
    int i = blockIdx.x * blockDim.x + threadIdx.x;
    float4* p = (float4*)g_agg;
    for (; i < NN * 16; i += gridDim.x * blockDim.x) p[i] = make_float4(0.f, 0.f, 0.f, 0.f);
}

// ===================== pre kernel: Xsr = [x@We1_s | x@We1_r + be1] =====================
#define P_TP 0
#define P_MB 16
#define P_B1 64
#define P_WSH 1024
#define P_WSL 9216
#define P_WRH 17408
#define P_WRL 25600
#define P_SZ  33792
#define P_AHI 0
#define P_ALO 32
#define P_D0  64
#define P_D1  128

__global__ __launch_bounds__(256, 2)
void pre_mma_kernel(const float* __restrict__ x,
                    const float* __restrict__ We1, const float* __restrict__ be1) {
    extern __shared__ char smc[];
    const int tid = threadIdx.x;
#if TC_PATH
    const uint32_t sb = smem_u32(smc);
    const int wid = tid >> 5, lane = tid & 31;
    if (wid == 0) { TC_ALLOC(sb + P_TP, 256); TC_RELINQ(); }
    if (tid == 0) MB_INIT(sb + P_MB, 1);
    float* b1s = (float*)(smc + P_B1);
    if (tid < 64) b1s[tid] = be1[tid];
    for (int i = tid; i < 4096; i += 256) {
        int k = i >> 6, n = i & 63;
        uint32_t o = OFFB(n, k);
        store_wsplit(smc, P_WSH, P_WSL, o, We1[(64 + k) * 64 + n]);
        store_wsplit(smc, P_WRH, P_WRL, o, We1[(128 + k) * 64 + n]);
    }
    __syncthreads();
    uint32_t tmem;
    asm volatile("ld.shared.b32 %0, [%1];" : "=r"(tmem) : "r"(sb + P_TP));
    const u64 dWsh = mkdesc(sb + P_WSH), dWsl = mkdesc(sb + P_WSL);
    const u64 dWrh = mkdesc(sb + P_WRH), dWrl = mkdesc(sb + P_WRL);
    uint32_t ph = 0;
    const int blk = wid & 3;
    const uint32_t rowoff = (uint32_t)blk << 21;
    const int row = blk * 32 + lane;
    const int c0 = (wid >= 4) ? 32 : 0;
    uint32_t d[32];
    const int NT = (NN + 127) / 128;
    const float4* x4 = (const float4*)x;
    float4 zero4 = make_float4(0.f, 0.f, 0.f, 0.f);

    for (int tile = blockIdx.x; tile < NT; tile += gridDim.x) {
        const int base = tile * 128;
        const int n = base + row;
        {
            float4 v[16];
            if (n < NN) {
#pragma unroll
                for (int j = 0; j < 16; j++) v[j] = x4[(size_t)n * 16 + j];
            } else {
#pragma unroll
                for (int j = 0; j < 16; j++) v[j] = zero4;
            }
            uint32_t hi[32], lo[32];
#pragma unroll
            for (int j = 0; j < 16; j++) {
                split2(v[j].x, v[j].y, hi[2 * j], lo[2 * j]);
                split2(v[j].z, v[j].w, hi[2 * j + 1], lo[2 * j + 1]);
            }
            if (wid < 4) TC_ST_X32(tmem + P_AHI + rowoff, hi);
            else         TC_ST_X32(tmem + P_ALO + rowoff, lo);
        }
        TC_WST(); TC_FB();
        __syncthreads();
        if (wid == 0 && elect1()) {
            TC_FA();
            mma_layer_ts(tmem + P_D0, tmem + P_AHI, tmem + P_ALO, dWsh, dWsl, 4, 0u);
            mma_layer_ts(tmem + P_D1, tmem + P_AHI, tmem + P_ALO, dWrh, dWrl, 4, 0u);
            TC_COMMIT(sb + P_MB);
        }
        MB_WAIT(sb + P_MB, ph); ph ^= 1;
        TC_FA();
        if (n < NN) {
            TC_LD_X32(d, tmem + P_D0 + c0);
            TC_WLD();
#pragma unroll
            for (int j = 0; j < 8; j++)
                *(float4*)&g_Xsr[(size_t)n * 128 + c0 + 4 * j] =
                    make_float4(__uint_as_float(d[4 * j]), __uint_as_float(d[4 * j + 1]),
                                __uint_as_float(d[4 * j + 2]), __uint_as_float(d[4 * j + 3]));
            TC_LD_X32(d, tmem + P_D1 + c0);
            TC_WLD();
#pragma unroll
            for (int j = 0; j < 8; j++)
                *(float4*)&g_Xsr[(size_t)n * 128 + 64 + c0 + 4 * j] =
                    make_float4(__uint_as_float(d[4 * j]) + b1s[c0 + 4 * j],
                                __uint_as_float(d[4 * j + 1]) + b1s[c0 + 4 * j + 1],
                                __uint_as_float(d[4 * j + 2]) + b1s[c0 + 4 * j + 2],
                                __uint_as_float(d[4 * j + 3]) + b1s[c0 + 4 * j + 3]);
        } else {
            TC_LD_X32(d, tmem + P_D0 + c0); TC_WLD();
            TC_LD_X32(d, tmem + P_D1 + c0); TC_WLD();
        }
        TC_FB();
        __syncthreads();
    }
    if (wid == 0) TC_DEALLOC(tmem, 256);
#else
    for (int i = blockIdx.x * blockDim.x + tid; i < NN; i += gridDim.x * blockDim.x)
        for (int j = 0; j < 64; j++) {
            float s = 0.f, r = be1[j];
            for (int k = 0; k < 64; k++) {
                s += x[(size_t)i * 64 + k] * We1[(64 + k) * 64 + j];
                r += x[(size_t)i * 64 + k] * We1[(128 + k) * 64 + j];
            }
            g_Xsr[(size_t)i * 128 + j] = s;
            g_Xsr[(size_t)i * 128 + 64 + j] = r;
        }
#endif
}

// ===================== edge kernel: two-tile ping-pong =====================
#define E_TP  0
#define E_MB0 16
#define E_MB1 24
#define E_B2  64
#define E_B3  320
#define E_SS  576      // 256 ints
#define E_TT  1600     // 256 ints
#define E_W1H 3072
#define E_W1L 11264
#define E_W2H 19456
#define E_W2L 27648
#define E_W3H 35840
#define E_W3L 44032
#define E_BX  52224    // 128 x 68 floats = 34816 B
#define E_SZ  87040
// TMEM (256 cols/CTA): T0: AHI[0,32) ALO[32,64) D[64,128); T1: +128
#define T0_AHI 0
#define T0_ALO 32
#define T0_D   64
#define T1_AHI 128
#define T1_ALO 160
#define T1_D   192

__global__ __launch_bounds__(256, 2)
void edge_mma_kernel(const float* __restrict__ x,
                     const float* __restrict__ e,
                     const int* __restrict__ senders,
                     const int* __restrict__ receivers,
                     const float* __restrict__ We1, const float* __restrict__ be1,
                     const float* __restrict__ We2, const float* __restrict__ be2,
                     const float* __restrict__ We3, const float* __restrict__ be3) {
    extern __shared__ char smc[];
    const int tid = threadIdx.x;
#if TC_PATH
    const uint32_t sb = smem_u32(smc);
    const int wid = tid >> 5, lane = tid & 31;
    if (wid == 0) { TC_ALLOC(sb + E_TP, 256); TC_RELINQ(); }
    if (tid == 0) { MB_INIT(sb + E_MB0, 1); MB_INIT(sb + E_MB1, 1); }
    float* b2s = (float*)(smc + E_B2);
    float* b3s = (float*)(smc + E_B3);
    int* ss = (int*)(smc + E_SS);
    int* tt = (int*)(smc + E_TT);
    float* Bx = (float*)(smc + E_BX);    // 128 rows x 68 stride (single buffer)
    if (tid < 64) { b2s[tid] = be2[tid]; b3s[tid] = be3[tid]; }
    for (int i = tid; i < 4096; i += 256) {
        int k = i >> 6, n = i & 63;
        uint32_t o = OFFB(n, k);
        store_wsplit(smc, E_W1H, E_W1L, o, We1[k * 64 + n]);   // e-part rows [0,64)
        store_wsplit(smc, E_W2H, E_W2L, o, We2[i]);
        store_wsplit(smc, E_W3H, E_W3L, o, We3[i]);
    }
    __syncthreads();
    uint32_t tmem;
    asm volatile("ld.shared.b32 %0, [%1];" : "=r"(tmem) : "r"(sb + E_TP));
    const u64 dW1h = mkdesc(sb + E_W1H), dW1l = mkdesc(sb + E_W1L);
    const u64 dW2h = mkdesc(sb + E_W2H), dW2l = mkdesc(sb + E_W2L);
    const u64 dW3h = mkdesc(sb + E_W3H), dW3l = mkdesc(sb + E_W3L);
    const float4* e4 = (const float4*)e;
    const float4* Xsr4 = (const float4*)g_Xsr;
    uint32_t ph0 = 0, ph1 = 0;
    const int blk = wid & 3;
    const uint32_t rowoff = (uint32_t)blk << 21;
    const int row = blk * 32 + lane;
    const int c0 = (wid >= 4) ? 32 : 0;
    uint32_t d[32];
    const int NT2 = NE / 256;

    for (int tile = blockIdx.x; tile < NT2; tile += gridDim.x) {
        const int base = tile * 256;
        ss[tid] = senders[base + tid];
        tt[tid] = receivers[base + tid];
        __syncthreads();
        // ---- stage T0: warps 0-3 e rows -> TMEM, warps 4-7 gather Bx(T0) ----
        if (wid < 4) {
            stage_row64(&e4[(size_t)(base + row) * 16],
                        tmem + T0_AHI + rowoff, tmem + T0_ALO + rowoff);
            TC_WST(); TC_FB();
        } else {
            const int g = tid - 128;
            const int s = ss[g], t = tt[g];
            const float4* ps = &Xsr4[(size_t)s * 32];
            const float4* pt = &Xsr4[(size_t)t * 32 + 16];
            float4* pb = (float4*)&Bx[g * 68];
#pragma unroll
            for (int j = 0; j < 16; j++) {
                float4 a = ps[j], b = pt[j];
                pb[j] = make_float4(a.x + b.x, a.y + b.y, a.z + b.z, a.w + b.w);
            }
        }
        __syncthreads();
        // issue M1(T0); meanwhile warps 4-7 stage T1 e rows
        if (wid == 0 && elect1()) {
            TC_FA();
            mma_layer_ts(tmem + T0_D, tmem + T0_AHI, tmem + T0_ALO, dW1h, dW1l, 4, 0u);
            TC_COMMIT(sb + E_MB0);
        }
        if (wid >= 4) {
            stage_row64(&e4[(size_t)(base + 128 + row) * 16],
                        tmem + T1_AHI + rowoff, tmem + T1_ALO + rowoff);
            TC_WST(); TC_FB();
        }
        __syncthreads();
        // issue M1(T1)
        if (wid == 0 && elect1()) {
            TC_FA();
            mma_layer_ts(tmem + T1_D, tmem + T1_AHI, tmem + T1_ALO, dW1h, dW1l, 4, 0u);
            TC_COMMIT(sb + E_MB1);
        }
        // ---- epi1(T0): relu(D0 + Bx) -> A0 ----
        MB_WAIT(sb + E_MB0, ph0); ph0 ^= 1;
        TC_FA();
        TC_LD_X32(d, tmem + T0_D + c0);
        TC_WLD();
        {
            uint32_t hi[16], lo[16];
            const float* bx = &Bx[row * 68 + c0];
#pragma unroll
            for (int j = 0; j < 16; j++) {
                float a = fmaxf(__uint_as_float(d[2 * j])     + bx[2 * j], 0.f);
                float b = fmaxf(__uint_as_float(d[2 * j + 1]) + bx[2 * j + 1], 0.f);
                split2(a, b, hi[j], lo[j]);
            }
            TC_ST_X16(tmem + T0_AHI + (c0 >> 1) + rowoff, hi);
            TC_ST_X16(tmem + T0_ALO + (c0 >> 1) + rowoff, lo);
            TC_WST();
        }
        TC_FB();
        __syncthreads();
        // issue M2(T0); warps 4-7 regather Bx for T1 (buffer now free)
        if (wid == 0 && elect1()) {
            TC_FA();
            mma_layer_ts(tmem + T0_D, tmem + T0_AHI, tmem + T0_ALO, dW2h, dW2l, 4, 0u);
            TC_COMMIT(sb + E_MB0);
        }
        if (wid >= 4) {
            const int g = tid - 128;
            const int s = ss[128 + g], t = tt[128 + g];
            const float4* ps = &Xsr4[(size_t)s * 32];
            const float4* pt = &Xsr4[(size_t)t * 32 + 16];
            float4* pb = (float4*)&Bx[g * 68];
#pragma unroll
            for (int j = 0; j < 16; j++) {
                float4 a = ps[j], b = pt[j];
                pb[j] = make_float4(a.x + b.x, a.y + b.y, a.z + b.z, a.w + b.w);
            }
        }
        __syncthreads();
        // ---- epi1(T1) ----
        MB_WAIT(sb + E_MB1, ph1); ph1 ^= 1;
        TC_FA();
        TC_LD_X32(d, tmem + T1_D + c0);
        TC_WLD();
        {
            uint32_t hi[16], lo[16];
            const float* bx = &Bx[row * 68 + c0];
#pragma unroll
            for (int j = 0; j < 16; j++) {
                float a = fmaxf(__uint_as_float(d[2 * j])     + bx[2 * j], 0.f);
                float b = fmaxf(__uint_as_float(d[2 * j + 1]) + bx[2 * j + 1], 0.f);
                split2(a, b, hi[j], lo[j]);
            }
            TC_ST_X16(tmem + T1_AHI + (c0 >> 1) + rowoff, hi);
            TC_ST_X16(tmem + T1_ALO + (c0 >> 1) + rowoff, lo);
            TC_WST();
        }
        TC_FB();
        __syncthreads();
        if (wid == 0 && elect1()) {
            TC_FA();
            mma_layer_ts(tmem + T1_D, tmem + T1_AHI, tmem + T1_ALO, dW2h, dW2l, 4, 0u);
            TC_COMMIT(sb + E_MB1);
        }
        // ---- epi2(T0) ----
        MB_WAIT(sb + E_MB0, ph0); ph0 ^= 1;
        TC_FA();
        TC_LD_X32(d, tmem + T0_D + c0);
        TC_WLD();
        {
            uint32_t hi[16], lo[16];
#pragma unroll
            for (int j = 0; j < 16; j++) {
                float a = fmaxf(__uint_as_float(d[2 * j])     + b2s[c0 + 2 * j], 0.f);
                float b = fmaxf(__uint_as_float(d[2 * j + 1]) + b2s[c0 + 2 * j + 1], 0.f);
                split2(a, b, hi[j], lo[j]);
            }
            TC_ST_X16(tmem + T0_AHI + (c0 >> 1) + rowoff, hi);
            TC_ST_X16(tmem + T0_ALO + (c0 >> 1) + rowoff, lo);
            TC_WST();
        }
        TC_FB();
        __syncthreads();
        if (wid == 0 && elect1()) {
            TC_FA();
            mma_layer_ts(tmem + T0_D, tmem + T0_AHI, tmem + T0_ALO, dW3h, dW3l, 4, 0u);
            TC_COMMIT(sb + E_MB0);
        }
        // ---- epi2(T1) ----
        MB_WAIT(sb + E_MB1, ph1); ph1 ^= 1;
        TC_FA();
        TC_LD_X32(d, tmem + T1_D + c0);
        TC_WLD();
        {
            uint32_t hi[16], lo[16];
#pragma unroll
            for (int j = 0; j < 16; j++) {
                float a = fmaxf(__uint_as_float(d[2 * j])     + b2s[c0 + 2 * j], 0.f);
                float b = fmaxf(__uint_as_float(d[2 * j + 1]) + b2s[c0 + 2 * j + 1], 0.f);
                split2(a, b, hi[j], lo[j]);
            }
            TC_ST_X16(tmem + T1_AHI + (c0 >> 1) + rowoff, hi);
            TC_ST_X16(tmem + T1_ALO + (c0 >> 1) + rowoff, lo);
            TC_WST();
        }
        TC_FB();
        __syncthreads();
        if (wid == 0 && elect1()) {
            TC_FA();
            mma_layer_ts(tmem + T1_D, tmem + T1_AHI, tmem + T1_ALO, dW3h, dW3l, 4, 0u);
            TC_COMMIT(sb + E_MB1);
        }
        // ---- epi3(T0): segment sum ----
        MB_WAIT(sb + E_MB0, ph0); ph0 ^= 1;
        TC_FA();
        TC_LD_X32(d, tmem + T0_D + c0);
        TC_WLD(); TC_FB();
        {
            float* p = &g_agg[(size_t)tt[row] * 64 + c0];
#pragma unroll
            for (int jj = 0; jj < 4; jj++) {
                float v[8];
#pragma unroll
                for (int j = 0; j < 8; j++)
                    v[j] = __uint_as_float(d[jj * 8 + j]) + b3s[c0 + jj * 8 + j];
                red_add_v4(p + jj * 8, v[0], v[1], v[2], v[3]);
                red_add_v4(p + jj * 8 + 4, v[4], v[5], v[6], v[7]);
            }
        }
        // ---- epi3(T1): segment sum ----
        MB_WAIT(sb + E_MB1, ph1); ph1 ^= 1;
        TC_FA();
        TC_LD_X32(d, tmem + T1_D + c0);
        TC_WLD(); TC_FB();
        {
            float* p = &g_agg[(size_t)tt[128 + row] * 64 + c0];
#pragma unroll
            for (int jj = 0; jj < 4; jj++) {
                float v[8];
#pragma unroll
                for (int j = 0; j < 8; j++)
                    v[j] = __uint_as_float(d[jj * 8 + j]) + b3s[c0 + jj * 8 + j];
                red_add_v4(p + jj * 8, v[0], v[1], v[2], v[3]);
                red_add_v4(p + jj * 8 + 4, v[4], v[5], v[6], v[7]);
            }
        }
        __syncthreads();   // protect ss/tt/Bx before next iteration
    }
    if (wid == 0) TC_DEALLOC(tmem, 256);
#else
    // naive correct fallback (compiled for non-sm_103a passes only)
    for (int i = blockIdx.x * blockDim.x + tid; i < NE; i += gridDim.x * blockDim.x) {
        int s = senders[i], t = receivers[i];
        float h1[64], h2[64];
        for (int j = 0; j < 64; j++) {
            float a = be1[j];
            for (int k = 0; k < 64; k++) a += e[(size_t)i * 64 + k] * We1[k * 64 + j];
            for (int k = 0; k < 64; k++) a += x[(size_t)s * 64 + k] * We1[(64 + k) * 64 + j];
            for (int k = 0; k < 64; k++) a += x[(size_t)t * 64 + k] * We1[(128 + k) * 64 + j];
            h1[j] = fmaxf(a, 0.f);
        }
        for (int j = 0; j < 64; j++) {
            float a = be2[j];
            for (int k = 0; k < 64; k++) a += h1[k] * We2[k * 64 + j];
            h2[j] = fmaxf(a, 0.f);
        }
        for (int j = 0; j < 64; j++) {
            float a = be3[j];
            for (int k = 0; k < 64; k++) a += h2[k] * We3[k * 64 + j];
            atomicAdd(&g_agg[(size_t)t * 64 + j], a);
        }
    }
#endif
}

// ===================== node kernel =====================
#define N_TP 0
#define N_MB 16
#define N_B1 64
#define N_B2 320
#define N_B3 576
#define N_W1H 1024
#define N_W1L 17408
#define N_W2H 33792
#define N_W2L 41984
#define N_W3H 50176
#define N_W3L 58368
#define N_SZ 66560
#define N_AHI 0
#define N_ALO 64
#define N_D   128

__global__ __launch_bounds__(256, 2)
void node_mma_kernel(const float* __restrict__ x,
                     const float* __restrict__ Wn1, const float* __restrict__ bn1,
                     const float* __restrict__ Wn2, const float* __restrict__ bn2,
                     const float* __restrict__ Wn3, const float* __restrict__ bn3,
                     float* __restrict__ out) {
    extern __shared__ char smc[];
    const int tid = threadIdx.x;
#if TC_PATH
    const uint32_t sb = smem_u32(smc);
    const int wid = tid >> 5, lane = tid & 31;
    if (wid == 0) { TC_ALLOC(sb + N_TP, 256); TC_RELINQ(); }
    if (tid == 0) MB_INIT(sb + N_MB, 1);
    float* b1s = (float*)(smc + N_B1);
    float* b2s = (float*)(smc + N_B2);
    float* b3s = (float*)(smc + N_B3);
    if (tid < 64) { b1s[tid] = bn1[tid]; b2s[tid] = bn2[tid]; b3s[tid] = bn3[tid]; }
    for (int i = tid; i < 8192; i += 256) {
        int k = i >> 6, n = i & 63;
        store_wsplit(smc, N_W1H, N_W1L, OFFB(n, k), Wn1[i]);
    }
    for (int i = tid; i < 4096; i += 256) {
        int k = i >> 6, n = i & 63;
        uint32_t o = OFFB(n, k);
        store_wsplit(smc, N_W2H, N_W2L, o, Wn2[i]);
        store_wsplit(smc, N_W3H, N_W3L, o, Wn3[i]);
    }
    __syncthreads();
    uint32_t tmem;
    asm volatile("ld.shared.b32 %0, [%1];" : "=r"(tmem) : "r"(sb + N_TP));
    const u64 dW1h = mkdesc(sb + N_W1H), dW1l = mkdesc(sb + N_W1L);
    const u64 dW2h = mkdesc(sb + N_W2H), dW2l = mkdesc(sb + N_W2L);
    const u64 dW3h = mkdesc(sb + N_W3H), dW3l = mkdesc(sb + N_W3L);
    const float4* x4 = (const float4*)x;
    const float4* ag4 = (const float4*)g_agg;
    uint32_t ph = 0;
    const int blk = wid & 3;
    const uint32_t rowoff = (uint32_t)blk << 21;
    const int row = blk * 32 + lane;
    const int c0 = (wid >= 4) ? 32 : 0;
    uint32_t d[32];
    const int NT = (NN + 127) / 128;
    float4 zero4 = make_float4(0.f, 0.f, 0.f, 0.f);

    for (int tile = blockIdx.x; tile < NT; tile += gridDim.x) {
        const int base = tile * 128;
        const int n = base + row;
        {
            const float4* src = (wid < 4) ? &x4[(size_t)n * 16] : &ag4[(size_t)n * 16];
            float4 v[16];
            if (n < NN) {
#pragma unroll
                for (int j = 0; j < 16; j++) v[j] = src[j];
            } else {
#pragma unroll
                for (int j = 0; j < 16; j++) v[j] = zero4;
            }
            uint32_t hi[32], lo[32];
#pragma unroll
            for (int j = 0; j < 16; j++) {
                split2(v[j].x, v[j].y, hi[2 * j], lo[2 * j]);
                split2(v[j].z, v[j].w, hi[2 * j + 1], lo[2 * j + 1]);
            }
            uint32_t off = (wid < 4) ? 0u : 32u;
            TC_ST_X32(tmem + N_AHI + off + rowoff, hi);
            TC_ST_X32(tmem + N_ALO + off + rowoff, lo);
        }
        TC_WST(); TC_FB();
        __syncthreads();
        if (wid == 0 && elect1()) {
            TC_FA();
            mma_layer_ts(tmem + N_D, tmem + N_AHI, tmem + N_ALO, dW1h, dW1l, 8, 0u);
            TC_COMMIT(sb + N_MB);
        }
        MB_WAIT(sb + N_MB, ph); ph ^= 1;
        TC_FA();
        TC_LD_X32(d, tmem + N_D + c0);
        TC_WLD();
        {
            uint32_t hi[16], lo[16];
#pragma unroll
            for (int j = 0; j < 16; j++) {
                float a = fmaxf(__uint_as_float(d[2 * j])     + b1s[c0 + 2 * j], 0.f);
                float b = fmaxf(__uint_as_float(d[2 * j + 1]) + b1s[c0 + 2 * j + 1], 0.f);
                split2(a, b, hi[j], lo[j]);
            }
            TC_ST_X16(tmem + N_AHI + (c0 >> 1) + rowoff, hi);
            TC_ST_X16(tmem + N_ALO + (c0 >> 1) + rowoff, lo);
            TC_WST();
        }
        TC_FB();
        __syncthreads();
        if (wid == 0 && elect1()) {
            TC_FA();
            mma_layer_ts(tmem + N_D, tmem + N_AHI, tmem + N_ALO, dW2h, dW2l, 4, 0u);
            TC_COMMIT(sb + N_MB);
        }
        MB_WAIT(sb + N_MB, ph); ph ^= 1;
        TC_FA();
        TC_LD_X32(d, tmem + N_D + c0);
        TC_WLD();
        {
            uint32_t hi[16], lo[16];
#pragma unroll
            for (int j = 0; j < 16; j++) {
                float a = fmaxf(__uint_as_float(d[2 * j])     + b2s[c0 + 2 * j], 0.f);
                float b = fmaxf(__uint_as_float(d[2 * j + 1]) + b2s[c0 + 2 * j + 1], 0.f);
                split2(a, b, hi[j], lo[j]);
            }
            TC_ST_X16(tmem + N_AHI + (c0 >> 1) + rowoff, hi);
            TC_ST_X16(tmem + N_ALO + (c0 >> 1) + rowoff, lo);
            TC_WST();
        }
        TC_FB();
        __syncthreads();
        if (wid == 0 && elect1()) {
            TC_FA();
            mma_layer_ts(tmem + N_D, tmem + N_AHI, tmem + N_ALO, dW3h, dW3l, 4, 0u);
            TC_COMMIT(sb + N_MB);
        }
        MB_WAIT(sb + N_MB, ph); ph ^= 1;
        TC_FA();
        TC_LD_X32(d, tmem + N_D + c0);
        TC_WLD(); TC_FB();
        if (n < NN) {
#pragma unroll
            for (int jj = 0; jj < 4; jj++) {
                float v[8];
#pragma unroll
                for (int j = 0; j < 8; j++)
                    v[j] = __uint_as_float(d[jj * 8 + j]) + b3s[c0 + jj * 8 + j];
                *(float4*)&out[(size_t)n * 64 + c0 + jj * 8]     = make_float4(v[0], v[1], v[2], v[3]);
                *(float4*)&out[(size_t)n * 64 + c0 + jj * 8 + 4] = make_float4(v[4], v[5], v[6], v[7]);
            }
        }
        __syncthreads();
    }
    if (wid == 0) TC_DEALLOC(tmem, 256);
#else
    for (int i = blockIdx.x * blockDim.x + tid; i < NN; i += gridDim.x * blockDim.x) {
        float h1[64], h2[64];
        for (int j = 0; j < 64; j++) {
            float a = bn1[j];
            for (int k = 0; k < 64; k++) a += x[(size_t)i * 64 + k] * Wn1[k * 64 + j];
            for (int k = 0; k < 64; k++) a += g_agg[(size_t)i * 64 + k] * Wn1[(64 + k) * 64 + j];
            h1[j] = fmaxf(a, 0.f);
        }
        for (int j = 0; j < 64; j++) {
            float a = bn2[j];
            for (int k = 0; k < 64; k++) a += h1[k] * Wn2[k * 64 + j];
            h2[j] = fmaxf(a, 0.f);
        }
        for (int j = 0; j < 64; j++) {
            float a = bn3[j];
            for (int k = 0; k < 64; k++) a += h2[k] * Wn3[k * 64 + j];
            out[(size_t)i * 64 + j] = a;
        }
    }
#endif
}

// ===================== launch =====================
extern "C" void kernel_launch(void* const* d_in, const int* in_sizes, int n_in,
                              void* d_out, int out_size) {
    const float* x         = (const float*)d_in[0];
    const float* e         = (const float*)d_in[1];
    const int*   senders   = (const int*)d_in[2];
    const int*   receivers = (const int*)d_in[3];
    const float* We1 = (const float*)d_in[4];
    const float* be1 = (const float*)d_in[5];
    const float* We2 = (const float*)d_in[6];
    const float* be2 = (const float*)d_in[7];
    const float* We3 = (const float*)d_in[8];
    const float* be3 = (const float*)d_in[9];
    const float* Wn1 = (const float*)d_in[10];
    const float* bn1 = (const float*)d_in[11];
    const float* Wn2 = (const float*)d_in[12];
    const float* bn2 = (const float*)d_in[13];
    const float* Wn3 = (const float*)d_in[14];
    const float* bn3 = (const float*)d_in[15];
    float* out = (float*)d_out;

    cudaFuncSetAttribute(pre_mma_kernel,  cudaFuncAttributeMaxDynamicSharedMemorySize, P_SZ);
    cudaFuncSetAttribute(edge_mma_kernel, cudaFuncAttributeMaxDynamicSharedMemorySize, E_SZ);
    cudaFuncSetAttribute(node_mma_kernel, cudaFuncAttributeMaxDynamicSharedMemorySize, N_SZ);

    zero_agg_kernel<<<304, 256>>>();
    pre_mma_kernel<<<304, 256, P_SZ>>>(x, We1, be1);
    edge_mma_kernel<<<304, 256, E_SZ>>>(x, e, senders, receivers,
                                        We1, be1, We2, be2, We3, be3);
    node_mma_kernel<<<304, 256, N_SZ>>>(x, Wn1, bn1, Wn2, bn2, Wn3, bn3, out);
}

// round 10
// speedup vs baseline: 5.6165x; 1.1065x over previous
#include <cuda_runtime.h>
#include <cuda_bf16.h>
#include <cstdint>

#define NN 100000
#define NE 1600000
using u64 = unsigned long long;

#if !defined(__CUDA_ARCH__) || defined(__CUDA_ARCH_FEAT_SM103_ALL)
#define TC_PATH 1
#else
#define TC_PATH 0
#endif

// scratch (static device globals: allocation-free)
__device__ float g_agg[NN * 64];
__device__ float g_Xsr[NN * 128];   // [Xs(64) | Xr+be1(64)] per node

__device__ __forceinline__ void red_add_v4(float* a, float x, float y, float z, float w) {
    asm volatile("red.global.add.v4.f32 [%0], {%1, %2, %3, %4};"
                 :: "l"(a), "f"(x), "f"(y), "f"(z), "f"(w) : "memory");
}

#if TC_PATH
// ===================== tcgen05 machinery (sm_103a only) =====================
__device__ __forceinline__ uint32_t smem_u32(const void* p) {
    return (uint32_t)__cvta_generic_to_shared(p);
}
__device__ __forceinline__ bool elect1() {
    uint32_t pr;
    asm volatile("{\n\t.reg .pred p;\n\telect.sync _|p, 0xFFFFFFFF;\n\tselp.b32 %0, 1, 0, p;\n\t}" : "=r"(pr));
    return pr != 0;
}
#define TC_ALLOC(a, n)  asm volatile("tcgen05.alloc.cta_group::1.sync.aligned.shared::cta.b32 [%0], %1;" :: "r"(a), "r"((uint32_t)(n)) : "memory")
#define TC_RELINQ()     asm volatile("tcgen05.relinquish_alloc_permit.cta_group::1.sync.aligned;")
#define TC_DEALLOC(t, n) asm volatile("tcgen05.dealloc.cta_group::1.sync.aligned.b32 %0, %1;" :: "r"(t), "r"((uint32_t)(n)))
#define TC_COMMIT(mb)   asm volatile("tcgen05.commit.cta_group::1.mbarrier::arrive::one.shared::cluster.b64 [%0];" :: "r"(mb) : "memory")
#define TC_FA()         asm volatile("tcgen05.fence::after_thread_sync;" ::: "memory")
#define TC_FB()         asm volatile("tcgen05.fence::before_thread_sync;" ::: "memory")
#define TC_WLD()        asm volatile("tcgen05.wait::ld.sync.aligned;" ::: "memory")
#define TC_WST()        asm volatile("tcgen05.wait::st.sync.aligned;" ::: "memory")
#define MB_INIT(mb, c)  asm volatile("mbarrier.init.shared.b64 [%0], %1;" :: "r"(mb), "r"((uint32_t)(c)) : "memory")
#define MB_WAIT(mb, ph) do { \
    uint32_t _m = (mb), _p = (ph), _d; \
    asm volatile("{\n\t.reg .pred p;\n\tmbarrier.try_wait.parity.acquire.cta.shared::cta.b64 p, [%1], %2;\n\tselp.b32 %0, 1, 0, p;\n\t}" \
        : "=r"(_d) : "r"(_m), "r"(_p) : "memory"); \
    if (!_d) { \
        asm volatile("{\n\t.reg .pred P1;\n\tWL_%=:\n\tmbarrier.try_wait.parity.acquire.cta.shared::cta.b64 P1, [%0], %1, 0x989680;\n\t@P1 bra.uni WD_%=;\n\tbra.uni WL_%=;\n\tWD_%=:\n\t}" \
            :: "r"(_m), "r"(_p) : "memory"); } \
} while (0)
#define TC_LD_X32(r, tm) \
    asm volatile("tcgen05.ld.sync.aligned.32x32b.x32.b32 " \
        "{%0,%1,%2,%3,%4,%5,%6,%7,%8,%9,%10,%11,%12,%13,%14,%15," \
        "%16,%17,%18,%19,%20,%21,%22,%23,%24,%25,%26,%27,%28,%29,%30,%31}, [%32];" \
        : "=r"((r)[0]),"=r"((r)[1]),"=r"((r)[2]),"=r"((r)[3]),"=r"((r)[4]),"=r"((r)[5]),"=r"((r)[6]),"=r"((r)[7]), \
          "=r"((r)[8]),"=r"((r)[9]),"=r"((r)[10]),"=r"((r)[11]),"=r"((r)[12]),"=r"((r)[13]),"=r"((r)[14]),"=r"((r)[15]), \
          "=r"((r)[16]),"=r"((r)[17]),"=r"((r)[18]),"=r"((r)[19]),"=r"((r)[20]),"=r"((r)[21]),"=r"((r)[22]),"=r"((r)[23]), \
          "=r"((r)[24]),"=r"((r)[25]),"=r"((r)[26]),"=r"((r)[27]),"=r"((r)[28]),"=r"((r)[29]),"=r"((r)[30]),"=r"((r)[31]) \
        : "r"(tm))
#define TC_ST_X32(tm, r) \
    asm volatile("tcgen05.st.sync.aligned.32x32b.x32.b32 [%0], " \
        "{%1,%2,%3,%4,%5,%6,%7,%8,%9,%10,%11,%12,%13,%14,%15,%16," \
        "%17,%18,%19,%20,%21,%22,%23,%24,%25,%26,%27,%28,%29,%30,%31,%32};" \
        :: "r"(tm), \
           "r"((r)[0]),"r"((r)[1]),"r"((r)[2]),"r"((r)[3]),"r"((r)[4]),"r"((r)[5]),"r"((r)[6]),"r"((r)[7]), \
           "r"((r)[8]),"r"((r)[9]),"r"((r)[10]),"r"((r)[11]),"r"((r)[12]),"r"((r)[13]),"r"((r)[14]),"r"((r)[15]), \
           "r"((r)[16]),"r"((r)[17]),"r"((r)[18]),"r"((r)[19]),"r"((r)[20]),"r"((r)[21]),"r"((r)[22]),"r"((r)[23]), \
           "r"((r)[24]),"r"((r)[25]),"r"((r)[26]),"r"((r)[27]),"r"((r)[28]),"r"((r)[29]),"r"((r)[30]),"r"((r)[31]) \
        : "memory")
#define TC_ST_X16(tm, r) \
    asm volatile("tcgen05.st.sync.aligned.32x32b.x16.b32 [%0], " \
        "{%1,%2,%3,%4,%5,%6,%7,%8,%9,%10,%11,%12,%13,%14,%15,%16};" \
        :: "r"(tm), \
           "r"((r)[0]),"r"((r)[1]),"r"((r)[2]),"r"((r)[3]),"r"((r)[4]),"r"((r)[5]),"r"((r)[6]),"r"((r)[7]), \
           "r"((r)[8]),"r"((r)[9]),"r"((r)[10]),"r"((r)[11]),"r"((r)[12]),"r"((r)[13]),"r"((r)[14]),"r"((r)[15]) \
        : "memory")

#define SWZ(b) ((b) ^ (((b) >> 3) & 0x70))
// B (weights in smem, 64 N-rows, K-major, SW128 blocked atoms): n row, k element
#define OFFB(n, k) ((uint32_t)(((uint32_t)((k) >> 6) * 8u + ((uint32_t)(n) >> 3)) * 1024u + SWZ((uint32_t)((((n) & 7) * 128) + ((k) & 63) * 2))))

static __device__ __forceinline__ u64 mkdesc(uint32_t a) {
    return (2ULL << 61) | (1ULL << 46) | (64ULL << 32) | (1ULL << 16) | ((u64)(a >> 4) & 0x3FFF);
}
#define IDESC 0x8100490u  // f32 accum, bf16 x bf16, K-major, M=128, N=64
__device__ __forceinline__ void mma_ts(uint32_t d, uint32_t a, u64 bd, uint32_t en) {
    asm volatile("{\n\t.reg .pred p;\n\tsetp.ne.u32 p, %5, 0;\n\t"
                 "tcgen05.mma.cta_group::1.kind::f16 [%0], [%1], %2, %3, {%4, %4, %4, %4}, p;\n\t}"
                 :: "r"(d), "r"(a), "l"(bd), "r"(IDESC), "r"(0u), "r"(en) : "memory");
}
// 3-pass split-bf16: D = Ah*Bh + Al*Bh + Ah*Bl  (nks K=16 steps per pass)
__device__ __forceinline__ void mma_layer_ts(uint32_t d, uint32_t ahi, uint32_t alo,
                                             u64 bh, u64 bl, int nks, uint32_t en0) {
#pragma unroll
    for (int p = 0; p < 3; p++) {
        uint32_t A = (p == 1) ? alo : ahi;
        u64 B = (p == 2) ? bl : bh;
        for (int ks = 0; ks < nks; ks++)
            mma_ts(d, A + ks * 8, B + (ks >> 2) * 512 + (ks & 3) * 2,
                   (p | ks) ? 1u : en0);
    }
}
__device__ __forceinline__ void split2(float a, float b, uint32_t& hi, uint32_t& lo) {
    __nv_bfloat162 h = __floats2bfloat162_rn(a, b);
    float2 hf = __bfloat1622float2(h);
    __nv_bfloat162 l = __floats2bfloat162_rn(a - hf.x, b - hf.y);
    hi = *(uint32_t*)&h;
    lo = *(uint32_t*)&l;
}
__device__ __forceinline__ void store_wsplit(char* smc, int oh, int ol, uint32_t off, float v) {
    __nv_bfloat16 h = __float2bfloat16(v);
    __nv_bfloat16 l = __float2bfloat16(v - __bfloat162float(h));
    *(unsigned short*)(smc + oh + off) = __bfloat16_as_ushort(h);
    *(unsigned short*)(smc + ol + off) = __bfloat16_as_ushort(l);
}
// load a fp32 row of 64 (16 float4) and split-store into TMEM cols [0,32) hi/lo
__device__ __forceinline__ void stage_row64(const float4* src, uint32_t tm_hi, uint32_t tm_lo) {
    float4 v[16];
#pragma unroll
    for (int j = 0; j < 16; j++) v[j] = src[j];
    uint32_t hi[32], lo[32];
#pragma unroll
    for (int j = 0; j < 16; j++) {
        split2(v[j].x, v[j].y, hi[2 * j], lo[2 * j]);
        split2(v[j].z, v[j].w, hi[2 * j + 1], lo[2 * j + 1]);
    }
    TC_ST_X32(tm_hi, hi);
    TC_ST_X32(tm_lo, lo);
}
#endif  // TC_PATH

// ===================== small kernels =====================
__global__ void zero_agg_kernel() {
    int i = blockIdx.x * blockDim.x + threadIdx.x;
    float4* p = (float4*)g_agg;
    for (; i < NN * 16; i += gridDim.x * blockDim.x) p[i] = make_float4(0.f, 0.f, 0.f, 0.f);
}

// ===================== pre kernel: Xsr = [x@We1_s | x@We1_r + be1] =====================
#define P_TP 0
#define P_MB 16
#define P_B1 64
#define P_WSH 1024
#define P_WSL 9216
#define P_WRH 17408
#define P_WRL 25600
#define P_SZ  33792
#define P_AHI 0
#define P_ALO 32
#define P_D0  64
#define P_D1  128

__global__ __launch_bounds__(256, 2)
void pre_mma_kernel(const float* __restrict__ x,
                    const float* __restrict__ We1, const float* __restrict__ be1) {
    extern __shared__ char smc[];
    const int tid = threadIdx.x;
#if TC_PATH
    const uint32_t sb = smem_u32(smc);
    const int wid = tid >> 5, lane = tid & 31;
    if (wid == 0) { TC_ALLOC(sb + P_TP, 256); TC_RELINQ(); }
    if (tid == 0) MB_INIT(sb + P_MB, 1);
    float* b1s = (float*)(smc + P_B1);
    if (tid < 64) b1s[tid] = be1[tid];
    for (int i = tid; i < 4096; i += 256) {
        int k = i >> 6, n = i & 63;
        uint32_t o = OFFB(n, k);
        store_wsplit(smc, P_WSH, P_WSL, o, We1[(64 + k) * 64 + n]);
        store_wsplit(smc, P_WRH, P_WRL, o, We1[(128 + k) * 64 + n]);
    }
    __syncthreads();
    uint32_t tmem;
    asm volatile("ld.shared.b32 %0, [%1];" : "=r"(tmem) : "r"(sb + P_TP));
    const u64 dWsh = mkdesc(sb + P_WSH), dWsl = mkdesc(sb + P_WSL);
    const u64 dWrh = mkdesc(sb + P_WRH), dWrl = mkdesc(sb + P_WRL);
    uint32_t ph = 0;
    const int blk = wid & 3;
    const uint32_t rowoff = (uint32_t)blk << 21;
    const int row = blk * 32 + lane;
    const int c0 = (wid >= 4) ? 32 : 0;
    uint32_t d[32];
    const int NT = (NN + 127) / 128;
    const float4* x4 = (const float4*)x;
    float4 zero4 = make_float4(0.f, 0.f, 0.f, 0.f);

    for (int tile = blockIdx.x; tile < NT; tile += gridDim.x) {
        const int base = tile * 128;
        const int n = base + row;
        {
            float4 v[16];
            if (n < NN) {
#pragma unroll
                for (int j = 0; j < 16; j++) v[j] = x4[(size_t)n * 16 + j];
            } else {
#pragma unroll
                for (int j = 0; j < 16; j++) v[j] = zero4;
            }
            uint32_t hi[32], lo[32];
#pragma unroll
            for (int j = 0; j < 16; j++) {
                split2(v[j].x, v[j].y, hi[2 * j], lo[2 * j]);
                split2(v[j].z, v[j].w, hi[2 * j + 1], lo[2 * j + 1]);
            }
            if (wid < 4) TC_ST_X32(tmem + P_AHI + rowoff, hi);
            else         TC_ST_X32(tmem + P_ALO + rowoff, lo);
        }
        TC_WST(); TC_FB();
        __syncthreads();
        if (wid == 0 && elect1()) {
            TC_FA();
            mma_layer_ts(tmem + P_D0, tmem + P_AHI, tmem + P_ALO, dWsh, dWsl, 4, 0u);
            mma_layer_ts(tmem + P_D1, tmem + P_AHI, tmem + P_ALO, dWrh, dWrl, 4, 0u);
            TC_COMMIT(sb + P_MB);
        }
        MB_WAIT(sb + P_MB, ph); ph ^= 1;
        TC_FA();
        if (n < NN) {
            TC_LD_X32(d, tmem + P_D0 + c0);
            TC_WLD();
#pragma unroll
            for (int j = 0; j < 8; j++)
                *(float4*)&g_Xsr[(size_t)n * 128 + c0 + 4 * j] =
                    make_float4(__uint_as_float(d[4 * j]), __uint_as_float(d[4 * j + 1]),
                                __uint_as_float(d[4 * j + 2]), __uint_as_float(d[4 * j + 3]));
            TC_LD_X32(d, tmem + P_D1 + c0);
            TC_WLD();
#pragma unroll
            for (int j = 0; j < 8; j++)
                *(float4*)&g_Xsr[(size_t)n * 128 + 64 + c0 + 4 * j] =
                    make_float4(__uint_as_float(d[4 * j]) + b1s[c0 + 4 * j],
                                __uint_as_float(d[4 * j + 1]) + b1s[c0 + 4 * j + 1],
                                __uint_as_float(d[4 * j + 2]) + b1s[c0 + 4 * j + 2],
                                __uint_as_float(d[4 * j + 3]) + b1s[c0 + 4 * j + 3]);
        } else {
            TC_LD_X32(d, tmem + P_D0 + c0); TC_WLD();
            TC_LD_X32(d, tmem + P_D1 + c0); TC_WLD();
        }
        TC_FB();
        __syncthreads();
    }
    if (wid == 0) TC_DEALLOC(tmem, 256);
#else
    for (int i = blockIdx.x * blockDim.x + tid; i < NN; i += gridDim.x * blockDim.x)
        for (int j = 0; j < 64; j++) {
            float s = 0.f, r = be1[j];
            for (int k = 0; k < 64; k++) {
                s += x[(size_t)i * 64 + k] * We1[(64 + k) * 64 + j];
                r += x[(size_t)i * 64 + k] * We1[(128 + k) * 64 + j];
            }
            g_Xsr[(size_t)i * 128 + j] = s;
            g_Xsr[(size_t)i * 128 + 64 + j] = r;
        }
#endif
}

// ===================== edge kernel: 256 edges per phase-set =====================
#define E_TP  0
#define E_MB  16
#define E_B2  64
#define E_B3  320
#define E_SS  576      // 256 ints
#define E_TT  1600     // 256 ints
#define E_W1H 3072
#define E_W1L 11264
#define E_W2H 19456
#define E_W2L 27648
#define E_W3H 35840
#define E_W3L 44032
#define E_SZ  52224
// TMEM (256 cols/CTA): h0: AHI 0 ALO 32 D 64; h1: AHI 128 ALO 160 D 192
#define H_AHI(h) ((h) ? 128u : 0u)
#define H_ALO(h) ((h) ? 160u : 32u)
#define H_D(h)   ((h) ? 192u : 64u)

__global__ __launch_bounds__(256, 2)
void edge_mma_kernel(const float* __restrict__ x,
                     const float* __restrict__ e,
                     const int* __restrict__ senders,
                     const int* __restrict__ receivers,
                     const float* __restrict__ We1, const float* __restrict__ be1,
                     const float* __restrict__ We2, const float* __restrict__ be2,
                     const float* __restrict__ We3, const float* __restrict__ be3) {
    extern __shared__ char smc[];
    const int tid = threadIdx.x;
#if TC_PATH
    const uint32_t sb = smem_u32(smc);
    const int wid = tid >> 5, lane = tid & 31;
    if (wid == 0) { TC_ALLOC(sb + E_TP, 256); TC_RELINQ(); }
    if (tid == 0) MB_INIT(sb + E_MB, 1);
    float* b2s = (float*)(smc + E_B2);
    float* b3s = (float*)(smc + E_B3);
    int* ss = (int*)(smc + E_SS);
    int* tt = (int*)(smc + E_TT);
    if (tid < 64) { b2s[tid] = be2[tid]; b3s[tid] = be3[tid]; }
    for (int i = tid; i < 4096; i += 256) {
        int k = i >> 6, n = i & 63;
        uint32_t o = OFFB(n, k);
        store_wsplit(smc, E_W1H, E_W1L, o, We1[k * 64 + n]);   // e-part rows [0,64)
        store_wsplit(smc, E_W2H, E_W2L, o, We2[i]);
        store_wsplit(smc, E_W3H, E_W3L, o, We3[i]);
    }
    __syncthreads();
    uint32_t tmem;
    asm volatile("ld.shared.b32 %0, [%1];" : "=r"(tmem) : "r"(sb + E_TP));
    const u64 dW1h = mkdesc(sb + E_W1H), dW1l = mkdesc(sb + E_W1L);
    const u64 dW2h = mkdesc(sb + E_W2H), dW2l = mkdesc(sb + E_W2L);
    const u64 dW3h = mkdesc(sb + E_W3H), dW3l = mkdesc(sb + E_W3L);
    const float4* e4 = (const float4*)e;
    uint32_t ph = 0;
    const int blk = wid & 3;
    const uint32_t rowoff = (uint32_t)blk << 21;
    const int row = blk * 32 + lane;
    const int half = (wid >= 4) ? 1 : 0;
    const int c0 = half ? 32 : 0;
    uint32_t d[32];
    const int NT2 = NE / 256;

    for (int tile = blockIdx.x; tile < NT2; tile += gridDim.x) {
        const int base = tile * 256;
        ss[tid] = senders[base + tid];
        tt[tid] = receivers[base + tid];
        // ---- P1: stage all 256 e rows (warp w -> rows of its half) ----
        stage_row64(&e4[(size_t)(base + half * 128 + row) * 16],
                    tmem + H_AHI(half) + rowoff, tmem + H_ALO(half) + rowoff);
        TC_WST(); TC_FB();
        __syncthreads();
        // ---- M1 both halves, one commit ----
        if (wid == 0 && elect1()) {
            TC_FA();
            mma_layer_ts(tmem + H_D(0), tmem + H_AHI(0), tmem + H_ALO(0), dW1h, dW1l, 4, 0u);
            mma_layer_ts(tmem + H_D(1), tmem + H_AHI(1), tmem + H_ALO(1), dW1h, dW1l, 4, 0u);
            TC_COMMIT(sb + E_MB);
        }
        MB_WAIT(sb + E_MB, ph); ph ^= 1;
        TC_FA();
        // ---- epi1 both halves: relu(D + Xs[s] + Xrb[t]) -> A ----
#pragma unroll
        for (int h = 0; h < 2; h++) {
            TC_LD_X32(d, tmem + H_D(h) + c0);
            const int r = h * 128 + row;
            const int s = ss[r], t = tt[r];
            const float4* ps = (const float4*)&g_Xsr[(size_t)s * 128 + c0];
            const float4* pt = (const float4*)&g_Xsr[(size_t)t * 128 + 64 + c0];
            TC_WLD();
            uint32_t hi[16], lo[16];
#pragma unroll
            for (int j = 0; j < 8; j++) {
                float4 a = ps[j], b = pt[j];
                float v0 = fmaxf(__uint_as_float(d[4 * j])     + a.x + b.x, 0.f);
                float v1 = fmaxf(__uint_as_float(d[4 * j + 1]) + a.y + b.y, 0.f);
                float v2 = fmaxf(__uint_as_float(d[4 * j + 2]) + a.z + b.z, 0.f);
                float v3 = fmaxf(__uint_as_float(d[4 * j + 3]) + a.w + b.w, 0.f);
                split2(v0, v1, hi[2 * j], lo[2 * j]);
                split2(v2, v3, hi[2 * j + 1], lo[2 * j + 1]);
            }
            TC_ST_X16(tmem + H_AHI(h) + (c0 >> 1) + rowoff, hi);
            TC_ST_X16(tmem + H_ALO(h) + (c0 >> 1) + rowoff, lo);
        }
        TC_WST(); TC_FB();
        __syncthreads();
        // ---- M2 both halves ----
        if (wid == 0 && elect1()) {
            TC_FA();
            mma_layer_ts(tmem + H_D(0), tmem + H_AHI(0), tmem + H_ALO(0), dW2h, dW2l, 4, 0u);
            mma_layer_ts(tmem + H_D(1), tmem + H_AHI(1), tmem + H_ALO(1), dW2h, dW2l, 4, 0u);
            TC_COMMIT(sb + E_MB);
        }
        MB_WAIT(sb + E_MB, ph); ph ^= 1;
        TC_FA();
        // ---- epi2 both halves: relu(D + b2) -> A ----
#pragma unroll
        for (int h = 0; h < 2; h++) {
            TC_LD_X32(d, tmem + H_D(h) + c0);
            TC_WLD();
            uint32_t hi[16], lo[16];
#pragma unroll
            for (int j = 0; j < 16; j++) {
                float a = fmaxf(__uint_as_float(d[2 * j])     + b2s[c0 + 2 * j], 0.f);
                float b = fmaxf(__uint_as_float(d[2 * j + 1]) + b2s[c0 + 2 * j + 1], 0.f);
                split2(a, b, hi[j], lo[j]);
            }
            TC_ST_X16(tmem + H_AHI(h) + (c0 >> 1) + rowoff, hi);
            TC_ST_X16(tmem + H_ALO(h) + (c0 >> 1) + rowoff, lo);
        }
        TC_WST(); TC_FB();
        __syncthreads();
        // ---- M3 both halves ----
        if (wid == 0 && elect1()) {
            TC_FA();
            mma_layer_ts(tmem + H_D(0), tmem + H_AHI(0), tmem + H_ALO(0), dW3h, dW3l, 4, 0u);
            mma_layer_ts(tmem + H_D(1), tmem + H_AHI(1), tmem + H_ALO(1), dW3h, dW3l, 4, 0u);
            TC_COMMIT(sb + E_MB);
        }
        MB_WAIT(sb + E_MB, ph); ph ^= 1;
        TC_FA();
        // ---- epi3 both halves: segment sum ----
#pragma unroll
        for (int h = 0; h < 2; h++) {
            TC_LD_X32(d, tmem + H_D(h) + c0);
            TC_WLD();
            float* p = &g_agg[(size_t)tt[h * 128 + row] * 64 + c0];
#pragma unroll
            for (int jj = 0; jj < 4; jj++) {
                float v[8];
#pragma unroll
                for (int j = 0; j < 8; j++)
                    v[j] = __uint_as_float(d[jj * 8 + j]) + b3s[c0 + jj * 8 + j];
                red_add_v4(p + jj * 8, v[0], v[1], v[2], v[3]);
                red_add_v4(p + jj * 8 + 4, v[4], v[5], v[6], v[7]);
            }
        }
        TC_FB();
        __syncthreads();   // protect ss/tt + TMEM A before next iteration
    }
    if (wid == 0) TC_DEALLOC(tmem, 256);
#else
    // naive correct fallback (compiled for non-sm_103a passes only)
    for (int i = blockIdx.x * blockDim.x + tid; i < NE; i += gridDim.x * blockDim.x) {
        int s = senders[i], t = receivers[i];
        float h1[64], h2[64];
        for (int j = 0; j < 64; j++) {
            float a = be1[j];
            for (int k = 0; k < 64; k++) a += e[(size_t)i * 64 + k] * We1[k * 64 + j];
            for (int k = 0; k < 64; k++) a += x[(size_t)s * 64 + k] * We1[(64 + k) * 64 + j];
            for (int k = 0; k < 64; k++) a += x[(size_t)t * 64 + k] * We1[(128 + k) * 64 + j];
            h1[j] = fmaxf(a, 0.f);
        }
        for (int j = 0; j < 64; j++) {
            float a = be2[j];
            for (int k = 0; k < 64; k++) a += h1[k] * We2[k * 64 + j];
            h2[j] = fmaxf(a, 0.f);
        }
        for (int j = 0; j < 64; j++) {
            float a = be3[j];
            for (int k = 0; k < 64; k++) a += h2[k] * We3[k * 64 + j];
            atomicAdd(&g_agg[(size_t)t * 64 + j], a);
        }
    }
#endif
}

// ===================== node kernel =====================
#define N_TP 0
#define N_MB 16
#define N_B1 64
#define N_B2 320
#define N_B3 576
#define N_W1H 1024
#define N_W1L 17408
#define N_W2H 33792
#define N_W2L 41984
#define N_W3H 50176
#define N_W3L 58368
#define N_SZ 66560
#define N_AHI 0
#define N_ALO 64
#define N_D   128

__global__ __launch_bounds__(256, 2)
void node_mma_kernel(const float* __restrict__ x,
                     const float* __restrict__ Wn1, const float* __restrict__ bn1,
                     const float* __restrict__ Wn2, const float* __restrict__ bn2,
                     const float* __restrict__ Wn3, const float* __restrict__ bn3,
                     float* __restrict__ out) {
    extern __shared__ char smc[];
    const int tid = threadIdx.x;
#if TC_PATH
    const uint32_t sb = smem_u32(smc);
    const int wid = tid >> 5, lane = tid & 31;
    if (wid == 0) { TC_ALLOC(sb + N_TP, 256); TC_RELINQ(); }
    if (tid == 0) MB_INIT(sb + N_MB, 1);
    float* b1s = (float*)(smc + N_B1);
    float* b2s = (float*)(smc + N_B2);
    float* b3s = (float*)(smc + N_B3);
    if (tid < 64) { b1s[tid] = bn1[tid]; b2s[tid] = bn2[tid]; b3s[tid] = bn3[tid]; }
    for (int i = tid; i < 8192; i += 256) {
        int k = i >> 6, n = i & 63;
        store_wsplit(smc, N_W1H, N_W1L, OFFB(n, k), Wn1[i]);
    }
    for (int i = tid; i < 4096; i += 256) {
        int k = i >> 6, n = i & 63;
        uint32_t o = OFFB(n, k);
        store_wsplit(smc, N_W2H, N_W2L, o, Wn2[i]);
        store_wsplit(smc, N_W3H, N_W3L, o, Wn3[i]);
    }
    __syncthreads();
    uint32_t tmem;
    asm volatile("ld.shared.b32 %0, [%1];" : "=r"(tmem) : "r"(sb + N_TP));
    const u64 dW1h = mkdesc(sb + N_W1H), dW1l = mkdesc(sb + N_W1L);
    const u64 dW2h = mkdesc(sb + N_W2H), dW2l = mkdesc(sb + N_W2L);
    const u64 dW3h = mkdesc(sb + N_W3H), dW3l = mkdesc(sb + N_W3L);
    const float4* x4 = (const float4*)x;
    const float4* ag4 = (const float4*)g_agg;
    uint32_t ph = 0;
    const int blk = wid & 3;
    const uint32_t rowoff = (uint32_t)blk << 21;
    const int row = blk * 32 + lane;
    const int c0 = (wid >= 4) ? 32 : 0;
    uint32_t d[32];
    const int NT = (NN + 127) / 128;
    float4 zero4 = make_float4(0.f, 0.f, 0.f, 0.f);

    for (int tile = blockIdx.x; tile < NT; tile += gridDim.x) {
        const int base = tile * 128;
        const int n = base + row;
        {
            const float4* src = (wid < 4) ? &x4[(size_t)n * 16] : &ag4[(size_t)n * 16];
            float4 v[16];
            if (n < NN) {
#pragma unroll
                for (int j = 0; j < 16; j++) v[j] = src[j];
            } else {
#pragma unroll
                for (int j = 0; j < 16; j++) v[j] = zero4;
            }
            uint32_t hi[32], lo[32];
#pragma unroll
            for (int j = 0; j < 16; j++) {
                split2(v[j].x, v[j].y, hi[2 * j], lo[2 * j]);
                split2(v[j].z, v[j].w, hi[2 * j + 1], lo[2 * j + 1]);
            }
            uint32_t off = (wid < 4) ? 0u : 32u;
            TC_ST_X32(tmem + N_AHI + off + rowoff, hi);
            TC_ST_X32(tmem + N_ALO + off + rowoff, lo);
        }
        TC_WST(); TC_FB();
        __syncthreads();
        if (wid == 0 && elect1()) {
            TC_FA();
            mma_layer_ts(tmem + N_D, tmem + N_AHI, tmem + N_ALO, dW1h, dW1l, 8, 0u);
            TC_COMMIT(sb + N_MB);
        }
        MB_WAIT(sb + N_MB, ph); ph ^= 1;
        TC_FA();
        TC_LD_X32(d, tmem + N_D + c0);
        TC_WLD();
        {
            uint32_t hi[16], lo[16];
#pragma unroll
            for (int j = 0; j < 16; j++) {
                float a = fmaxf(__uint_as_float(d[2 * j])     + b1s[c0 + 2 * j], 0.f);
                float b = fmaxf(__uint_as_float(d[2 * j + 1]) + b1s[c0 + 2 * j + 1], 0.f);
                split2(a, b, hi[j], lo[j]);
            }
            TC_ST_X16(tmem + N_AHI + (c0 >> 1) + rowoff, hi);
            TC_ST_X16(tmem + N_ALO + (c0 >> 1) + rowoff, lo);
            TC_WST();
        }
        TC_FB();
        __syncthreads();
        if (wid == 0 && elect1()) {
            TC_FA();
            mma_layer_ts(tmem + N_D, tmem + N_AHI, tmem + N_ALO, dW2h, dW2l, 4, 0u);
            TC_COMMIT(sb + N_MB);
        }
        MB_WAIT(sb + N_MB, ph); ph ^= 1;
        TC_FA();
        TC_LD_X32(d, tmem + N_D + c0);
        TC_WLD();
        {
            uint32_t hi[16], lo[16];
#pragma unroll
            for (int j = 0; j < 16; j++) {
                float a = fmaxf(__uint_as_float(d[2 * j])     + b2s[c0 + 2 * j], 0.f);
                float b = fmaxf(__uint_as_float(d[2 * j + 1]) + b2s[c0 + 2 * j + 1], 0.f);
                split2(a, b, hi[j], lo[j]);
            }
            TC_ST_X16(tmem + N_AHI + (c0 >> 1) + rowoff, hi);
            TC_ST_X16(tmem + N_ALO + (c0 >> 1) + rowoff, lo);
            TC_WST();
        }
        TC_FB();
        __syncthreads();
        if (wid == 0 && elect1()) {
            TC_FA();
            mma_layer_ts(tmem + N_D, tmem + N_AHI, tmem + N_ALO, dW3h, dW3l, 4, 0u);
            TC_COMMIT(sb + N_MB);
        }
        MB_WAIT(sb + N_MB, ph); ph ^= 1;
        TC_FA();
        TC_LD_X32(d, tmem + N_D + c0);
        TC_WLD(); TC_FB();
        if (n < NN) {
#pragma unroll
            for (int jj = 0; jj < 4; jj++) {
                float v[8];
#pragma unroll
                for (int j = 0; j < 8; j++)
                    v[j] = __uint_as_float(d[jj * 8 + j]) + b3s[c0 + jj * 8 + j];
                *(float4*)&out[(size_t)n * 64 + c0 + jj * 8]     = make_float4(v[0], v[1], v[2], v[3]);
                *(float4*)&out[(size_t)n * 64 + c0 + jj * 8 + 4] = make_float4(v[4], v[5], v[6], v[7]);
            }
        }
        __syncthreads();
    }
    if (wid == 0) TC_DEALLOC(tmem, 256);
#else
    for (int i = blockIdx.x * blockDim.x + tid; i < NN; i += gridDim.x * blockDim.x) {
        float h1[64], h2[64];
        for (int j = 0; j < 64; j++) {
            float a = bn1[j];
            for (int k = 0; k < 64; k++) a += x[(size_t)i * 64 + k] * Wn1[k * 64 + j];
            for (int k = 0; k < 64; k++) a += g_agg[(size_t)i * 64 + k] * Wn1[(64 + k) * 64 + j];
            h1[j] = fmaxf(a, 0.f);
        }
        for (int j = 0; j < 64; j++) {
            float a = bn2[j];
            for (int k = 0; k < 64; k++) a += h1[k] * Wn2[k * 64 + j];
            h2[j] = fmaxf(a, 0.f);
        }
        for (int j = 0; j < 64; j++) {
            float a = bn3[j];
            for (int k = 0; k < 64; k++) a += h2[k] * Wn3[k * 64 + j];
            out[(size_t)i * 64 + j] = a;
        }
    }
#endif
}

// ===================== launch =====================
extern "C" void kernel_launch(void* const* d_in, const int* in_sizes, int n_in,
                              void* d_out, int out_size) {
    const float* x         = (const float*)d_in[0];
    const float* e         = (const float*)d_in[1];
    const int*   senders   = (const int*)d_in[2];
    const int*   receivers = (const int*)d_in[3];
    const float* We1 = (const float*)d_in[4];
    const float* be1 = (const float*)d_in[5];
    const float* We2 = (const float*)d_in[6];
    const float* be2 = (const float*)d_in[7];
    const float* We3 = (const float*)d_in[8];
    const float* be3 = (const float*)d_in[9];
    const float* Wn1 = (const float*)d_in[10];
    const float* bn1 = (const float*)d_in[11];
    const float* Wn2 = (const float*)d_in[12];
    const float* bn2 = (const float*)d_in[13];
    const float* Wn3 = (const float*)d_in[14];
    const float* bn3 = (const float*)d_in[15];
    float* out = (float*)d_out;

    cudaFuncSetAttribute(pre_mma_kernel,  cudaFuncAttributeMaxDynamicSharedMemorySize, P_SZ);
    cudaFuncSetAttribute(edge_mma_kernel, cudaFuncAttributeMaxDynamicSharedMemorySize, E_SZ);
    cudaFuncSetAttribute(node_mma_kernel, cudaFuncAttributeMaxDynamicSharedMemorySize, N_SZ);

    zero_agg_kernel<<<304, 256>>>();
    pre_mma_kernel<<<304, 256, P_SZ>>>(x, We1, be1);
    edge_mma_kernel<<<304, 256, E_SZ>>>(x, e, senders, receivers,
                                        We1, be1, We2, be2, We3, be3);
    node_mma_kernel<<<304, 256, N_SZ>>>(x, Wn1, bn1, Wn2, bn2, Wn3, bn3, out);
}